// round 2
// baseline (speedup 1.0000x reference)
#include <cuda_runtime.h>

#define Bn 64
#define Sn 1024
#define Xn 256
#define Yn 128

typedef unsigned long long ull;

// ---------------- scratch (device globals: no cudaMalloc allowed) ----------
__device__ float g_Q[Bn * Sn * Yn];                 // 32 MB
__device__ float g_K[Bn * Sn * Yn];                 // 32 MB
__device__ float g_V[Bn * Sn * Yn];                 // 32 MB (becomes V/Z in place)
__device__ float g_Sc[(size_t)Bn * Sn * Sn];        // 256 MB scores [b][q][k]
__device__ float g_m[Bn * Sn];                      // per-(b,k) column max
__device__ float g_Zr[Bn * Sn];                     // per-(b,k) 1/sum
__device__ float g_O[Bn * Sn * Yn];                 // 32 MB pre-max output

// ---------------- packed fp32x2 helpers (sm_100+) ---------------------------
__device__ __forceinline__ ull bcast2(float x) {
    ull r; asm("mov.b64 %0, {%1, %1};" : "=l"(r) : "f"(x)); return r;
}
__device__ __forceinline__ void fma2(ull& c, ull a, ull b) {
    asm("fma.rn.f32x2 %0, %1, %2, %0;" : "+l"(c) : "l"(a), "l"(b));
}
__device__ __forceinline__ float2 unpack2(ull v) {
    float2 f; asm("mov.b64 {%0, %1}, %2;" : "=f"(f.x), "=f"(f.y) : "l"(v)); return f;
}

// Microkernel step: acc2[8][4] += a[8] (broadcast pairs) * b[8] (packed pairs)
__device__ __forceinline__ void mk_step(ull (&acc2)[8][4],
                                        const float* __restrict__ asr,  // &as[k][ty*8]
                                        const float* __restrict__ bsr)  // &bs[k][tx*8]
{
    float4 ra0 = *(const float4*)(asr);
    float4 ra1 = *(const float4*)(asr + 4);
    const ull* bp = (const ull*)(bsr);   // 32B-aligned (tx*8 floats)
    ull rb0 = bp[0], rb1 = bp[1], rb2 = bp[2], rb3 = bp[3];
    float ra[8] = {ra0.x, ra0.y, ra0.z, ra0.w, ra1.x, ra1.y, ra1.z, ra1.w};
    #pragma unroll
    for (int i = 0; i < 8; i++) {
        ull aa = bcast2(ra[i]);
        fma2(acc2[i][0], aa, rb0);
        fma2(acc2[i][1], aa, rb1);
        fma2(acc2[i][2], aa, rb2);
        fma2(acc2[i][3], aa, rb3);
    }
}

// ============================================================================
// K1: QKV projection. C[m,n] = sum_x q[m,x] * W[n,x] + b[n]
// 128x128 tile, BK=16, 8x8 per thread (fp32x2 packed), 256 threads.
// ============================================================================
__global__ __launch_bounds__(256, 2)
void qkv_kernel(const float* __restrict__ q,
                const float* __restrict__ Wq, const float* __restrict__ bq,
                const float* __restrict__ Wk, const float* __restrict__ bk,
                const float* __restrict__ Wv, const float* __restrict__ bv)
{
    const float* W; const float* bias; float* out;
    if (blockIdx.y == 0)      { W = Wq; bias = bq; out = g_Q; }
    else if (blockIdx.y == 1) { W = Wk; bias = bk; out = g_K; }
    else                      { W = Wv; bias = bv; out = g_V; }

    __shared__ float as[16][128];   // [k][m]
    __shared__ float ws[16][128];   // [k][n]

    const int tid = threadIdx.x;
    const int lr  = tid >> 1;
    const int lc  = (tid & 1) * 8;
    const int tx  = tid & 15;
    const int ty  = tid >> 4;
    const int rowBase = blockIdx.x * 128;

    ull acc2[8][4];
    #pragma unroll
    for (int i = 0; i < 8; i++)
        #pragma unroll
        for (int j = 0; j < 4; j++) acc2[i][j] = 0ULL;

    const float* Arow = q + (size_t)(rowBase + lr) * Xn;
    const float* Wrow = W + (size_t)lr * Xn;

    for (int kc = 0; kc < Xn; kc += 16) {
        float4 a0 = *(const float4*)(Arow + kc + lc);
        float4 a1 = *(const float4*)(Arow + kc + lc + 4);
        float4 w0 = *(const float4*)(Wrow + kc + lc);
        float4 w1 = *(const float4*)(Wrow + kc + lc + 4);
        as[lc+0][lr]=a0.x; as[lc+1][lr]=a0.y; as[lc+2][lr]=a0.z; as[lc+3][lr]=a0.w;
        as[lc+4][lr]=a1.x; as[lc+5][lr]=a1.y; as[lc+6][lr]=a1.z; as[lc+7][lr]=a1.w;
        ws[lc+0][lr]=w0.x; ws[lc+1][lr]=w0.y; ws[lc+2][lr]=w0.z; ws[lc+3][lr]=w0.w;
        ws[lc+4][lr]=w1.x; ws[lc+5][lr]=w1.y; ws[lc+6][lr]=w1.z; ws[lc+7][lr]=w1.w;
        __syncthreads();
        #pragma unroll
        for (int k = 0; k < 16; k++)
            mk_step(acc2, &as[k][ty*8], &ws[k][tx*8]);
        __syncthreads();
    }

    #pragma unroll
    for (int i = 0; i < 8; i++) {
        float* orow = out + (size_t)(rowBase + ty*8 + i) * Yn;
        #pragma unroll
        for (int j2 = 0; j2 < 4; j2 += 2) {
            float2 c0 = unpack2(acc2[i][j2]);
            float2 c1 = unpack2(acc2[i][j2+1]);
            float4 v;
            v.x = c0.x + bias[tx*8 + j2*2 + 0];
            v.y = c0.y + bias[tx*8 + j2*2 + 1];
            v.z = c1.x + bias[tx*8 + j2*2 + 2];
            v.w = c1.y + bias[tx*8 + j2*2 + 3];
            *(float4*)(orow + tx*8 + j2*2) = v;
        }
    }
}

// ============================================================================
// K2: scores S[b,q,k] = (1/sqrt(128)) * sum_d Q[b,q,d] * K[b,k,d]
// ============================================================================
__global__ __launch_bounds__(256, 2)
void scores_kernel()
{
    const int b  = blockIdx.z;
    const int qt = blockIdx.y;
    const int kt = blockIdx.x;

    const float* Qp = g_Q + (size_t)b * Sn * Yn;
    const float* Kp = g_K + (size_t)b * Sn * Yn;

    __shared__ float as[16][128];
    __shared__ float bs[16][128];

    const int tid = threadIdx.x;
    const int lr  = tid >> 1;
    const int lc  = (tid & 1) * 8;
    const int tx  = tid & 15;
    const int ty  = tid >> 4;

    ull acc2[8][4];
    #pragma unroll
    for (int i = 0; i < 8; i++)
        #pragma unroll
        for (int j = 0; j < 4; j++) acc2[i][j] = 0ULL;

    const float* Arow = Qp + (size_t)(qt*128 + lr) * Yn;
    const float* Brow = Kp + (size_t)(kt*128 + lr) * Yn;

    for (int kc = 0; kc < Yn; kc += 16) {
        float4 a0 = *(const float4*)(Arow + kc + lc);
        float4 a1 = *(const float4*)(Arow + kc + lc + 4);
        float4 b0 = *(const float4*)(Brow + kc + lc);
        float4 b1 = *(const float4*)(Brow + kc + lc + 4);
        as[lc+0][lr]=a0.x; as[lc+1][lr]=a0.y; as[lc+2][lr]=a0.z; as[lc+3][lr]=a0.w;
        as[lc+4][lr]=a1.x; as[lc+5][lr]=a1.y; as[lc+6][lr]=a1.z; as[lc+7][lr]=a1.w;
        bs[lc+0][lr]=b0.x; bs[lc+1][lr]=b0.y; bs[lc+2][lr]=b0.z; bs[lc+3][lr]=b0.w;
        bs[lc+4][lr]=b1.x; bs[lc+5][lr]=b1.y; bs[lc+6][lr]=b1.z; bs[lc+7][lr]=b1.w;
        __syncthreads();
        #pragma unroll
        for (int k = 0; k < 16; k++)
            mk_step(acc2, &as[k][ty*8], &bs[k][tx*8]);
        __syncthreads();
    }

    const float scale = 0.08838834764831845f;  // 1/sqrt(128)
    float* Sp = g_Sc + (size_t)b * Sn * Sn;
    #pragma unroll
    for (int i = 0; i < 8; i++) {
        float* srow = Sp + (size_t)(qt*128 + ty*8 + i) * Sn + kt*128;
        #pragma unroll
        for (int j2 = 0; j2 < 4; j2 += 2) {
            float2 c0 = unpack2(acc2[i][j2]);
            float2 c1 = unpack2(acc2[i][j2+1]);
            float4 v;
            v.x = c0.x * scale;
            v.y = c0.y * scale;
            v.z = c1.x * scale;
            v.w = c1.y * scale;
            *(float4*)(srow + tx*8 + j2*2) = v;
        }
    }
}

// ============================================================================
// K3: per-column (over q) max + sum-exp. grid = (S/256, B), 256 threads
// ============================================================================
__global__ void colstats_kernel()
{
    const int b = blockIdx.y;
    const int k = blockIdx.x * 256 + threadIdx.x;
    const float* Sp = g_Sc + (size_t)b * Sn * Sn;

    float m = -3.4e38f, z = 0.f;
    for (int q = 0; q < Sn; q += 4) {
        float sv[4];
        sv[0] = Sp[(size_t)(q+0)*Sn + k];
        sv[1] = Sp[(size_t)(q+1)*Sn + k];
        sv[2] = Sp[(size_t)(q+2)*Sn + k];
        sv[3] = Sp[(size_t)(q+3)*Sn + k];
        #pragma unroll
        for (int u = 0; u < 4; u++) {
            float s = sv[u];
            if (s <= m) {
                z += __expf(s - m);
            } else {
                z = z * __expf(m - s) + 1.0f;
                m = s;
            }
        }
    }
    g_m[b*Sn + k]  = m;
    g_Zr[b*Sn + k] = 1.0f / z;
}

// ============================================================================
// K3b: fold 1/Z into V rows (in place). grid = B*S*Y/256
// ============================================================================
__global__ void vnorm_kernel()
{
    const int i = blockIdx.x * 256 + threadIdx.x;
    g_V[i] *= g_Zr[i / Yn];
}

// ============================================================================
// K4: O[b,q,d] = sum_k exp(S[b,q,k] - m[b,k]) * Vn[b,k,d]
// exp applied while loading A tile. grid = (S/128, B)
// ============================================================================
__global__ __launch_bounds__(256, 2)
void pv_kernel()
{
    const int b  = blockIdx.y;
    const int qt = blockIdx.x;

    const float* Sp = g_Sc + (size_t)b * Sn * Sn;
    const float* Vp = g_V  + (size_t)b * Sn * Yn;
    const float* mp = g_m  + b * Sn;

    __shared__ float as[16][128];   // [k][q], holds exp(S - m)
    __shared__ float bs[16][128];   // [k][d]

    const int tid = threadIdx.x;
    const int lr  = tid >> 1;
    const int lc  = (tid & 1) * 8;
    const int tx  = tid & 15;
    const int ty  = tid >> 4;

    const int f0 = tid * 2;
    const int bk = f0 >> 5;
    const int bd = (f0 & 31) * 4;

    ull acc2[8][4];
    #pragma unroll
    for (int i = 0; i < 8; i++)
        #pragma unroll
        for (int j = 0; j < 4; j++) acc2[i][j] = 0ULL;

    const float* Arow = Sp + (size_t)(qt*128 + lr) * Sn;

    for (int kc = 0; kc < Sn; kc += 16) {
        float4 s0 = *(const float4*)(Arow + kc + lc);
        float4 s1 = *(const float4*)(Arow + kc + lc + 4);
        float4 m0 = *(const float4*)(mp + kc + lc);
        float4 m1 = *(const float4*)(mp + kc + lc + 4);
        as[lc+0][lr] = __expf(s0.x - m0.x);
        as[lc+1][lr] = __expf(s0.y - m0.y);
        as[lc+2][lr] = __expf(s0.z - m0.z);
        as[lc+3][lr] = __expf(s0.w - m0.w);
        as[lc+4][lr] = __expf(s1.x - m1.x);
        as[lc+5][lr] = __expf(s1.y - m1.y);
        as[lc+6][lr] = __expf(s1.z - m1.z);
        as[lc+7][lr] = __expf(s1.w - m1.w);

        const float* vrow = Vp + (size_t)(kc + bk) * Yn;
        float4 v0 = *(const float4*)(vrow + bd);
        float4 v1 = *(const float4*)(vrow + bd + 4);
        *(float4*)&bs[bk][bd]     = v0;
        *(float4*)&bs[bk][bd + 4] = v1;
        __syncthreads();
        #pragma unroll
        for (int k = 0; k < 16; k++)
            mk_step(acc2, &as[k][ty*8], &bs[k][tx*8]);
        __syncthreads();
    }

    float* Op = g_O + (size_t)b * Sn * Yn;
    #pragma unroll
    for (int i = 0; i < 8; i++) {
        float* orow = Op + (size_t)(qt*128 + ty*8 + i) * Yn;
        #pragma unroll
        for (int j2 = 0; j2 < 4; j2 += 2) {
            float2 c0 = unpack2(acc2[i][j2]);
            float2 c1 = unpack2(acc2[i][j2+1]);
            float4 v;
            v.x = c0.x; v.y = c0.y; v.z = c1.x; v.w = c1.y;
            *(float4*)(orow + tx*8 + j2*2) = v;
        }
    }
}

// ============================================================================
// K5: out[b,d] = max_q O[b,q,d]. grid = B, 128 threads
// ============================================================================
__global__ void maxout_kernel(float* __restrict__ out)
{
    const int b = blockIdx.x;
    const int d = threadIdx.x;
    const float* Op = g_O + (size_t)b * Sn * Yn;

    float m0 = -3.4e38f, m1 = -3.4e38f, m2 = -3.4e38f, m3 = -3.4e38f;
    for (int q = 0; q < Sn; q += 4) {
        m0 = fmaxf(m0, Op[(size_t)(q+0)*Yn + d]);
        m1 = fmaxf(m1, Op[(size_t)(q+1)*Yn + d]);
        m2 = fmaxf(m2, Op[(size_t)(q+2)*Yn + d]);
        m3 = fmaxf(m3, Op[(size_t)(q+3)*Yn + d]);
    }
    out[b*Yn + d] = fmaxf(fmaxf(m0, m1), fmaxf(m2, m3));
}

// ============================================================================
extern "C" void kernel_launch(void* const* d_in, const int* in_sizes, int n_in,
                              void* d_out, int out_size)
{
    const float* q  = (const float*)d_in[0];
    const float* Wq = (const float*)d_in[1];
    const float* bq = (const float*)d_in[2];
    const float* Wk = (const float*)d_in[3];
    const float* bk = (const float*)d_in[4];
    const float* Wv = (const float*)d_in[5];
    const float* bv = (const float*)d_in[6];
    float* out = (float*)d_out;

    qkv_kernel<<<dim3(Bn * Sn / 128, 3), 256>>>(q, Wq, bq, Wk, bk, Wv, bv);
    scores_kernel<<<dim3(Sn / 128, Sn / 128, Bn), 256>>>();
    colstats_kernel<<<dim3(Sn / 256, Bn), 256>>>();
    vnorm_kernel<<<(Bn * Sn * Yn) / 256, 256>>>();
    pv_kernel<<<dim3(Sn / 128, Bn), 256>>>();
    maxout_kernel<<<Bn, 128>>>(out);
}

// round 4
// speedup vs baseline: 1.7333x; 1.7333x over previous
#include <cuda_runtime.h>
#include <cuda_bf16.h>
#include <cstdint>

#define Bn 64
#define Sn 1024
#define Xn 256
#define Yn 128

typedef unsigned int uint;
typedef unsigned short ushort;

// ---------------- scratch (device globals: no cudaMalloc allowed) ----------
__device__ __nv_bfloat16 g_qh[Bn * Sn * Xn];   // q split hi
__device__ __nv_bfloat16 g_ql[Bn * Sn * Xn];   // q split lo
__device__ __nv_bfloat16 g_Wh[3][Yn * Xn];     // Wq/Wk/Wv hi
__device__ __nv_bfloat16 g_Wl[3][Yn * Xn];     // Wq/Wk/Wv lo
__device__ __nv_bfloat16 g_Qh[Bn * Sn * Yn], g_Ql[Bn * Sn * Yn];
__device__ __nv_bfloat16 g_Kh[Bn * Sn * Yn], g_Kl[Bn * Sn * Yn];
__device__ float         g_V [Bn * Sn * Yn];              // V fp32 (pre-norm)
__device__ float         g_Sc[(size_t)Bn * Sn * Sn];      // 256MB scores
__device__ float         g_m [Bn * Sn];                   // col max
__device__ float         g_Zr[Bn * Sn];                   // col 1/sum
__device__ __nv_bfloat16 g_Vth[Bn * Yn * Sn], g_Vtl[Bn * Yn * Sn]; // V^T/Z hi/lo [b][d][k]
__device__ float         g_O [Bn * Sn * Yn];              // pre-max output

// ---------------- shared tile layout (halves; padded stride) -----------------
#define TSTR  136                      // 128 + 8 halves pad -> conflict-free
#define T_AH  0
#define T_AL  (128 * TSTR)
#define T_BH  (2 * 128 * TSTR)
#define T_BL  (3 * 128 * TSTR)
#define SM_TOTAL (4 * 128 * TSTR * 2)  // 139264 bytes

// ---------------- bf16 split helper ------------------------------------------
__device__ __forceinline__ void split1(float v, ushort& h, ushort& l) {
    __nv_bfloat16 hb = __float2bfloat16(v);
    __nv_bfloat16 lb = __float2bfloat16(v - __bfloat162float(hb));
    h = __bfloat16_as_ushort(hb);
    l = __bfloat16_as_ushort(lb);
}

// ---------------- mma.sync m16n8k16 bf16 (compute_103-legal) -----------------
__device__ __forceinline__ void mma16816(float* c, const uint* a, const uint* b) {
    asm volatile("mma.sync.aligned.m16n8k16.row.col.f32.bf16.bf16.f32 "
        "{%0,%1,%2,%3}, {%4,%5,%6,%7}, {%8,%9}, {%0,%1,%2,%3};"
        : "+f"(c[0]), "+f"(c[1]), "+f"(c[2]), "+f"(c[3])
        : "r"(a[0]), "r"(a[1]), "r"(a[2]), "r"(a[3]), "r"(b[0]), "r"(b[1]));
}

// Tile fill: 128 rows x 128 bf16 into padded shared. 8 iters x 256 thr x uint4.
__device__ __forceinline__ void fill_tile(ushort* dst, const __nv_bfloat16* src,
                                          int stride, int tid) {
    #pragma unroll
    for (int it = 0; it < 8; it++) {
        int idx  = it * 256 + tid;
        int row  = idx >> 4;
        int col8 = (idx & 15) << 3;
        uint4 v = *(const uint4*)(src + (size_t)row * stride + col8);
        *(uint4*)(dst + row * TSTR + col8) = v;
    }
}

// Warp compute over one 128x128(x128k) chunk: 3-pass bf16 split, 8 k-steps.
// Warp tile 32m x 64n. Fragment mapping per PTX m16n8k16 row.col spec.
__device__ __forceinline__ void warp_mma_chunk(float (&c)[2][8][4],
        const ushort* sh, int m0, int n0, int g, int t) {
    #pragma unroll
    for (int pass = 0; pass < 3; pass++) {
        const ushort* A = sh + ((pass == 2) ? T_AL : T_AH);
        const ushort* B = sh + ((pass == 1) ? T_BL : T_BH);
        #pragma unroll
        for (int ks = 0; ks < 8; ks++) {
            const int k = ks * 16;
            uint a[2][4], b[8][2];
            #pragma unroll
            for (int tm = 0; tm < 2; tm++) {
                const ushort* ap = A + (m0 + tm * 16 + g) * TSTR + k + t * 2;
                a[tm][0] = *(const uint*)(ap);
                a[tm][1] = *(const uint*)(ap + 8 * TSTR);
                a[tm][2] = *(const uint*)(ap + 8);
                a[tm][3] = *(const uint*)(ap + 8 * TSTR + 8);
            }
            #pragma unroll
            for (int tn = 0; tn < 8; tn++) {
                const ushort* bp = B + (n0 + tn * 8 + g) * TSTR + k + t * 2;
                b[tn][0] = *(const uint*)(bp);
                b[tn][1] = *(const uint*)(bp + 8);
            }
            #pragma unroll
            for (int tm = 0; tm < 2; tm++)
                #pragma unroll
                for (int tn = 0; tn < 8; tn++)
                    mma16816(c[tm][tn], a[tm], b[tn]);
        }
    }
}

// ---------------- K0: fp32 -> bf16 hi/lo split --------------------------------
__global__ void split_q_kernel(const float* __restrict__ src) {
    int i = (blockIdx.x * 256 + threadIdx.x) * 4;
    float4 v = *(const float4*)(src + i);
    ushort h0, h1, h2, h3, l0, l1, l2, l3;
    split1(v.x, h0, l0); split1(v.y, h1, l1); split1(v.z, h2, l2); split1(v.w, h3, l3);
    *(uint2*)(g_qh + i) = make_uint2((uint)h0 | ((uint)h1 << 16), (uint)h2 | ((uint)h3 << 16));
    *(uint2*)(g_ql + i) = make_uint2((uint)l0 | ((uint)l1 << 16), (uint)l2 | ((uint)l3 << 16));
}
__global__ void split_w_kernel(const float* __restrict__ src, int sel) {
    int i = (blockIdx.x * 256 + threadIdx.x) * 4;
    float4 v = *(const float4*)(src + i);
    ushort h0, h1, h2, h3, l0, l1, l2, l3;
    split1(v.x, h0, l0); split1(v.y, h1, l1); split1(v.z, h2, l2); split1(v.w, h3, l3);
    *(uint2*)(g_Wh[sel] + i) = make_uint2((uint)h0 | ((uint)h1 << 16), (uint)h2 | ((uint)h3 << 16));
    *(uint2*)(g_Wl[sel] + i) = make_uint2((uint)l0 | ((uint)l1 << 16), (uint)l2 | ((uint)l3 << 16));
}

// ---------------- K1: QKV projection ------------------------------------------
// grid (512, 3), 256 thr. C[128 x 128] = q[128 x 256] . W[128 x 256]^T + b
__global__ __launch_bounds__(256, 1)
void qkv_mma_kernel(const float* __restrict__ bq, const float* __restrict__ bk,
                    const float* __restrict__ bv) {
    extern __shared__ ushort sh[];
    const int tid = threadIdx.x;
    const int w = tid >> 5, lane = tid & 31, g = lane >> 2, t = lane & 3;
    const int m0 = (w & 3) * 32, n0 = (w >> 2) * 64;
    const int rowBase = blockIdx.x * 128;
    const int sel = blockIdx.y;

    float c[2][8][4];
    #pragma unroll
    for (int i = 0; i < 2; i++)
        #pragma unroll
        for (int j = 0; j < 8; j++)
            #pragma unroll
            for (int r = 0; r < 4; r++) c[i][j][r] = 0.f;

    for (int ch = 0; ch < 2; ch++) {
        const int kc = ch * 128;
        fill_tile(sh + T_AH, g_qh + (size_t)rowBase * Xn + kc, Xn, tid);
        fill_tile(sh + T_AL, g_ql + (size_t)rowBase * Xn + kc, Xn, tid);
        fill_tile(sh + T_BH, g_Wh[sel] + kc, Xn, tid);
        fill_tile(sh + T_BL, g_Wl[sel] + kc, Xn, tid);
        __syncthreads();
        warp_mma_chunk(c, sh, m0, n0, g, t);
        __syncthreads();
    }

    const float* bias = (sel == 0) ? bq : (sel == 1) ? bk : bv;
    #pragma unroll
    for (int tm = 0; tm < 2; tm++) {
        #pragma unroll
        for (int half = 0; half < 2; half++) {
            const int mloc = m0 + tm * 16 + g + half * 8;
            const size_t row = (size_t)(rowBase + mloc) * Yn;
            #pragma unroll
            for (int tn = 0; tn < 8; tn++) {
                const int n = n0 + tn * 8 + t * 2;
                float v0 = c[tm][tn][half * 2 + 0] + __ldg(bias + n);
                float v1 = c[tm][tn][half * 2 + 1] + __ldg(bias + n + 1);
                if (sel < 2) {
                    __nv_bfloat16* dh = (sel == 0) ? g_Qh : g_Kh;
                    __nv_bfloat16* dl = (sel == 0) ? g_Ql : g_Kl;
                    ushort h0, h1, l0, l1;
                    split1(v0, h0, l0); split1(v1, h1, l1);
                    *(uint*)(dh + row + n) = (uint)h0 | ((uint)h1 << 16);
                    *(uint*)(dl + row + n) = (uint)l0 | ((uint)l1 << 16);
                } else {
                    *(float2*)(g_V + row + n) = make_float2(v0, v1);
                }
            }
        }
    }
}

// ---------------- K2: scores ----------------------------------------------------
// grid (8, 8, 64): S[b][qt*128+i][kt*128+j] = Q . K^T / sqrt(128)
__global__ __launch_bounds__(256, 1)
void scores_mma_kernel() {
    extern __shared__ ushort sh[];
    const int tid = threadIdx.x;
    const int w = tid >> 5, lane = tid & 31, g = lane >> 2, t = lane & 3;
    const int m0 = (w & 3) * 32, n0 = (w >> 2) * 64;
    const int kt = blockIdx.x, qt = blockIdx.y, b = blockIdx.z;

    float c[2][8][4];
    #pragma unroll
    for (int i = 0; i < 2; i++)
        #pragma unroll
        for (int j = 0; j < 8; j++)
            #pragma unroll
            for (int r = 0; r < 4; r++) c[i][j][r] = 0.f;

    const size_t qoff = ((size_t)b * Sn + qt * 128) * Yn;
    const size_t koff = ((size_t)b * Sn + kt * 128) * Yn;
    fill_tile(sh + T_AH, g_Qh + qoff, Yn, tid);
    fill_tile(sh + T_AL, g_Ql + qoff, Yn, tid);
    fill_tile(sh + T_BH, g_Kh + koff, Yn, tid);
    fill_tile(sh + T_BL, g_Kl + koff, Yn, tid);
    __syncthreads();
    warp_mma_chunk(c, sh, m0, n0, g, t);

    const float scale = 0.08838834764831845f;  // 1/sqrt(128)
    float* Sp = g_Sc + (size_t)b * Sn * Sn;
    #pragma unroll
    for (int tm = 0; tm < 2; tm++) {
        #pragma unroll
        for (int half = 0; half < 2; half++) {
            const int m = qt * 128 + m0 + tm * 16 + g + half * 8;
            float* srow = Sp + (size_t)m * Sn + kt * 128;
            #pragma unroll
            for (int tn = 0; tn < 8; tn++) {
                const int n = n0 + tn * 8 + t * 2;
                *(float2*)(srow + n) = make_float2(c[tm][tn][half * 2 + 0] * scale,
                                                   c[tm][tn][half * 2 + 1] * scale);
            }
        }
    }
}

// ---------------- K3: per-column (over q) max + sum-exp ------------------------
__global__ void colstats_kernel() {
    const int b = blockIdx.y;
    const int k = blockIdx.x * 256 + threadIdx.x;
    const float* Sp = g_Sc + (size_t)b * Sn * Sn;
    float m = -3.4e38f, z = 0.f;
    for (int q = 0; q < Sn; q += 4) {
        float sv[4];
        sv[0] = Sp[(size_t)(q + 0) * Sn + k];
        sv[1] = Sp[(size_t)(q + 1) * Sn + k];
        sv[2] = Sp[(size_t)(q + 2) * Sn + k];
        sv[3] = Sp[(size_t)(q + 3) * Sn + k];
        #pragma unroll
        for (int u = 0; u < 4; u++) {
            float s = sv[u];
            if (s <= m) z += __expf(s - m);
            else { z = z * __expf(m - s) + 1.0f; m = s; }
        }
    }
    g_m[b * Sn + k]  = m;
    g_Zr[b * Sn + k] = 1.0f / z;
}

// ---------------- K3b: V^T with 1/Z folded, bf16 hi/lo -------------------------
__global__ __launch_bounds__(256)
void vtrans_kernel() {
    __shared__ ushort shh[64][65], shl[64][65];   // [d][k]
    const int b  = blockIdx.z;
    const int d0 = blockIdx.y * 64;
    const int k0 = blockIdx.x * 64;
    const int tt = threadIdx.x;
    {
        const int k   = tt >> 2;
        const int d16 = (tt & 3) * 16;
        const float zr = __ldg(g_Zr + b * Sn + k0 + k);
        const float* vp = g_V + ((size_t)b * Sn + k0 + k) * Yn + d0 + d16;
        #pragma unroll
        for (int j = 0; j < 4; j++) {
            float4 v = *(const float4*)(vp + j * 4);
            ushort h0, h1, h2, h3, l0, l1, l2, l3;
            split1(v.x * zr, h0, l0); split1(v.y * zr, h1, l1);
            split1(v.z * zr, h2, l2); split1(v.w * zr, h3, l3);
            const int dd = d16 + j * 4;
            shh[dd + 0][k] = h0; shh[dd + 1][k] = h1; shh[dd + 2][k] = h2; shh[dd + 3][k] = h3;
            shl[dd + 0][k] = l0; shl[dd + 1][k] = l1; shl[dd + 2][k] = l2; shl[dd + 3][k] = l3;
        }
    }
    __syncthreads();
    {
        const int d  = tt >> 2;
        const int kq = (tt & 3) * 16;
        __nv_bfloat16* oh = g_Vth + ((size_t)b * Yn + d0 + d) * Sn + k0 + kq;
        __nv_bfloat16* ol = g_Vtl + ((size_t)b * Yn + d0 + d) * Sn + k0 + kq;
        #pragma unroll
        for (int p = 0; p < 2; p++) {
            uint4 u;
            u.x = (uint)shh[d][kq+p*8+0] | ((uint)shh[d][kq+p*8+1] << 16);
            u.y = (uint)shh[d][kq+p*8+2] | ((uint)shh[d][kq+p*8+3] << 16);
            u.z = (uint)shh[d][kq+p*8+4] | ((uint)shh[d][kq+p*8+5] << 16);
            u.w = (uint)shh[d][kq+p*8+6] | ((uint)shh[d][kq+p*8+7] << 16);
            *(uint4*)(oh + p * 8) = u;
            u.x = (uint)shl[d][kq+p*8+0] | ((uint)shl[d][kq+p*8+1] << 16);
            u.y = (uint)shl[d][kq+p*8+2] | ((uint)shl[d][kq+p*8+3] << 16);
            u.z = (uint)shl[d][kq+p*8+4] | ((uint)shl[d][kq+p*8+5] << 16);
            u.w = (uint)shl[d][kq+p*8+6] | ((uint)shl[d][kq+p*8+7] << 16);
            *(uint4*)(ol + p * 8) = u;
        }
    }
}

// ---------------- K4: PV ---------------------------------------------------------
// grid (8, 64): O[b][qt*128+i][d] = sum_k exp(S - m[k]) * (V/Z)[k][d]
__global__ __launch_bounds__(256, 1)
void pv_mma_kernel() {
    extern __shared__ ushort sh[];
    const int tid = threadIdx.x;
    const int w = tid >> 5, lane = tid & 31, g = lane >> 2, t = lane & 3;
    const int m0 = (w & 3) * 32, n0 = (w >> 2) * 64;
    const int qt = blockIdx.x, b = blockIdx.y;

    const float* Sp = g_Sc + (size_t)b * Sn * Sn;
    const float* mp = g_m + b * Sn;

    float c[2][8][4];
    #pragma unroll
    for (int i = 0; i < 2; i++)
        #pragma unroll
        for (int j = 0; j < 8; j++)
            #pragma unroll
            for (int r = 0; r < 4; r++) c[i][j][r] = 0.f;

    for (int ch = 0; ch < 8; ch++) {
        const int kc = ch * 128;
        // A tile: exp(S - m) hi/lo, computed on the fly
        #pragma unroll
        for (int it = 0; it < 16; it++) {
            const int idx = it * 256 + tid;
            const int row = idx >> 5;
            const int c4  = (idx & 31) << 2;
            float4 s  = *(const float4*)(Sp + (size_t)(qt * 128 + row) * Sn + kc + c4);
            float4 mm = *(const float4*)(mp + kc + c4);
            ushort h[4], l[4];
            split1(__expf(s.x - mm.x), h[0], l[0]);
            split1(__expf(s.y - mm.y), h[1], l[1]);
            split1(__expf(s.z - mm.z), h[2], l[2]);
            split1(__expf(s.w - mm.w), h[3], l[3]);
            const int off = row * TSTR + c4;
            *(uint2*)(sh + T_AH + off) = make_uint2((uint)h[0] | ((uint)h[1] << 16),
                                                    (uint)h[2] | ((uint)h[3] << 16));
            *(uint2*)(sh + T_AL + off) = make_uint2((uint)l[0] | ((uint)l[1] << 16),
                                                    (uint)l[2] | ((uint)l[3] << 16));
        }
        fill_tile(sh + T_BH, g_Vth + (size_t)b * Yn * Sn + kc, Sn, tid);
        fill_tile(sh + T_BL, g_Vtl + (size_t)b * Yn * Sn + kc, Sn, tid);
        __syncthreads();
        warp_mma_chunk(c, sh, m0, n0, g, t);
        __syncthreads();
    }

    float* Op = g_O + ((size_t)b * Sn + qt * 128) * Yn;
    #pragma unroll
    for (int tm = 0; tm < 2; tm++) {
        #pragma unroll
        for (int half = 0; half < 2; half++) {
            const int mloc = m0 + tm * 16 + g + half * 8;
            float* orow = Op + (size_t)mloc * Yn;
            #pragma unroll
            for (int tn = 0; tn < 8; tn++) {
                const int n = n0 + tn * 8 + t * 2;
                *(float2*)(orow + n) = make_float2(c[tm][tn][half * 2 + 0],
                                                   c[tm][tn][half * 2 + 1]);
            }
        }
    }
}

// ---------------- K5: out[b,d] = max_q O[b,q,d] --------------------------------
__global__ void maxout_kernel(float* __restrict__ out) {
    const int b = blockIdx.x;
    const int d = threadIdx.x;
    const float* Op = g_O + (size_t)b * Sn * Yn;
    float m0 = -3.4e38f, m1 = -3.4e38f, m2 = -3.4e38f, m3 = -3.4e38f;
    for (int q = 0; q < Sn; q += 4) {
        m0 = fmaxf(m0, Op[(size_t)(q + 0) * Yn + d]);
        m1 = fmaxf(m1, Op[(size_t)(q + 1) * Yn + d]);
        m2 = fmaxf(m2, Op[(size_t)(q + 2) * Yn + d]);
        m3 = fmaxf(m3, Op[(size_t)(q + 3) * Yn + d]);
    }
    out[b * Yn + d] = fmaxf(fmaxf(m0, m1), fmaxf(m2, m3));
}

// ============================================================================
extern "C" void kernel_launch(void* const* d_in, const int* in_sizes, int n_in,
                              void* d_out, int out_size)
{
    const float* q  = (const float*)d_in[0];
    const float* Wq = (const float*)d_in[1];
    const float* bq = (const float*)d_in[2];
    const float* Wk = (const float*)d_in[3];
    const float* bk = (const float*)d_in[4];
    const float* Wv = (const float*)d_in[5];
    const float* bv = (const float*)d_in[6];
    float* out = (float*)d_out;

    cudaFuncSetAttribute(qkv_mma_kernel,    cudaFuncAttributeMaxDynamicSharedMemorySize, SM_TOTAL);
    cudaFuncSetAttribute(scores_mma_kernel, cudaFuncAttributeMaxDynamicSharedMemorySize, SM_TOTAL);
    cudaFuncSetAttribute(pv_mma_kernel,     cudaFuncAttributeMaxDynamicSharedMemorySize, SM_TOTAL);

    split_q_kernel<<<(Bn * Sn * Xn) / 1024, 256>>>(q);
    split_w_kernel<<<(Yn * Xn) / 1024, 256>>>(Wq, 0);
    split_w_kernel<<<(Yn * Xn) / 1024, 256>>>(Wk, 1);
    split_w_kernel<<<(Yn * Xn) / 1024, 256>>>(Wv, 2);
    qkv_mma_kernel<<<dim3(Bn * Sn / 128, 3), 256, SM_TOTAL>>>(bq, bk, bv);
    scores_mma_kernel<<<dim3(Sn / 128, Sn / 128, Bn), 256, SM_TOTAL>>>();
    colstats_kernel<<<dim3(Sn / 256, Bn), 256>>>();
    vtrans_kernel<<<dim3(Sn / 64, Yn / 64, Bn), 256>>>();
    pv_mma_kernel<<<dim3(Sn / 128, Bn), 256, SM_TOTAL>>>();
    maxout_kernel<<<Bn, 128>>>(out);
}

// round 5
// speedup vs baseline: 1.8872x; 1.0888x over previous
#include <cuda_runtime.h>
#include <cuda_bf16.h>
#include <cstdint>

#define Bn 64
#define Sn 1024
#define Xn 256
#define Yn 128

typedef unsigned int uint;
typedef unsigned short ushort;

// ---------------- scratch (device globals: no cudaMalloc allowed) ----------
__device__ __nv_bfloat16 g_qh[Bn * Sn * Xn];   // q split hi
__device__ __nv_bfloat16 g_ql[Bn * Sn * Xn];   // q split lo
__device__ __nv_bfloat16 g_Wh[3][Yn * Xn];     // Wq/Wk/Wv hi
__device__ __nv_bfloat16 g_Wl[3][Yn * Xn];     // Wq/Wk/Wv lo
__device__ __nv_bfloat16 g_Qh[Bn * Sn * Yn], g_Ql[Bn * Sn * Yn];
__device__ __nv_bfloat16 g_Kh[Bn * Sn * Yn], g_Kl[Bn * Sn * Yn];
__device__ float         g_V [Bn * Sn * Yn];              // V fp32 (pre-norm)
__device__ float         g_Sc[(size_t)Bn * Sn * Sn];      // 256MB scores
__device__ float         g_m [Bn * Sn];                   // col max
__device__ float         g_Zr[Bn * Sn];                   // col 1/sum
__device__ __nv_bfloat16 g_Vth[Bn * Yn * Sn], g_Vtl[Bn * Yn * Sn]; // V^T/Z hi/lo [b][d][k]

// ---------------- shared tile layout (halves; padded stride) -----------------
#define TSTR  136                      // 128 + 8 halves pad -> conflict-free
#define T_AH  0
#define T_AL  (128 * TSTR)
#define T_BH  (2 * 128 * TSTR)
#define T_BL  (3 * 128 * TSTR)
#define SM_TOTAL (4 * 128 * TSTR * 2)  // 139264 bytes

// ---------------- helpers ------------------------------------------------------
__device__ __forceinline__ void split1(float v, ushort& h, ushort& l) {
    __nv_bfloat16 hb = __float2bfloat16(v);
    __nv_bfloat16 lb = __float2bfloat16(v - __bfloat162float(hb));
    h = __bfloat16_as_ushort(hb);
    l = __bfloat16_as_ushort(lb);
}

__device__ __forceinline__ uint32_t smem_u32(const void* p) {
    uint32_t a;
    asm("{ .reg .u64 t; cvta.to.shared.u64 t, %1; cvt.u32.u64 %0, t; }" : "=r"(a) : "l"(p));
    return a;
}

__device__ __forceinline__ void mma16816(float* c, const uint* a, const uint* b) {
    asm volatile("mma.sync.aligned.m16n8k16.row.col.f32.bf16.bf16.f32 "
        "{%0,%1,%2,%3}, {%4,%5,%6,%7}, {%8,%9}, {%0,%1,%2,%3};"
        : "+f"(c[0]), "+f"(c[1]), "+f"(c[2]), "+f"(c[3])
        : "r"(a[0]), "r"(a[1]), "r"(a[2]), "r"(a[3]), "r"(b[0]), "r"(b[1]));
}

#define LDSM4(r0, r1, r2, r3, addr) \
    asm volatile("ldmatrix.sync.aligned.m8n8.x4.shared.b16 {%0,%1,%2,%3}, [%4];" \
        : "=r"(r0), "=r"(r1), "=r"(r2), "=r"(r3) : "r"(addr))

__device__ __forceinline__ void atomicMaxF(float* a, float v) {
    if (v >= 0.f) atomicMax((int*)a, __float_as_int(v));
    else          atomicMin((uint*)a, (uint)__float_as_int(v));
}

// Tile fill: 128 rows x 128 bf16 into padded shared. 8 iters x 256 thr x uint4.
__device__ __forceinline__ void fill_tile(ushort* dst, const __nv_bfloat16* src,
                                          int stride, int tid) {
    #pragma unroll
    for (int it = 0; it < 8; it++) {
        int idx  = it * 256 + tid;
        int row  = idx >> 4;
        int col8 = (idx & 15) << 3;
        uint4 v = *(const uint4*)(src + (size_t)row * stride + col8);
        *(uint4*)(dst + row * TSTR + col8) = v;
    }
}

// Warp compute over one 128x128(x128k) chunk via ldmatrix; fragments loaded once
// per k-step and reused across all 3 split passes (hi*hi + hi*lo + lo*hi).
// aH/aL/bH/bL are this lane's ldmatrix base byte-addresses at k=0 (tm=0 / pair=0).
__device__ __forceinline__ void warp_mma_chunk(float (&c)[2][8][4],
        uint32_t aH, uint32_t aL, uint32_t bH, uint32_t bL) {
    #pragma unroll
    for (int ks = 0; ks < 8; ks++) {
        const uint32_t ko = ks * 32;   // 16 halves per k-step
        uint ah[2][4], al[2][4], bh[4][4], bl[4][4];
        #pragma unroll
        for (int tm = 0; tm < 2; tm++) {
            LDSM4(ah[tm][0], ah[tm][1], ah[tm][2], ah[tm][3], aH + tm * (16 * TSTR * 2) + ko);
            LDSM4(al[tm][0], al[tm][1], al[tm][2], al[tm][3], aL + tm * (16 * TSTR * 2) + ko);
        }
        #pragma unroll
        for (int p = 0; p < 4; p++) {
            LDSM4(bh[p][0], bh[p][1], bh[p][2], bh[p][3], bH + p * (16 * TSTR * 2) + ko);
            LDSM4(bl[p][0], bl[p][1], bl[p][2], bl[p][3], bL + p * (16 * TSTR * 2) + ko);
        }
        #pragma unroll
        for (int tm = 0; tm < 2; tm++) {
            #pragma unroll
            for (int tn = 0; tn < 8; tn++) {
                const int p = tn >> 1, s = (tn & 1) * 2;
                mma16816(c[tm][tn], ah[tm], &bh[p][s]);   // hi * hi
                mma16816(c[tm][tn], ah[tm], &bl[p][s]);   // hi * lo
                mma16816(c[tm][tn], al[tm], &bh[p][s]);   // lo * hi
            }
        }
    }
}

// Per-warp lane ldmatrix offsets (in bytes, halves*2), relative to tile base.
// A (row-major m x k): grp0 rows m0+r @k | grp1 +8rows | grp2 @k+8 | grp3 +8rows@k+8
// B (row-major n x k): grp0 rows n0+r @k | grp1 @k+8   | grp2 +8rows | grp3 +8rows@k+8
__device__ __forceinline__ uint32_t a_lane_off(int m0, int lane) {
    int r = lane & 7, grp = lane >> 3;
    return (uint32_t)(((m0 + (grp & 1) * 8 + r) * TSTR + (grp >> 1) * 8) * 2);
}
__device__ __forceinline__ uint32_t b_lane_off(int n0, int lane) {
    int r = lane & 7, grp = lane >> 3;
    return (uint32_t)(((n0 + (grp >> 1) * 8 + r) * TSTR + (grp & 1) * 8) * 2);
}

// ---------------- K0: fp32 -> bf16 hi/lo split --------------------------------
__global__ void split_q_kernel(const float* __restrict__ src) {
    int i = (blockIdx.x * 256 + threadIdx.x) * 4;
    float4 v = *(const float4*)(src + i);
    ushort h0, h1, h2, h3, l0, l1, l2, l3;
    split1(v.x, h0, l0); split1(v.y, h1, l1); split1(v.z, h2, l2); split1(v.w, h3, l3);
    *(uint2*)(g_qh + i) = make_uint2((uint)h0 | ((uint)h1 << 16), (uint)h2 | ((uint)h3 << 16));
    *(uint2*)(g_ql + i) = make_uint2((uint)l0 | ((uint)l1 << 16), (uint)l2 | ((uint)l3 << 16));
}
__global__ void split_w_kernel(const float* __restrict__ src, int sel) {
    int i = (blockIdx.x * 256 + threadIdx.x) * 4;
    float4 v = *(const float4*)(src + i);
    ushort h0, h1, h2, h3, l0, l1, l2, l3;
    split1(v.x, h0, l0); split1(v.y, h1, l1); split1(v.z, h2, l2); split1(v.w, h3, l3);
    *(uint2*)(g_Wh[sel] + i) = make_uint2((uint)h0 | ((uint)h1 << 16), (uint)h2 | ((uint)h3 << 16));
    *(uint2*)(g_Wl[sel] + i) = make_uint2((uint)l0 | ((uint)l1 << 16), (uint)l2 | ((uint)l3 << 16));
}

// ---------------- init d_out to -inf -------------------------------------------
__global__ void initout_kernel(float* __restrict__ out) {
    out[blockIdx.x * 256 + threadIdx.x] = __int_as_float(0xFF800000);
}

// ---------------- K1: QKV projection ------------------------------------------
__global__ __launch_bounds__(256, 1)
void qkv_mma_kernel(const float* __restrict__ bq, const float* __restrict__ bk,
                    const float* __restrict__ bv) {
    extern __shared__ ushort sh[];
    const int tid = threadIdx.x;
    const int w = tid >> 5, lane = tid & 31, g = lane >> 2, t = lane & 3;
    const int m0 = (w & 3) * 32, n0 = (w >> 2) * 64;
    const int rowBase = blockIdx.x * 128;
    const int sel = blockIdx.y;

    const uint32_t base = smem_u32(sh);
    const uint32_t aoff = a_lane_off(m0, lane), boff = b_lane_off(n0, lane);
    const uint32_t aH = base + T_AH * 2 + aoff, aL = base + T_AL * 2 + aoff;
    const uint32_t bH = base + T_BH * 2 + boff, bL = base + T_BL * 2 + boff;

    float c[2][8][4];
    #pragma unroll
    for (int i = 0; i < 2; i++)
        #pragma unroll
        for (int j = 0; j < 8; j++)
            #pragma unroll
            for (int r = 0; r < 4; r++) c[i][j][r] = 0.f;

    for (int ch = 0; ch < 2; ch++) {
        const int kc = ch * 128;
        fill_tile(sh + T_AH, g_qh + (size_t)rowBase * Xn + kc, Xn, tid);
        fill_tile(sh + T_AL, g_ql + (size_t)rowBase * Xn + kc, Xn, tid);
        fill_tile(sh + T_BH, g_Wh[sel] + kc, Xn, tid);
        fill_tile(sh + T_BL, g_Wl[sel] + kc, Xn, tid);
        __syncthreads();
        warp_mma_chunk(c, aH, aL, bH, bL);
        __syncthreads();
    }

    const float* bias = (sel == 0) ? bq : (sel == 1) ? bk : bv;
    #pragma unroll
    for (int tm = 0; tm < 2; tm++) {
        #pragma unroll
        for (int half = 0; half < 2; half++) {
            const int mloc = m0 + tm * 16 + g + half * 8;
            const size_t row = (size_t)(rowBase + mloc) * Yn;
            #pragma unroll
            for (int tn = 0; tn < 8; tn++) {
                const int n = n0 + tn * 8 + t * 2;
                float v0 = c[tm][tn][half * 2 + 0] + __ldg(bias + n);
                float v1 = c[tm][tn][half * 2 + 1] + __ldg(bias + n + 1);
                if (sel < 2) {
                    __nv_bfloat16* dh = (sel == 0) ? g_Qh : g_Kh;
                    __nv_bfloat16* dl = (sel == 0) ? g_Ql : g_Kl;
                    ushort h0, h1, l0, l1;
                    split1(v0, h0, l0); split1(v1, h1, l1);
                    *(uint*)(dh + row + n) = (uint)h0 | ((uint)h1 << 16);
                    *(uint*)(dl + row + n) = (uint)l0 | ((uint)l1 << 16);
                } else {
                    *(float2*)(g_V + row + n) = make_float2(v0, v1);
                }
            }
        }
    }
}

// ---------------- K2: scores -----------------------------------------------------
__global__ __launch_bounds__(256, 1)
void scores_mma_kernel() {
    extern __shared__ ushort sh[];
    const int tid = threadIdx.x;
    const int w = tid >> 5, lane = tid & 31, g = lane >> 2, t = lane & 3;
    const int m0 = (w & 3) * 32, n0 = (w >> 2) * 64;
    const int kt = blockIdx.x, qt = blockIdx.y, b = blockIdx.z;

    const uint32_t base = smem_u32(sh);
    const uint32_t aoff = a_lane_off(m0, lane), boff = b_lane_off(n0, lane);

    float c[2][8][4];
    #pragma unroll
    for (int i = 0; i < 2; i++)
        #pragma unroll
        for (int j = 0; j < 8; j++)
            #pragma unroll
            for (int r = 0; r < 4; r++) c[i][j][r] = 0.f;

    const size_t qoff = ((size_t)b * Sn + qt * 128) * Yn;
    const size_t koff = ((size_t)b * Sn + kt * 128) * Yn;
    fill_tile(sh + T_AH, g_Qh + qoff, Yn, tid);
    fill_tile(sh + T_AL, g_Ql + qoff, Yn, tid);
    fill_tile(sh + T_BH, g_Kh + koff, Yn, tid);
    fill_tile(sh + T_BL, g_Kl + koff, Yn, tid);
    __syncthreads();
    warp_mma_chunk(c, base + T_AH * 2 + aoff, base + T_AL * 2 + aoff,
                   base + T_BH * 2 + boff, base + T_BL * 2 + boff);

    const float scale = 0.08838834764831845f;  // 1/sqrt(128)
    float* Sp = g_Sc + (size_t)b * Sn * Sn;
    #pragma unroll
    for (int tm = 0; tm < 2; tm++) {
        #pragma unroll
        for (int half = 0; half < 2; half++) {
            const int m = qt * 128 + m0 + tm * 16 + g + half * 8;
            float* srow = Sp + (size_t)m * Sn + kt * 128;
            #pragma unroll
            for (int tn = 0; tn < 8; tn++) {
                const int n = n0 + tn * 8 + t * 2;
                *(float2*)(srow + n) = make_float2(c[tm][tn][half * 2 + 0] * scale,
                                                   c[tm][tn][half * 2 + 1] * scale);
            }
        }
    }
}

// ---------------- K3: per-column (over q) max + sum-exp ------------------------
__global__ void colstats_kernel() {
    const int b = blockIdx.y;
    const int k = blockIdx.x * 256 + threadIdx.x;
    const float* Sp = g_Sc + (size_t)b * Sn * Sn;
    float m = -3.4e38f, z = 0.f;
    for (int q = 0; q < Sn; q += 4) {
        float sv[4];
        sv[0] = Sp[(size_t)(q + 0) * Sn + k];
        sv[1] = Sp[(size_t)(q + 1) * Sn + k];
        sv[2] = Sp[(size_t)(q + 2) * Sn + k];
        sv[3] = Sp[(size_t)(q + 3) * Sn + k];
        #pragma unroll
        for (int u = 0; u < 4; u++) {
            float s = sv[u];
            if (s <= m) z += __expf(s - m);
            else { z = z * __expf(m - s) + 1.0f; m = s; }
        }
    }
    g_m[b * Sn + k]  = m;
    g_Zr[b * Sn + k] = 1.0f / z;
}

// ---------------- K3b: V^T with 1/Z folded, bf16 hi/lo -------------------------
__global__ __launch_bounds__(256)
void vtrans_kernel() {
    __shared__ ushort shh[64][65], shl[64][65];   // [d][k]
    const int b  = blockIdx.z;
    const int d0 = blockIdx.y * 64;
    const int k0 = blockIdx.x * 64;
    const int tt = threadIdx.x;
    {
        const int k   = tt >> 2;
        const int d16 = (tt & 3) * 16;
        const float zr = __ldg(g_Zr + b * Sn + k0 + k);
        const float* vp = g_V + ((size_t)b * Sn + k0 + k) * Yn + d0 + d16;
        #pragma unroll
        for (int j = 0; j < 4; j++) {
            float4 v = *(const float4*)(vp + j * 4);
            ushort h0, h1, h2, h3, l0, l1, l2, l3;
            split1(v.x * zr, h0, l0); split1(v.y * zr, h1, l1);
            split1(v.z * zr, h2, l2); split1(v.w * zr, h3, l3);
            const int dd = d16 + j * 4;
            shh[dd + 0][k] = h0; shh[dd + 1][k] = h1; shh[dd + 2][k] = h2; shh[dd + 3][k] = h3;
            shl[dd + 0][k] = l0; shl[dd + 1][k] = l1; shl[dd + 2][k] = l2; shl[dd + 3][k] = l3;
        }
    }
    __syncthreads();
    {
        const int d  = tt >> 2;
        const int kq = (tt & 3) * 16;
        __nv_bfloat16* oh = g_Vth + ((size_t)b * Yn + d0 + d) * Sn + k0 + kq;
        __nv_bfloat16* ol = g_Vtl + ((size_t)b * Yn + d0 + d) * Sn + k0 + kq;
        #pragma unroll
        for (int p = 0; p < 2; p++) {
            uint4 u;
            u.x = (uint)shh[d][kq+p*8+0] | ((uint)shh[d][kq+p*8+1] << 16);
            u.y = (uint)shh[d][kq+p*8+2] | ((uint)shh[d][kq+p*8+3] << 16);
            u.z = (uint)shh[d][kq+p*8+4] | ((uint)shh[d][kq+p*8+5] << 16);
            u.w = (uint)shh[d][kq+p*8+6] | ((uint)shh[d][kq+p*8+7] << 16);
            *(uint4*)(oh + p * 8) = u;
            u.x = (uint)shl[d][kq+p*8+0] | ((uint)shl[d][kq+p*8+1] << 16);
            u.y = (uint)shl[d][kq+p*8+2] | ((uint)shl[d][kq+p*8+3] << 16);
            u.z = (uint)shl[d][kq+p*8+4] | ((uint)shl[d][kq+p*8+5] << 16);
            u.w = (uint)shl[d][kq+p*8+6] | ((uint)shl[d][kq+p*8+7] << 16);
            *(uint4*)(ol + p * 8) = u;
        }
    }
}

// ---------------- K4: PV + fused max -------------------------------------------
// grid (8, 64): O[q][d] = sum_k exp(S - m[k]) * (V/Z)[k][d]; out[b][d] = max_q O
__global__ __launch_bounds__(256, 1)
void pv_mma_kernel(float* __restrict__ out) {
    extern __shared__ ushort sh[];
    const int tid = threadIdx.x;
    const int w = tid >> 5, lane = tid & 31, t = lane & 3;
    const int m0 = (w & 3) * 32, n0 = (w >> 2) * 64;
    const int qt = blockIdx.x, b = blockIdx.y;

    const uint32_t base = smem_u32(sh);
    const uint32_t aoff = a_lane_off(m0, lane), boff = b_lane_off(n0, lane);
    const uint32_t aH = base + T_AH * 2 + aoff, aL = base + T_AL * 2 + aoff;
    const uint32_t bH = base + T_BH * 2 + boff, bL = base + T_BL * 2 + boff;

    const float* Sp = g_Sc + (size_t)b * Sn * Sn;
    const float* mp = g_m + b * Sn;

    float c[2][8][4];
    #pragma unroll
    for (int i = 0; i < 2; i++)
        #pragma unroll
        for (int j = 0; j < 8; j++)
            #pragma unroll
            for (int r = 0; r < 4; r++) c[i][j][r] = 0.f;

    for (int ch = 0; ch < 8; ch++) {
        const int kc = ch * 128;
        // A tile: exp(S - m) hi/lo, computed on the fly
        #pragma unroll
        for (int it = 0; it < 16; it++) {
            const int idx = it * 256 + tid;
            const int row = idx >> 5;
            const int c4  = (idx & 31) << 2;
            float4 s  = *(const float4*)(Sp + (size_t)(qt * 128 + row) * Sn + kc + c4);
            float4 mm = *(const float4*)(mp + kc + c4);
            ushort h[4], l[4];
            split1(__expf(s.x - mm.x), h[0], l[0]);
            split1(__expf(s.y - mm.y), h[1], l[1]);
            split1(__expf(s.z - mm.z), h[2], l[2]);
            split1(__expf(s.w - mm.w), h[3], l[3]);
            const int off = row * TSTR + c4;
            *(uint2*)(sh + T_AH + off) = make_uint2((uint)h[0] | ((uint)h[1] << 16),
                                                    (uint)h[2] | ((uint)h[3] << 16));
            *(uint2*)(sh + T_AL + off) = make_uint2((uint)l[0] | ((uint)l[1] << 16),
                                                    (uint)l[2] | ((uint)l[3] << 16));
        }
        fill_tile(sh + T_BH, g_Vth + (size_t)b * Yn * Sn + kc, Sn, tid);
        fill_tile(sh + T_BL, g_Vtl + (size_t)b * Yn * Sn + kc, Sn, tid);
        __syncthreads();
        warp_mma_chunk(c, aH, aL, bH, bL);
        __syncthreads();
    }

    // fused max over q: thread-local max over tm/half, shuffle-reduce over g,
    // then one atomic per (warp, n).
    #pragma unroll
    for (int tn = 0; tn < 8; tn++) {
        #pragma unroll
        for (int par = 0; par < 2; par++) {
            float v = c[0][tn][par];
            v = fmaxf(v, c[0][tn][2 + par]);
            v = fmaxf(v, c[1][tn][par]);
            v = fmaxf(v, c[1][tn][2 + par]);
            v = fmaxf(v, __shfl_xor_sync(0xFFFFFFFF, v, 4));
            v = fmaxf(v, __shfl_xor_sync(0xFFFFFFFF, v, 8));
            v = fmaxf(v, __shfl_xor_sync(0xFFFFFFFF, v, 16));
            if (lane < 4)
                atomicMaxF(out + b * Yn + n0 + tn * 8 + t * 2 + par, v);
        }
    }
}

// ============================================================================
extern "C" void kernel_launch(void* const* d_in, const int* in_sizes, int n_in,
                              void* d_out, int out_size)
{
    const float* q  = (const float*)d_in[0];
    const float* Wq = (const float*)d_in[1];
    const float* bq = (const float*)d_in[2];
    const float* Wk = (const float*)d_in[3];
    const float* bk = (const float*)d_in[4];
    const float* Wv = (const float*)d_in[5];
    const float* bv = (const float*)d_in[6];
    float* out = (float*)d_out;

    cudaFuncSetAttribute(qkv_mma_kernel,    cudaFuncAttributeMaxDynamicSharedMemorySize, SM_TOTAL);
    cudaFuncSetAttribute(scores_mma_kernel, cudaFuncAttributeMaxDynamicSharedMemorySize, SM_TOTAL);
    cudaFuncSetAttribute(pv_mma_kernel,     cudaFuncAttributeMaxDynamicSharedMemorySize, SM_TOTAL);

    split_q_kernel<<<(Bn * Sn * Xn) / 1024, 256>>>(q);
    split_w_kernel<<<(Yn * Xn) / 1024, 256>>>(Wq, 0);
    split_w_kernel<<<(Yn * Xn) / 1024, 256>>>(Wk, 1);
    split_w_kernel<<<(Yn * Xn) / 1024, 256>>>(Wv, 2);
    initout_kernel<<<(Bn * Yn) / 256, 256>>>(out);
    qkv_mma_kernel<<<dim3(Bn * Sn / 128, 3), 256, SM_TOTAL>>>(bq, bk, bv);
    scores_mma_kernel<<<dim3(Sn / 128, Sn / 128, Bn), 256, SM_TOTAL>>>();
    colstats_kernel<<<dim3(Sn / 256, Bn), 256>>>();
    vtrans_kernel<<<dim3(Sn / 64, Yn / 64, Bn), 256>>>();
    pv_mma_kernel<<<dim3(Sn / 128, Bn), 256, SM_TOTAL>>>(out);
}

// round 6
// speedup vs baseline: 2.2846x; 1.2106x over previous
#include <cuda_runtime.h>
#include <cuda_bf16.h>
#include <cstdint>

#define Bn 64
#define Sn 1024
#define Xn 256
#define Yn 128

typedef unsigned int uint;
typedef unsigned short ushort;

// ---------------- scratch (device globals: no cudaMalloc allowed) ----------
__device__ __nv_bfloat16 g_qh[Bn * Sn * Xn];   // q split hi
__device__ __nv_bfloat16 g_ql[Bn * Sn * Xn];   // q split lo
__device__ __nv_bfloat16 g_Wh[3][Yn * Xn];     // Wq/Wk/Wv hi
__device__ __nv_bfloat16 g_Wl[3][Yn * Xn];     // Wq/Wk/Wv lo
__device__ __nv_bfloat16 g_Qh[Bn * Sn * Yn], g_Ql[Bn * Sn * Yn];
__device__ __nv_bfloat16 g_Kh[Bn * Sn * Yn], g_Kl[Bn * Sn * Yn];
__device__ float         g_V [Bn * Sn * Yn];              // V fp32 (pre-norm)
__device__ float         g_Sc[(size_t)Bn * Sn * Sn];      // 256MB scores
__device__ float         g_pm[Bn * 8 * Sn];               // per-(b,qt,k) tile col max
__device__ float         g_pz[Bn * 8 * Sn];               // per-(b,qt,k) tile col sum
__device__ float         g_m [Bn * Sn];                   // col max
__device__ float         g_Zr[Bn * Sn];                   // col 1/sum
__device__ __nv_bfloat16 g_Vth[Bn * Yn * Sn], g_Vtl[Bn * Yn * Sn]; // V^T/Z hi/lo [b][d][k]

// ---------------- shared tile layout (halves; padded stride) -----------------
#define TSTR  136                      // 128 + 8 halves pad -> conflict-free
#define T_AH  0
#define T_AL  (128 * TSTR)
#define T_BH  (2 * 128 * TSTR)
#define T_BL  (3 * 128 * TSTR)
#define SM_TOTAL (4 * 128 * TSTR * 2)  // 139264 bytes (qkv / scores)
// pv: A hi/lo single + B hi/lo double-buffered
#define PV_BH(s) ((2 + 2 * (s)) * 128 * TSTR)
#define PV_BL(s) ((3 + 2 * (s)) * 128 * TSTR)
#define SM_TOTAL_PV (6 * 128 * TSTR * 2)   // 208896 bytes

// ---------------- helpers ------------------------------------------------------
__device__ __forceinline__ void split1(float v, ushort& h, ushort& l) {
    __nv_bfloat16 hb = __float2bfloat16(v);
    __nv_bfloat16 lb = __float2bfloat16(v - __bfloat162float(hb));
    h = __bfloat16_as_ushort(hb);
    l = __bfloat16_as_ushort(lb);
}

__device__ __forceinline__ uint32_t smem_u32(const void* p) {
    uint32_t a;
    asm("{ .reg .u64 t; cvta.to.shared.u64 t, %1; cvt.u32.u64 %0, t; }" : "=r"(a) : "l"(p));
    return a;
}

__device__ __forceinline__ void mma16816(float* c, const uint* a, const uint* b) {
    asm volatile("mma.sync.aligned.m16n8k16.row.col.f32.bf16.bf16.f32 "
        "{%0,%1,%2,%3}, {%4,%5,%6,%7}, {%8,%9}, {%0,%1,%2,%3};"
        : "+f"(c[0]), "+f"(c[1]), "+f"(c[2]), "+f"(c[3])
        : "r"(a[0]), "r"(a[1]), "r"(a[2]), "r"(a[3]), "r"(b[0]), "r"(b[1]));
}

#define LDSM4(r0, r1, r2, r3, addr) \
    asm volatile("ldmatrix.sync.aligned.m8n8.x4.shared.b16 {%0,%1,%2,%3}, [%4];" \
        : "=r"(r0), "=r"(r1), "=r"(r2), "=r"(r3) : "r"(addr))

#define CP_ASYNC16(dst, src) \
    asm volatile("cp.async.cg.shared.global [%0], [%1], 16;" :: "r"(dst), "l"(src))
#define CP_COMMIT() asm volatile("cp.async.commit_group;" ::: "memory")
#define CP_WAIT(N)  asm volatile("cp.async.wait_group %0;" :: "n"(N) : "memory")

__device__ __forceinline__ void atomicMaxF(float* a, float v) {
    if (v >= 0.f) atomicMax((int*)a, __float_as_int(v));
    else          atomicMin((uint*)a, (uint)__float_as_int(v));
}

// Async tile fill: 128 rows x 128 bf16 into padded shared (16B per cp.async).
__device__ __forceinline__ void fill_tile_async(uint32_t dst, const __nv_bfloat16* src,
                                                int stride, int tid) {
    #pragma unroll
    for (int it = 0; it < 8; it++) {
        int idx  = it * 256 + tid;
        int row  = idx >> 4;
        int col8 = (idx & 15) << 3;
        CP_ASYNC16(dst + (uint32_t)(row * TSTR + col8) * 2,
                   src + (size_t)row * stride + col8);
    }
}

// Warp compute over one 128x128(x128k) chunk via ldmatrix; fragments loaded once
// per k-step and reused across all 3 split passes (hi*hi + hi*lo + lo*hi).
__device__ __forceinline__ void warp_mma_chunk(float (&c)[2][8][4],
        uint32_t aH, uint32_t aL, uint32_t bH, uint32_t bL) {
    #pragma unroll
    for (int ks = 0; ks < 8; ks++) {
        const uint32_t ko = ks * 32;   // 16 halves per k-step
        uint ah[2][4], al[2][4], bh[4][4], bl[4][4];
        #pragma unroll
        for (int tm = 0; tm < 2; tm++) {
            LDSM4(ah[tm][0], ah[tm][1], ah[tm][2], ah[tm][3], aH + tm * (16 * TSTR * 2) + ko);
            LDSM4(al[tm][0], al[tm][1], al[tm][2], al[tm][3], aL + tm * (16 * TSTR * 2) + ko);
        }
        #pragma unroll
        for (int p = 0; p < 4; p++) {
            LDSM4(bh[p][0], bh[p][1], bh[p][2], bh[p][3], bH + p * (16 * TSTR * 2) + ko);
            LDSM4(bl[p][0], bl[p][1], bl[p][2], bl[p][3], bL + p * (16 * TSTR * 2) + ko);
        }
        #pragma unroll
        for (int tm = 0; tm < 2; tm++) {
            #pragma unroll
            for (int tn = 0; tn < 8; tn++) {
                const int p = tn >> 1, s = (tn & 1) * 2;
                mma16816(c[tm][tn], ah[tm], &bh[p][s]);   // hi * hi
                mma16816(c[tm][tn], ah[tm], &bl[p][s]);   // hi * lo
                mma16816(c[tm][tn], al[tm], &bh[p][s]);   // lo * hi
            }
        }
    }
}

__device__ __forceinline__ uint32_t a_lane_off(int m0, int lane) {
    int r = lane & 7, grp = lane >> 3;
    return (uint32_t)(((m0 + (grp & 1) * 8 + r) * TSTR + (grp >> 1) * 8) * 2);
}
__device__ __forceinline__ uint32_t b_lane_off(int n0, int lane) {
    int r = lane & 7, grp = lane >> 3;
    return (uint32_t)(((n0 + (grp >> 1) * 8 + r) * TSTR + (grp & 1) * 8) * 2);
}

// ---------------- K0: fp32 -> bf16 hi/lo split --------------------------------
__global__ void split_q_kernel(const float* __restrict__ src) {
    int i = (blockIdx.x * 256 + threadIdx.x) * 4;
    float4 v = *(const float4*)(src + i);
    ushort h0, h1, h2, h3, l0, l1, l2, l3;
    split1(v.x, h0, l0); split1(v.y, h1, l1); split1(v.z, h2, l2); split1(v.w, h3, l3);
    *(uint2*)(g_qh + i) = make_uint2((uint)h0 | ((uint)h1 << 16), (uint)h2 | ((uint)h3 << 16));
    *(uint2*)(g_ql + i) = make_uint2((uint)l0 | ((uint)l1 << 16), (uint)l2 | ((uint)l3 << 16));
}
__global__ void split_w_kernel(const float* __restrict__ src, int sel) {
    int i = (blockIdx.x * 256 + threadIdx.x) * 4;
    float4 v = *(const float4*)(src + i);
    ushort h0, h1, h2, h3, l0, l1, l2, l3;
    split1(v.x, h0, l0); split1(v.y, h1, l1); split1(v.z, h2, l2); split1(v.w, h3, l3);
    *(uint2*)(g_Wh[sel] + i) = make_uint2((uint)h0 | ((uint)h1 << 16), (uint)h2 | ((uint)h3 << 16));
    *(uint2*)(g_Wl[sel] + i) = make_uint2((uint)l0 | ((uint)l1 << 16), (uint)l2 | ((uint)l3 << 16));
}

// ---------------- init d_out to -inf -------------------------------------------
__global__ void initout_kernel(float* __restrict__ out) {
    out[blockIdx.x * 256 + threadIdx.x] = __int_as_float(0xFF800000);
}

// ---------------- K1: QKV projection ------------------------------------------
__global__ __launch_bounds__(256, 1)
void qkv_mma_kernel(const float* __restrict__ bq, const float* __restrict__ bk,
                    const float* __restrict__ bv) {
    extern __shared__ ushort sh[];
    const int tid = threadIdx.x;
    const int w = tid >> 5, lane = tid & 31, g = lane >> 2, t = lane & 3;
    const int m0 = (w & 3) * 32, n0 = (w >> 2) * 64;
    const int rowBase = blockIdx.x * 128;
    const int sel = blockIdx.y;

    const uint32_t base = smem_u32(sh);
    const uint32_t aoff = a_lane_off(m0, lane), boff = b_lane_off(n0, lane);
    const uint32_t aH = base + T_AH * 2 + aoff, aL = base + T_AL * 2 + aoff;
    const uint32_t bH = base + T_BH * 2 + boff, bL = base + T_BL * 2 + boff;

    float c[2][8][4];
    #pragma unroll
    for (int i = 0; i < 2; i++)
        #pragma unroll
        for (int j = 0; j < 8; j++)
            #pragma unroll
            for (int r = 0; r < 4; r++) c[i][j][r] = 0.f;

    for (int ch = 0; ch < 2; ch++) {
        const int kc = ch * 128;
        fill_tile_async(base + T_AH * 2, g_qh + (size_t)rowBase * Xn + kc, Xn, tid);
        fill_tile_async(base + T_AL * 2, g_ql + (size_t)rowBase * Xn + kc, Xn, tid);
        fill_tile_async(base + T_BH * 2, g_Wh[sel] + kc, Xn, tid);
        fill_tile_async(base + T_BL * 2, g_Wl[sel] + kc, Xn, tid);
        CP_COMMIT();
        CP_WAIT(0);
        __syncthreads();
        warp_mma_chunk(c, aH, aL, bH, bL);
        __syncthreads();
    }

    const float* bias = (sel == 0) ? bq : (sel == 1) ? bk : bv;
    #pragma unroll
    for (int tm = 0; tm < 2; tm++) {
        #pragma unroll
        for (int half = 0; half < 2; half++) {
            const int mloc = m0 + tm * 16 + g + half * 8;
            const size_t row = (size_t)(rowBase + mloc) * Yn;
            #pragma unroll
            for (int tn = 0; tn < 8; tn++) {
                const int n = n0 + tn * 8 + t * 2;
                float v0 = c[tm][tn][half * 2 + 0] + __ldg(bias + n);
                float v1 = c[tm][tn][half * 2 + 1] + __ldg(bias + n + 1);
                if (sel < 2) {
                    __nv_bfloat16* dh = (sel == 0) ? g_Qh : g_Kh;
                    __nv_bfloat16* dl = (sel == 0) ? g_Ql : g_Kl;
                    ushort h0, h1, l0, l1;
                    split1(v0, h0, l0); split1(v1, h1, l1);
                    *(uint*)(dh + row + n) = (uint)h0 | ((uint)h1 << 16);
                    *(uint*)(dl + row + n) = (uint)l0 | ((uint)l1 << 16);
                } else {
                    *(float2*)(g_V + row + n) = make_float2(v0, v1);
                }
            }
        }
    }
}

// ---------------- K2: scores + fused per-tile column stats ---------------------
__global__ __launch_bounds__(256, 1)
void scores_mma_kernel() {
    extern __shared__ ushort sh[];
    const int tid = threadIdx.x;
    const int w = tid >> 5, lane = tid & 31, g = lane >> 2, t = lane & 3;
    const int m0 = (w & 3) * 32, n0 = (w >> 2) * 64, mw = w & 3;
    const int kt = blockIdx.x, qt = blockIdx.y, b = blockIdx.z;

    const uint32_t base = smem_u32(sh);
    const uint32_t aoff = a_lane_off(m0, lane), boff = b_lane_off(n0, lane);

    float c[2][8][4];
    #pragma unroll
    for (int i = 0; i < 2; i++)
        #pragma unroll
        for (int j = 0; j < 8; j++)
            #pragma unroll
            for (int r = 0; r < 4; r++) c[i][j][r] = 0.f;

    const size_t qoff = ((size_t)b * Sn + qt * 128) * Yn;
    const size_t koff = ((size_t)b * Sn + kt * 128) * Yn;
    fill_tile_async(base + T_AH * 2, g_Qh + qoff, Yn, tid);
    fill_tile_async(base + T_AL * 2, g_Ql + qoff, Yn, tid);
    fill_tile_async(base + T_BH * 2, g_Kh + koff, Yn, tid);
    fill_tile_async(base + T_BL * 2, g_Kl + koff, Yn, tid);
    CP_COMMIT();
    CP_WAIT(0);
    __syncthreads();
    warp_mma_chunk(c, base + T_AH * 2 + aoff, base + T_AL * 2 + aoff,
                   base + T_BH * 2 + boff, base + T_BL * 2 + boff);

    const float scale = 0.08838834764831845f;  // 1/sqrt(128)
    float* Sp = g_Sc + (size_t)b * Sn * Sn;
    #pragma unroll
    for (int tm = 0; tm < 2; tm++) {
        #pragma unroll
        for (int half = 0; half < 2; half++) {
            const int m = qt * 128 + m0 + tm * 16 + g + half * 8;
            float* srow = Sp + (size_t)m * Sn + kt * 128;
            #pragma unroll
            for (int tn = 0; tn < 8; tn++) {
                const int n = n0 + tn * 8 + t * 2;
                *(float2*)(srow + n) = make_float2(c[tm][tn][half * 2 + 0] * scale,
                                                   c[tm][tn][half * 2 + 1] * scale);
            }
        }
    }

    // fused per-tile column stats (max + sum-exp over this CTA's 128 q rows)
    __syncthreads();                       // tiles no longer needed; reuse smem
    float* smax = (float*)sh;              // [128][4]
    float* szz  = (float*)sh + 512;        // [128][4]

    float vm[16];
    #pragma unroll
    for (int tn = 0; tn < 8; tn++) {
        #pragma unroll
        for (int par = 0; par < 2; par++) {
            float v = fmaxf(fmaxf(c[0][tn][par], c[0][tn][2 + par]),
                            fmaxf(c[1][tn][par], c[1][tn][2 + par])) * scale;
            v = fmaxf(v, __shfl_xor_sync(0xFFFFFFFF, v, 4));
            v = fmaxf(v, __shfl_xor_sync(0xFFFFFFFF, v, 8));
            v = fmaxf(v, __shfl_xor_sync(0xFFFFFFFF, v, 16));
            vm[tn * 2 + par] = v;
        }
    }
    if (lane < 4) {
        #pragma unroll
        for (int tn = 0; tn < 8; tn++)
            #pragma unroll
            for (int par = 0; par < 2; par++)
                smax[(n0 + tn * 8 + t * 2 + par) * 4 + mw] = vm[tn * 2 + par];
    }
    __syncthreads();
    float vz[16];
    #pragma unroll
    for (int tn = 0; tn < 8; tn++) {
        #pragma unroll
        for (int par = 0; par < 2; par++) {
            const int n = n0 + tn * 8 + t * 2 + par;
            const float mt = fmaxf(fmaxf(smax[n * 4 + 0], smax[n * 4 + 1]),
                                   fmaxf(smax[n * 4 + 2], smax[n * 4 + 3]));
            float z = __expf(c[0][tn][par] * scale - mt)
                    + __expf(c[0][tn][2 + par] * scale - mt)
                    + __expf(c[1][tn][par] * scale - mt)
                    + __expf(c[1][tn][2 + par] * scale - mt);
            z += __shfl_xor_sync(0xFFFFFFFF, z, 4);
            z += __shfl_xor_sync(0xFFFFFFFF, z, 8);
            z += __shfl_xor_sync(0xFFFFFFFF, z, 16);
            vz[tn * 2 + par] = z;
        }
    }
    if (lane < 4) {
        #pragma unroll
        for (int tn = 0; tn < 8; tn++)
            #pragma unroll
            for (int par = 0; par < 2; par++)
                szz[(n0 + tn * 8 + t * 2 + par) * 4 + mw] = vz[tn * 2 + par];
    }
    __syncthreads();
    if (tid < 128) {
        const int n = tid;
        const float mt = fmaxf(fmaxf(smax[n * 4 + 0], smax[n * 4 + 1]),
                               fmaxf(smax[n * 4 + 2], smax[n * 4 + 3]));
        const float z = szz[n * 4 + 0] + szz[n * 4 + 1] + szz[n * 4 + 2] + szz[n * 4 + 3];
        const size_t o = ((size_t)(b * 8 + qt)) * Sn + kt * 128 + n;
        g_pm[o] = mt;
        g_pz[o] = z;
    }
}

// ---------------- K3: combine per-tile stats -> g_m, g_Zr ----------------------
__global__ void combine_kernel() {
    const int b = blockIdx.y;
    const int k = blockIdx.x * 256 + threadIdx.x;
    float m = -3.4e38f;
    #pragma unroll
    for (int i = 0; i < 8; i++)
        m = fmaxf(m, g_pm[((size_t)(b * 8 + i)) * Sn + k]);
    float z = 0.f;
    #pragma unroll
    for (int i = 0; i < 8; i++) {
        const size_t o = ((size_t)(b * 8 + i)) * Sn + k;
        z += g_pz[o] * __expf(g_pm[o] - m);
    }
    g_m[b * Sn + k]  = m;
    g_Zr[b * Sn + k] = 1.0f / z;
}

// ---------------- K3b: V^T with 1/Z folded, bf16 hi/lo -------------------------
__global__ __launch_bounds__(256)
void vtrans_kernel() {
    __shared__ ushort shh[64][65], shl[64][65];   // [d][k]
    const int b  = blockIdx.z;
    const int d0 = blockIdx.y * 64;
    const int k0 = blockIdx.x * 64;
    const int tt = threadIdx.x;
    {
        const int k   = tt >> 2;
        const int d16 = (tt & 3) * 16;
        const float zr = __ldg(g_Zr + b * Sn + k0 + k);
        const float* vp = g_V + ((size_t)b * Sn + k0 + k) * Yn + d0 + d16;
        #pragma unroll
        for (int j = 0; j < 4; j++) {
            float4 v = *(const float4*)(vp + j * 4);
            ushort h0, h1, h2, h3, l0, l1, l2, l3;
            split1(v.x * zr, h0, l0); split1(v.y * zr, h1, l1);
            split1(v.z * zr, h2, l2); split1(v.w * zr, h3, l3);
            const int dd = d16 + j * 4;
            shh[dd + 0][k] = h0; shh[dd + 1][k] = h1; shh[dd + 2][k] = h2; shh[dd + 3][k] = h3;
            shl[dd + 0][k] = l0; shl[dd + 1][k] = l1; shl[dd + 2][k] = l2; shl[dd + 3][k] = l3;
        }
    }
    __syncthreads();
    {
        const int d  = tt >> 2;
        const int kq = (tt & 3) * 16;
        __nv_bfloat16* oh = g_Vth + ((size_t)b * Yn + d0 + d) * Sn + k0 + kq;
        __nv_bfloat16* ol = g_Vtl + ((size_t)b * Yn + d0 + d) * Sn + k0 + kq;
        #pragma unroll
        for (int p = 0; p < 2; p++) {
            uint4 u;
            u.x = (uint)shh[d][kq+p*8+0] | ((uint)shh[d][kq+p*8+1] << 16);
            u.y = (uint)shh[d][kq+p*8+2] | ((uint)shh[d][kq+p*8+3] << 16);
            u.z = (uint)shh[d][kq+p*8+4] | ((uint)shh[d][kq+p*8+5] << 16);
            u.w = (uint)shh[d][kq+p*8+6] | ((uint)shh[d][kq+p*8+7] << 16);
            *(uint4*)(oh + p * 8) = u;
            u.x = (uint)shl[d][kq+p*8+0] | ((uint)shl[d][kq+p*8+1] << 16);
            u.y = (uint)shl[d][kq+p*8+2] | ((uint)shl[d][kq+p*8+3] << 16);
            u.z = (uint)shl[d][kq+p*8+4] | ((uint)shl[d][kq+p*8+5] << 16);
            u.w = (uint)shl[d][kq+p*8+6] | ((uint)shl[d][kq+p*8+7] << 16);
            *(uint4*)(ol + p * 8) = u;
        }
    }
}

// ---------------- K4: PV + fused max, cp.async double-buffered B ----------------
__global__ __launch_bounds__(256, 1)
void pv_mma_kernel(float* __restrict__ out) {
    extern __shared__ ushort sh[];
    const int tid = threadIdx.x;
    const int w = tid >> 5, lane = tid & 31, t = lane & 3;
    const int m0 = (w & 3) * 32, n0 = (w >> 2) * 64;
    const int qt = blockIdx.x, b = blockIdx.y;

    const uint32_t base = smem_u32(sh);
    const uint32_t aoff = a_lane_off(m0, lane), boff = b_lane_off(n0, lane);
    const uint32_t aH = base + T_AH * 2 + aoff, aL = base + T_AL * 2 + aoff;

    const float* Sp = g_Sc + (size_t)b * Sn * Sn;
    const float* mp = g_m + b * Sn;
    const __nv_bfloat16* Vh = g_Vth + (size_t)b * Yn * Sn;
    const __nv_bfloat16* Vl = g_Vtl + (size_t)b * Yn * Sn;

    float c[2][8][4];
    #pragma unroll
    for (int i = 0; i < 2; i++)
        #pragma unroll
        for (int j = 0; j < 8; j++)
            #pragma unroll
            for (int r = 0; r < 4; r++) c[i][j][r] = 0.f;

    // prefetch chunk 0 B tiles into stage 0
    fill_tile_async(base + PV_BH(0) * 2, Vh, Sn, tid);
    fill_tile_async(base + PV_BL(0) * 2, Vl, Sn, tid);
    CP_COMMIT();

    for (int ch = 0; ch < 8; ch++) {
        const int kc = ch * 128;
        const int stage = ch & 1;
        // A tile: exp(S - m) hi/lo, computed on the fly (plain stores)
        #pragma unroll
        for (int it = 0; it < 16; it++) {
            const int idx = it * 256 + tid;
            const int row = idx >> 5;
            const int c4  = (idx & 31) << 2;
            float4 s  = *(const float4*)(Sp + (size_t)(qt * 128 + row) * Sn + kc + c4);
            float4 mm = *(const float4*)(mp + kc + c4);
            ushort h[4], l[4];
            split1(__expf(s.x - mm.x), h[0], l[0]);
            split1(__expf(s.y - mm.y), h[1], l[1]);
            split1(__expf(s.z - mm.z), h[2], l[2]);
            split1(__expf(s.w - mm.w), h[3], l[3]);
            const int off = row * TSTR + c4;
            *(uint2*)(sh + T_AH + off) = make_uint2((uint)h[0] | ((uint)h[1] << 16),
                                                    (uint)h[2] | ((uint)h[3] << 16));
            *(uint2*)(sh + T_AL + off) = make_uint2((uint)l[0] | ((uint)l[1] << 16),
                                                    (uint)l[2] | ((uint)l[3] << 16));
        }
        if (ch < 7) {
            fill_tile_async(base + PV_BH(stage ^ 1) * 2, Vh + kc + 128, Sn, tid);
            fill_tile_async(base + PV_BL(stage ^ 1) * 2, Vl + kc + 128, Sn, tid);
            CP_COMMIT();
            CP_WAIT(1);       // current stage's tiles are complete
        } else {
            CP_WAIT(0);
        }
        __syncthreads();
        warp_mma_chunk(c, aH, aL,
                       base + PV_BH(stage) * 2 + boff, base + PV_BL(stage) * 2 + boff);
        __syncthreads();
    }

    // fused max over q: thread-local max, shuffle-reduce over g, one atomic per n.
    #pragma unroll
    for (int tn = 0; tn < 8; tn++) {
        #pragma unroll
        for (int par = 0; par < 2; par++) {
            float v = c[0][tn][par];
            v = fmaxf(v, c[0][tn][2 + par]);
            v = fmaxf(v, c[1][tn][par]);
            v = fmaxf(v, c[1][tn][2 + par]);
            v = fmaxf(v, __shfl_xor_sync(0xFFFFFFFF, v, 4));
            v = fmaxf(v, __shfl_xor_sync(0xFFFFFFFF, v, 8));
            v = fmaxf(v, __shfl_xor_sync(0xFFFFFFFF, v, 16));
            if (lane < 4)
                atomicMaxF(out + b * Yn + n0 + tn * 8 + t * 2 + par, v);
        }
    }
}

// ============================================================================
extern "C" void kernel_launch(void* const* d_in, const int* in_sizes, int n_in,
                              void* d_out, int out_size)
{
    const float* q  = (const float*)d_in[0];
    const float* Wq = (const float*)d_in[1];
    const float* bq = (const float*)d_in[2];
    const float* Wk = (const float*)d_in[3];
    const float* bk = (const float*)d_in[4];
    const float* Wv = (const float*)d_in[5];
    const float* bv = (const float*)d_in[6];
    float* out = (float*)d_out;

    cudaFuncSetAttribute(qkv_mma_kernel,    cudaFuncAttributeMaxDynamicSharedMemorySize, SM_TOTAL);
    cudaFuncSetAttribute(scores_mma_kernel, cudaFuncAttributeMaxDynamicSharedMemorySize, SM_TOTAL);
    cudaFuncSetAttribute(pv_mma_kernel,     cudaFuncAttributeMaxDynamicSharedMemorySize, SM_TOTAL_PV);

    split_q_kernel<<<(Bn * Sn * Xn) / 1024, 256>>>(q);
    split_w_kernel<<<(Yn * Xn) / 1024, 256>>>(Wq, 0);
    split_w_kernel<<<(Yn * Xn) / 1024, 256>>>(Wk, 1);
    split_w_kernel<<<(Yn * Xn) / 1024, 256>>>(Wv, 2);
    initout_kernel<<<(Bn * Yn) / 256, 256>>>(out);
    qkv_mma_kernel<<<dim3(Bn * Sn / 128, 3), 256, SM_TOTAL>>>(bq, bk, bv);
    scores_mma_kernel<<<dim3(Sn / 128, Sn / 128, Bn), 256, SM_TOTAL>>>();
    combine_kernel<<<dim3(Sn / 256, Bn), 256>>>();
    vtrans_kernel<<<dim3(Sn / 64, Yn / 64, Bn), 256>>>();
    pv_mma_kernel<<<dim3(Sn / 128, Bn), 256, SM_TOTAL_PV>>>(out);
}

// round 7
// speedup vs baseline: 2.4216x; 1.0599x over previous
#include <cuda_runtime.h>
#include <cuda_bf16.h>
#include <cstdint>

#define Bn 64
#define Sn 1024
#define Xn 256
#define Yn 128

typedef unsigned int uint;
typedef unsigned short ushort;

// ---------------- scratch (device globals: no cudaMalloc allowed) ----------
__device__ __nv_bfloat16 g_qh[Bn * Sn * Xn];   // q split hi
__device__ __nv_bfloat16 g_ql[Bn * Sn * Xn];   // q split lo
__device__ __nv_bfloat16 g_Wh[3][Yn * Xn];     // Wq/Wk/Wv hi
__device__ __nv_bfloat16 g_Wl[3][Yn * Xn];     // Wq/Wk/Wv lo
__device__ __nv_bfloat16 g_Qh[Bn * Sn * Yn], g_Ql[Bn * Sn * Yn];
__device__ __nv_bfloat16 g_Kh[Bn * Sn * Yn], g_Kl[Bn * Sn * Yn];
__device__ float         g_V [Bn * Sn * Yn];              // V fp32 (pre-norm)
__device__ float         g_Sc[(size_t)Bn * Sn * Sn];      // 256MB scores
__device__ float         g_pz[Bn * 8 * Sn];               // per-(b,qt,k) tile col sum-exp
__device__ float         g_Zr[Bn * Sn];                   // col 1/sum
__device__ __nv_bfloat16 g_Vth[Bn * Yn * Sn], g_Vtl[Bn * Yn * Sn]; // V^T/Z hi/lo [b][d][k]

// ---------------- shared tile layout (halves; padded stride) -----------------
// 144 halves = 288 B row stride: row r starts at byte 16*r (mod 128) ->
// ldmatrix phases read 8 rows at 8 DISTINCT 16B groups (conflict-free).
#define TSTR  144
#define T_AH  0
#define T_AL  (128 * TSTR)
#define T_BH  (2 * 128 * TSTR)
#define T_BL  (3 * 128 * TSTR)
#define SM_TOTAL (4 * 128 * TSTR * 2)      // 147456 bytes (qkv / scores)
#define PV_BH(s) ((2 + 2 * (s)) * 128 * TSTR)
#define PV_BL(s) ((3 + 2 * (s)) * 128 * TSTR)
#define SM_TOTAL_PV (6 * 128 * TSTR * 2)   // 221184 bytes

// ---------------- helpers ------------------------------------------------------
__device__ __forceinline__ void split1(float v, ushort& h, ushort& l) {
    __nv_bfloat16 hb = __float2bfloat16(v);
    __nv_bfloat16 lb = __float2bfloat16(v - __bfloat162float(hb));
    h = __bfloat16_as_ushort(hb);
    l = __bfloat16_as_ushort(lb);
}

__device__ __forceinline__ uint32_t smem_u32(const void* p) {
    uint32_t a;
    asm("{ .reg .u64 t; cvta.to.shared.u64 t, %1; cvt.u32.u64 %0, t; }" : "=r"(a) : "l"(p));
    return a;
}

__device__ __forceinline__ void mma16816(float* c, const uint* a, const uint* b) {
    asm volatile("mma.sync.aligned.m16n8k16.row.col.f32.bf16.bf16.f32 "
        "{%0,%1,%2,%3}, {%4,%5,%6,%7}, {%8,%9}, {%0,%1,%2,%3};"
        : "+f"(c[0]), "+f"(c[1]), "+f"(c[2]), "+f"(c[3])
        : "r"(a[0]), "r"(a[1]), "r"(a[2]), "r"(a[3]), "r"(b[0]), "r"(b[1]));
}

#define LDSM4(r0, r1, r2, r3, addr) \
    asm volatile("ldmatrix.sync.aligned.m8n8.x4.shared.b16 {%0,%1,%2,%3}, [%4];" \
        : "=r"(r0), "=r"(r1), "=r"(r2), "=r"(r3) : "r"(addr))

#define CP_ASYNC16(dst, src) \
    asm volatile("cp.async.cg.shared.global [%0], [%1], 16;" :: "r"(dst), "l"(src))
#define CP_COMMIT() asm volatile("cp.async.commit_group;" ::: "memory")
#define CP_WAIT(N)  asm volatile("cp.async.wait_group %0;" :: "n"(N) : "memory")

__device__ __forceinline__ void atomicMaxF(float* a, float v) {
    if (v >= 0.f) atomicMax((int*)a, __float_as_int(v));
    else          atomicMin((uint*)a, (uint)__float_as_int(v));
}

// Async tile fill: 128 rows x 128 bf16 into padded shared (16B per cp.async).
__device__ __forceinline__ void fill_tile_async(uint32_t dst, const __nv_bfloat16* src,
                                                int stride, int tid) {
    #pragma unroll
    for (int it = 0; it < 8; it++) {
        int idx  = it * 256 + tid;
        int row  = idx >> 4;
        int col8 = (idx & 15) << 3;
        CP_ASYNC16(dst + (uint32_t)(row * TSTR + col8) * 2,
                   src + (size_t)row * stride + col8);
    }
}

// Warp compute over one 128x128(x128k) chunk via ldmatrix; fragments loaded once
// per k-step and reused across all 3 split passes (hi*hi + hi*lo + lo*hi).
__device__ __forceinline__ void warp_mma_chunk(float (&c)[2][8][4],
        uint32_t aH, uint32_t aL, uint32_t bH, uint32_t bL) {
    #pragma unroll
    for (int ks = 0; ks < 8; ks++) {
        const uint32_t ko = ks * 32;   // 16 halves per k-step
        uint ah[2][4], al[2][4], bh[4][4], bl[4][4];
        #pragma unroll
        for (int tm = 0; tm < 2; tm++) {
            LDSM4(ah[tm][0], ah[tm][1], ah[tm][2], ah[tm][3], aH + tm * (16 * TSTR * 2) + ko);
            LDSM4(al[tm][0], al[tm][1], al[tm][2], al[tm][3], aL + tm * (16 * TSTR * 2) + ko);
        }
        #pragma unroll
        for (int p = 0; p < 4; p++) {
            LDSM4(bh[p][0], bh[p][1], bh[p][2], bh[p][3], bH + p * (16 * TSTR * 2) + ko);
            LDSM4(bl[p][0], bl[p][1], bl[p][2], bl[p][3], bL + p * (16 * TSTR * 2) + ko);
        }
        #pragma unroll
        for (int tm = 0; tm < 2; tm++) {
            #pragma unroll
            for (int tn = 0; tn < 8; tn++) {
                const int p = tn >> 1, s = (tn & 1) * 2;
                mma16816(c[tm][tn], ah[tm], &bh[p][s]);   // hi * hi
                mma16816(c[tm][tn], ah[tm], &bl[p][s]);   // hi * lo
                mma16816(c[tm][tn], al[tm], &bh[p][s]);   // lo * hi
            }
        }
    }
}

__device__ __forceinline__ uint32_t a_lane_off(int m0, int lane) {
    int r = lane & 7, grp = lane >> 3;
    return (uint32_t)(((m0 + (grp & 1) * 8 + r) * TSTR + (grp >> 1) * 8) * 2);
}
__device__ __forceinline__ uint32_t b_lane_off(int n0, int lane) {
    int r = lane & 7, grp = lane >> 3;
    return (uint32_t)(((n0 + (grp >> 1) * 8 + r) * TSTR + (grp & 1) * 8) * 2);
}

// ---------------- K0: fp32 -> bf16 hi/lo split --------------------------------
__global__ void split_q_kernel(const float* __restrict__ src) {
    int i = (blockIdx.x * 256 + threadIdx.x) * 4;
    float4 v = *(const float4*)(src + i);
    ushort h0, h1, h2, h3, l0, l1, l2, l3;
    split1(v.x, h0, l0); split1(v.y, h1, l1); split1(v.z, h2, l2); split1(v.w, h3, l3);
    *(uint2*)(g_qh + i) = make_uint2((uint)h0 | ((uint)h1 << 16), (uint)h2 | ((uint)h3 << 16));
    *(uint2*)(g_ql + i) = make_uint2((uint)l0 | ((uint)l1 << 16), (uint)l2 | ((uint)l3 << 16));
}
__global__ void split_w_kernel(const float* __restrict__ src, int sel) {
    int i = (blockIdx.x * 256 + threadIdx.x) * 4;
    float4 v = *(const float4*)(src + i);
    ushort h0, h1, h2, h3, l0, l1, l2, l3;
    split1(v.x, h0, l0); split1(v.y, h1, l1); split1(v.z, h2, l2); split1(v.w, h3, l3);
    *(uint2*)(g_Wh[sel] + i) = make_uint2((uint)h0 | ((uint)h1 << 16), (uint)h2 | ((uint)h3 << 16));
    *(uint2*)(g_Wl[sel] + i) = make_uint2((uint)l0 | ((uint)l1 << 16), (uint)l2 | ((uint)l3 << 16));
}

// ---------------- init d_out to -inf -------------------------------------------
__global__ void initout_kernel(float* __restrict__ out) {
    out[blockIdx.x * 256 + threadIdx.x] = __int_as_float(0xFF800000);
}

// ---------------- K1: QKV projection ------------------------------------------
__global__ __launch_bounds__(256, 1)
void qkv_mma_kernel(const float* __restrict__ bq, const float* __restrict__ bk,
                    const float* __restrict__ bv) {
    extern __shared__ ushort sh[];
    const int tid = threadIdx.x;
    const int w = tid >> 5, lane = tid & 31, g = lane >> 2, t = lane & 3;
    const int m0 = (w & 3) * 32, n0 = (w >> 2) * 64;
    const int rowBase = blockIdx.x * 128;
    const int sel = blockIdx.y;

    const uint32_t base = smem_u32(sh);
    const uint32_t aoff = a_lane_off(m0, lane), boff = b_lane_off(n0, lane);
    const uint32_t aH = base + T_AH * 2 + aoff, aL = base + T_AL * 2 + aoff;
    const uint32_t bH = base + T_BH * 2 + boff, bL = base + T_BL * 2 + boff;

    float c[2][8][4];
    #pragma unroll
    for (int i = 0; i < 2; i++)
        #pragma unroll
        for (int j = 0; j < 8; j++)
            #pragma unroll
            for (int r = 0; r < 4; r++) c[i][j][r] = 0.f;

    for (int ch = 0; ch < 2; ch++) {
        const int kc = ch * 128;
        fill_tile_async(base + T_AH * 2, g_qh + (size_t)rowBase * Xn + kc, Xn, tid);
        fill_tile_async(base + T_AL * 2, g_ql + (size_t)rowBase * Xn + kc, Xn, tid);
        fill_tile_async(base + T_BH * 2, g_Wh[sel] + kc, Xn, tid);
        fill_tile_async(base + T_BL * 2, g_Wl[sel] + kc, Xn, tid);
        CP_COMMIT();
        CP_WAIT(0);
        __syncthreads();
        warp_mma_chunk(c, aH, aL, bH, bL);
        __syncthreads();
    }

    const float* bias = (sel == 0) ? bq : (sel == 1) ? bk : bv;
    #pragma unroll
    for (int tm = 0; tm < 2; tm++) {
        #pragma unroll
        for (int half = 0; half < 2; half++) {
            const int mloc = m0 + tm * 16 + g + half * 8;
            const size_t row = (size_t)(rowBase + mloc) * Yn;
            #pragma unroll
            for (int tn = 0; tn < 8; tn++) {
                const int n = n0 + tn * 8 + t * 2;
                float v0 = c[tm][tn][half * 2 + 0] + __ldg(bias + n);
                float v1 = c[tm][tn][half * 2 + 1] + __ldg(bias + n + 1);
                if (sel < 2) {
                    __nv_bfloat16* dh = (sel == 0) ? g_Qh : g_Kh;
                    __nv_bfloat16* dl = (sel == 0) ? g_Ql : g_Kl;
                    ushort h0, h1, l0, l1;
                    split1(v0, h0, l0); split1(v1, h1, l1);
                    *(uint*)(dh + row + n) = (uint)h0 | ((uint)h1 << 16);
                    *(uint*)(dl + row + n) = (uint)l0 | ((uint)l1 << 16);
                } else {
                    *(float2*)(g_V + row + n) = make_float2(v0, v1);
                }
            }
        }
    }
}

// ---------------- K2: scores + fused per-tile column sum-exp -------------------
__global__ __launch_bounds__(256, 1)
void scores_mma_kernel() {
    extern __shared__ ushort sh[];
    const int tid = threadIdx.x;
    const int w = tid >> 5, lane = tid & 31, g = lane >> 2, t = lane & 3;
    const int m0 = (w & 3) * 32, n0 = (w >> 2) * 64, mw = w & 3;
    const int kt = blockIdx.x, qt = blockIdx.y, b = blockIdx.z;

    const uint32_t base = smem_u32(sh);
    const uint32_t aoff = a_lane_off(m0, lane), boff = b_lane_off(n0, lane);

    float c[2][8][4];
    #pragma unroll
    for (int i = 0; i < 2; i++)
        #pragma unroll
        for (int j = 0; j < 8; j++)
            #pragma unroll
            for (int r = 0; r < 4; r++) c[i][j][r] = 0.f;

    const size_t qoff = ((size_t)b * Sn + qt * 128) * Yn;
    const size_t koff = ((size_t)b * Sn + kt * 128) * Yn;
    fill_tile_async(base + T_AH * 2, g_Qh + qoff, Yn, tid);
    fill_tile_async(base + T_AL * 2, g_Ql + qoff, Yn, tid);
    fill_tile_async(base + T_BH * 2, g_Kh + koff, Yn, tid);
    fill_tile_async(base + T_BL * 2, g_Kl + koff, Yn, tid);
    CP_COMMIT();
    CP_WAIT(0);
    __syncthreads();
    warp_mma_chunk(c, base + T_AH * 2 + aoff, base + T_AL * 2 + aoff,
                   base + T_BH * 2 + boff, base + T_BL * 2 + boff);

    const float scale = 0.08838834764831845f;  // 1/sqrt(128)
    float* Sp = g_Sc + (size_t)b * Sn * Sn;
    #pragma unroll
    for (int tm = 0; tm < 2; tm++) {
        #pragma unroll
        for (int half = 0; half < 2; half++) {
            const int m = qt * 128 + m0 + tm * 16 + g + half * 8;
            float* srow = Sp + (size_t)m * Sn + kt * 128;
            #pragma unroll
            for (int tn = 0; tn < 8; tn++) {
                const int n = n0 + tn * 8 + t * 2;
                *(float2*)(srow + n) = make_float2(c[tm][tn][half * 2 + 0] * scale,
                                                   c[tm][tn][half * 2 + 1] * scale);
            }
        }
    }

    // fused per-tile column sum of exp(S) over this CTA's 128 q rows (no max).
    __syncthreads();                       // tiles no longer needed; reuse smem
    float* szz = (float*)sh;               // [128][4]
    float vz[16];
    #pragma unroll
    for (int tn = 0; tn < 8; tn++) {
        #pragma unroll
        for (int par = 0; par < 2; par++) {
            float z = __expf(c[0][tn][par] * scale)
                    + __expf(c[0][tn][2 + par] * scale)
                    + __expf(c[1][tn][par] * scale)
                    + __expf(c[1][tn][2 + par] * scale);
            z += __shfl_xor_sync(0xFFFFFFFF, z, 4);
            z += __shfl_xor_sync(0xFFFFFFFF, z, 8);
            z += __shfl_xor_sync(0xFFFFFFFF, z, 16);
            vz[tn * 2 + par] = z;
        }
    }
    if (lane < 4) {
        #pragma unroll
        for (int tn = 0; tn < 8; tn++)
            #pragma unroll
            for (int par = 0; par < 2; par++)
                szz[(n0 + tn * 8 + t * 2 + par) * 4 + mw] = vz[tn * 2 + par];
    }
    __syncthreads();
    if (tid < 128) {
        const int n = tid;
        const float z = szz[n * 4 + 0] + szz[n * 4 + 1] + szz[n * 4 + 2] + szz[n * 4 + 3];
        g_pz[((size_t)(b * 8 + qt)) * Sn + kt * 128 + n] = z;
    }
}

// ---------------- K3: combine per-tile sums -> g_Zr ----------------------------
__global__ void combine_kernel() {
    const int b = blockIdx.y;
    const int k = blockIdx.x * 256 + threadIdx.x;
    float z = 0.f;
    #pragma unroll
    for (int i = 0; i < 8; i++)
        z += g_pz[((size_t)(b * 8 + i)) * Sn + k];
    g_Zr[b * Sn + k] = 1.0f / z;
}

// ---------------- K3b: V^T with 1/Z folded, bf16 hi/lo -------------------------
__global__ __launch_bounds__(256)
void vtrans_kernel() {
    __shared__ ushort shh[64][65], shl[64][65];   // [d][k]
    const int b  = blockIdx.z;
    const int d0 = blockIdx.y * 64;
    const int k0 = blockIdx.x * 64;
    const int tt = threadIdx.x;
    {
        const int k   = tt >> 2;
        const int d16 = (tt & 3) * 16;
        const float zr = __ldg(g_Zr + b * Sn + k0 + k);
        const float* vp = g_V + ((size_t)b * Sn + k0 + k) * Yn + d0 + d16;
        #pragma unroll
        for (int j = 0; j < 4; j++) {
            float4 v = *(const float4*)(vp + j * 4);
            ushort h0, h1, h2, h3, l0, l1, l2, l3;
            split1(v.x * zr, h0, l0); split1(v.y * zr, h1, l1);
            split1(v.z * zr, h2, l2); split1(v.w * zr, h3, l3);
            const int dd = d16 + j * 4;
            shh[dd + 0][k] = h0; shh[dd + 1][k] = h1; shh[dd + 2][k] = h2; shh[dd + 3][k] = h3;
            shl[dd + 0][k] = l0; shl[dd + 1][k] = l1; shl[dd + 2][k] = l2; shl[dd + 3][k] = l3;
        }
    }
    __syncthreads();
    {
        const int d  = tt >> 2;
        const int kq = (tt & 3) * 16;
        __nv_bfloat16* oh = g_Vth + ((size_t)b * Yn + d0 + d) * Sn + k0 + kq;
        __nv_bfloat16* ol = g_Vtl + ((size_t)b * Yn + d0 + d) * Sn + k0 + kq;
        #pragma unroll
        for (int p = 0; p < 2; p++) {
            uint4 u;
            u.x = (uint)shh[d][kq+p*8+0] | ((uint)shh[d][kq+p*8+1] << 16);
            u.y = (uint)shh[d][kq+p*8+2] | ((uint)shh[d][kq+p*8+3] << 16);
            u.z = (uint)shh[d][kq+p*8+4] | ((uint)shh[d][kq+p*8+5] << 16);
            u.w = (uint)shh[d][kq+p*8+6] | ((uint)shh[d][kq+p*8+7] << 16);
            *(uint4*)(oh + p * 8) = u;
            u.x = (uint)shl[d][kq+p*8+0] | ((uint)shl[d][kq+p*8+1] << 16);
            u.y = (uint)shl[d][kq+p*8+2] | ((uint)shl[d][kq+p*8+3] << 16);
            u.z = (uint)shl[d][kq+p*8+4] | ((uint)shl[d][kq+p*8+5] << 16);
            u.w = (uint)shl[d][kq+p*8+6] | ((uint)shl[d][kq+p*8+7] << 16);
            *(uint4*)(ol + p * 8) = u;
        }
    }
}

// ---------------- K4: PV + fused max, cp.async double-buffered B ----------------
__global__ __launch_bounds__(256, 1)
void pv_mma_kernel(float* __restrict__ out) {
    extern __shared__ ushort sh[];
    const int tid = threadIdx.x;
    const int w = tid >> 5, lane = tid & 31, t = lane & 3;
    const int m0 = (w & 3) * 32, n0 = (w >> 2) * 64;
    const int qt = blockIdx.x, b = blockIdx.y;

    const uint32_t base = smem_u32(sh);
    const uint32_t aoff = a_lane_off(m0, lane), boff = b_lane_off(n0, lane);
    const uint32_t aH = base + T_AH * 2 + aoff, aL = base + T_AL * 2 + aoff;

    const float* Sp = g_Sc + (size_t)b * Sn * Sn;
    const __nv_bfloat16* Vh = g_Vth + (size_t)b * Yn * Sn;
    const __nv_bfloat16* Vl = g_Vtl + (size_t)b * Yn * Sn;

    float c[2][8][4];
    #pragma unroll
    for (int i = 0; i < 2; i++)
        #pragma unroll
        for (int j = 0; j < 8; j++)
            #pragma unroll
            for (int r = 0; r < 4; r++) c[i][j][r] = 0.f;

    // prefetch chunk 0 B tiles into stage 0
    fill_tile_async(base + PV_BH(0) * 2, Vh, Sn, tid);
    fill_tile_async(base + PV_BL(0) * 2, Vl, Sn, tid);
    CP_COMMIT();

    for (int ch = 0; ch < 8; ch++) {
        const int kc = ch * 128;
        const int stage = ch & 1;
        // A tile: P = exp(S) hi/lo (no max subtraction), computed on the fly
        #pragma unroll
        for (int it = 0; it < 16; it++) {
            const int idx = it * 256 + tid;
            const int row = idx >> 5;
            const int c4  = (idx & 31) << 2;
            float4 s = *(const float4*)(Sp + (size_t)(qt * 128 + row) * Sn + kc + c4);
            ushort h[4], l[4];
            split1(__expf(s.x), h[0], l[0]);
            split1(__expf(s.y), h[1], l[1]);
            split1(__expf(s.z), h[2], l[2]);
            split1(__expf(s.w), h[3], l[3]);
            const int off = row * TSTR + c4;
            *(uint2*)(sh + T_AH + off) = make_uint2((uint)h[0] | ((uint)h[1] << 16),
                                                    (uint)h[2] | ((uint)h[3] << 16));
            *(uint2*)(sh + T_AL + off) = make_uint2((uint)l[0] | ((uint)l[1] << 16),
                                                    (uint)l[2] | ((uint)l[3] << 16));
        }
        if (ch < 7) {
            fill_tile_async(base + PV_BH(stage ^ 1) * 2, Vh + kc + 128, Sn, tid);
            fill_tile_async(base + PV_BL(stage ^ 1) * 2, Vl + kc + 128, Sn, tid);
            CP_COMMIT();
            CP_WAIT(1);       // current stage's tiles are complete
        } else {
            CP_WAIT(0);
        }
        __syncthreads();
        warp_mma_chunk(c, aH, aL,
                       base + PV_BH(stage) * 2 + boff, base + PV_BL(stage) * 2 + boff);
        __syncthreads();
    }

    // fused max over q: thread-local max, shuffle-reduce over g, one atomic per n.
    #pragma unroll
    for (int tn = 0; tn < 8; tn++) {
        #pragma unroll
        for (int par = 0; par < 2; par++) {
            float v = c[0][tn][par];
            v = fmaxf(v, c[0][tn][2 + par]);
            v = fmaxf(v, c[1][tn][par]);
            v = fmaxf(v, c[1][tn][2 + par]);
            v = fmaxf(v, __shfl_xor_sync(0xFFFFFFFF, v, 4));
            v = fmaxf(v, __shfl_xor_sync(0xFFFFFFFF, v, 8));
            v = fmaxf(v, __shfl_xor_sync(0xFFFFFFFF, v, 16));
            if (lane < 4)
                atomicMaxF(out + b * Yn + n0 + tn * 8 + t * 2 + par, v);
        }
    }
}

// ============================================================================
extern "C" void kernel_launch(void* const* d_in, const int* in_sizes, int n_in,
                              void* d_out, int out_size)
{
    const float* q  = (const float*)d_in[0];
    const float* Wq = (const float*)d_in[1];
    const float* bq = (const float*)d_in[2];
    const float* Wk = (const float*)d_in[3];
    const float* bk = (const float*)d_in[4];
    const float* Wv = (const float*)d_in[5];
    const float* bv = (const float*)d_in[6];
    float* out = (float*)d_out;

    cudaFuncSetAttribute(qkv_mma_kernel,    cudaFuncAttributeMaxDynamicSharedMemorySize, SM_TOTAL);
    cudaFuncSetAttribute(scores_mma_kernel, cudaFuncAttributeMaxDynamicSharedMemorySize, SM_TOTAL);
    cudaFuncSetAttribute(pv_mma_kernel,     cudaFuncAttributeMaxDynamicSharedMemorySize, SM_TOTAL_PV);

    initout_kernel<<<(Bn * Yn) / 256, 256>>>(out);
    split_q_kernel<<<(Bn * Sn * Xn) / 1024, 256>>>(q);
    split_w_kernel<<<(Yn * Xn) / 1024, 256>>>(Wq, 0);
    split_w_kernel<<<(Yn * Xn) / 1024, 256>>>(Wk, 1);
    split_w_kernel<<<(Yn * Xn) / 1024, 256>>>(Wv, 2);
    qkv_mma_kernel<<<dim3(Bn * Sn / 128, 3), 256, SM_TOTAL>>>(bq, bk, bv);
    scores_mma_kernel<<<dim3(Sn / 128, Sn / 128, Bn), 256, SM_TOTAL>>>();
    combine_kernel<<<dim3(Sn / 256, Bn), 256>>>();
    vtrans_kernel<<<dim3(Sn / 64, Yn / 64, Bn), 256>>>();
    pv_mma_kernel<<<dim3(Sn / 128, Bn), 256, SM_TOTAL_PV>>>(out);
}

// round 8
// speedup vs baseline: 2.4976x; 1.0314x over previous
#include <cuda_runtime.h>
#include <cuda_bf16.h>
#include <cstdint>

#define Bn 64
#define Sn 1024
#define Xn 256
#define Yn 128

typedef unsigned int uint;
typedef unsigned short ushort;

// ---------------- scratch (device globals: no cudaMalloc allowed) ----------
__device__ __nv_bfloat16 g_qh[Bn * Sn * Xn];   // q split hi
__device__ __nv_bfloat16 g_ql[Bn * Sn * Xn];   // q split lo
__device__ __nv_bfloat16 g_Wh[3][Yn * Xn];     // Wq/Wk/Wv hi
__device__ __nv_bfloat16 g_Wl[3][Yn * Xn];     // Wq/Wk/Wv lo
__device__ __nv_bfloat16 g_Qh[Bn * Sn * Yn], g_Ql[Bn * Sn * Yn];
__device__ __nv_bfloat16 g_Kh[Bn * Sn * Yn], g_Kl[Bn * Sn * Yn];
__device__ float         g_V [Bn * Sn * Yn];              // V fp32 (pre-norm)
__device__ __nv_bfloat16 g_Ph[(size_t)Bn * Sn * Sn];      // exp(S) hi  128MB
__device__ __nv_bfloat16 g_Pl[(size_t)Bn * Sn * Sn];      // exp(S) lo  128MB
__device__ float         g_pz[Bn * 8 * Sn];               // per-(b,qt,k) tile col sum-exp
__device__ float         g_Zr[Bn * Sn];                   // col 1/sum
__device__ __nv_bfloat16 g_Vth[Bn * Yn * Sn], g_Vtl[Bn * Yn * Sn]; // V^T/Z hi/lo [b][d][k]

// ---------------- shared tile layouts -----------------------------------------
// 144-halves stride (288B): row r starts at 16*r mod 128 -> conflict-free LDSM.
#define TSTR  144
#define T_AH  0
#define T_AL  (128 * TSTR)
#define T_BH  (2 * 128 * TSTR)
#define T_BL  (3 * 128 * TSTR)
#define SM_TOTAL (4 * 128 * TSTR * 2)      // 147456 bytes (qkv / scores)

// pv: k=64 chunks, 8 sub-tiles (A/B hi/lo x 2 stages), stride 72 (144B: 16*r mod 128)
#define TS2   72
#define PVT(i) ((i) * 128 * TS2)           // half offset of sub-tile i
#define SM_TOTAL_PV (8 * 128 * TS2 * 2)    // 147456 bytes

// ---------------- helpers ------------------------------------------------------
__device__ __forceinline__ void split1(float v, ushort& h, ushort& l) {
    __nv_bfloat16 hb = __float2bfloat16(v);
    __nv_bfloat16 lb = __float2bfloat16(v - __bfloat162float(hb));
    h = __bfloat16_as_ushort(hb);
    l = __bfloat16_as_ushort(lb);
}

__device__ __forceinline__ uint32_t smem_u32(const void* p) {
    uint32_t a;
    asm("{ .reg .u64 t; cvta.to.shared.u64 t, %1; cvt.u32.u64 %0, t; }" : "=r"(a) : "l"(p));
    return a;
}

__device__ __forceinline__ void mma16816(float* c, const uint* a, const uint* b) {
    asm volatile("mma.sync.aligned.m16n8k16.row.col.f32.bf16.bf16.f32 "
        "{%0,%1,%2,%3}, {%4,%5,%6,%7}, {%8,%9}, {%0,%1,%2,%3};"
        : "+f"(c[0]), "+f"(c[1]), "+f"(c[2]), "+f"(c[3])
        : "r"(a[0]), "r"(a[1]), "r"(a[2]), "r"(a[3]), "r"(b[0]), "r"(b[1]));
}

#define LDSM4(r0, r1, r2, r3, addr) \
    asm volatile("ldmatrix.sync.aligned.m8n8.x4.shared.b16 {%0,%1,%2,%3}, [%4];" \
        : "=r"(r0), "=r"(r1), "=r"(r2), "=r"(r3) : "r"(addr))

#define CP_ASYNC16(dst, src) \
    asm volatile("cp.async.cg.shared.global [%0], [%1], 16;" :: "r"(dst), "l"(src))
#define CP_COMMIT() asm volatile("cp.async.commit_group;" ::: "memory")
#define CP_WAIT(N)  asm volatile("cp.async.wait_group %0;" :: "n"(N) : "memory")

__device__ __forceinline__ void atomicMaxF(float* a, float v) {
    if (v >= 0.f) atomicMax((int*)a, __float_as_int(v));
    else          atomicMin((uint*)a, (uint)__float_as_int(v));
}

// Async tile fill: 128 rows x 128 bf16, stride TSTR.
__device__ __forceinline__ void fill_tile_async(uint32_t dst, const __nv_bfloat16* src,
                                                int stride, int tid) {
    #pragma unroll
    for (int it = 0; it < 8; it++) {
        int idx  = it * 256 + tid;
        int row  = idx >> 4;
        int col8 = (idx & 15) << 3;
        CP_ASYNC16(dst + (uint32_t)(row * TSTR + col8) * 2,
                   src + (size_t)row * stride + col8);
    }
}

// Async tile fill: 128 rows x 64 bf16, stride TS2.
__device__ __forceinline__ void fill_tile64_async(uint32_t dst, const __nv_bfloat16* src,
                                                  int stride, int tid) {
    #pragma unroll
    for (int it = 0; it < 4; it++) {
        int idx  = it * 256 + tid;
        int row  = idx >> 3;
        int col8 = (idx & 7) << 3;
        CP_ASYNC16(dst + (uint32_t)(row * TS2 + col8) * 2,
                   src + (size_t)row * stride + col8);
    }
}

// Warp compute, 128-k chunk (8 k-steps), 3-pass bf16 split.
__device__ __forceinline__ void warp_mma_chunk(float (&c)[2][8][4],
        uint32_t aH, uint32_t aL, uint32_t bH, uint32_t bL) {
    #pragma unroll
    for (int ks = 0; ks < 8; ks++) {
        const uint32_t ko = ks * 32;
        uint ah[2][4], al[2][4], bh[4][4], bl[4][4];
        #pragma unroll
        for (int tm = 0; tm < 2; tm++) {
            LDSM4(ah[tm][0], ah[tm][1], ah[tm][2], ah[tm][3], aH + tm * (16 * TSTR * 2) + ko);
            LDSM4(al[tm][0], al[tm][1], al[tm][2], al[tm][3], aL + tm * (16 * TSTR * 2) + ko);
        }
        #pragma unroll
        for (int p = 0; p < 4; p++) {
            LDSM4(bh[p][0], bh[p][1], bh[p][2], bh[p][3], bH + p * (16 * TSTR * 2) + ko);
            LDSM4(bl[p][0], bl[p][1], bl[p][2], bl[p][3], bL + p * (16 * TSTR * 2) + ko);
        }
        #pragma unroll
        for (int tm = 0; tm < 2; tm++) {
            #pragma unroll
            for (int tn = 0; tn < 8; tn++) {
                const int p = tn >> 1, s = (tn & 1) * 2;
                mma16816(c[tm][tn], ah[tm], &bh[p][s]);
                mma16816(c[tm][tn], ah[tm], &bl[p][s]);
                mma16816(c[tm][tn], al[tm], &bh[p][s]);
            }
        }
    }
}

// Warp compute, 64-k chunk (4 k-steps), stride TS2.
__device__ __forceinline__ void warp_mma_chunk64(float (&c)[2][8][4],
        uint32_t aH, uint32_t aL, uint32_t bH, uint32_t bL) {
    #pragma unroll
    for (int ks = 0; ks < 4; ks++) {
        const uint32_t ko = ks * 32;
        uint ah[2][4], al[2][4], bh[4][4], bl[4][4];
        #pragma unroll
        for (int tm = 0; tm < 2; tm++) {
            LDSM4(ah[tm][0], ah[tm][1], ah[tm][2], ah[tm][3], aH + tm * (16 * TS2 * 2) + ko);
            LDSM4(al[tm][0], al[tm][1], al[tm][2], al[tm][3], aL + tm * (16 * TS2 * 2) + ko);
        }
        #pragma unroll
        for (int p = 0; p < 4; p++) {
            LDSM4(bh[p][0], bh[p][1], bh[p][2], bh[p][3], bH + p * (16 * TS2 * 2) + ko);
            LDSM4(bl[p][0], bl[p][1], bl[p][2], bl[p][3], bL + p * (16 * TS2 * 2) + ko);
        }
        #pragma unroll
        for (int tm = 0; tm < 2; tm++) {
            #pragma unroll
            for (int tn = 0; tn < 8; tn++) {
                const int p = tn >> 1, s = (tn & 1) * 2;
                mma16816(c[tm][tn], ah[tm], &bh[p][s]);
                mma16816(c[tm][tn], ah[tm], &bl[p][s]);
                mma16816(c[tm][tn], al[tm], &bh[p][s]);
            }
        }
    }
}

__device__ __forceinline__ uint32_t a_lane_off(int m0, int lane, int str) {
    int r = lane & 7, grp = lane >> 3;
    return (uint32_t)(((m0 + (grp & 1) * 8 + r) * str + (grp >> 1) * 8) * 2);
}
__device__ __forceinline__ uint32_t b_lane_off(int n0, int lane, int str) {
    int r = lane & 7, grp = lane >> 3;
    return (uint32_t)(((n0 + (grp >> 1) * 8 + r) * str + (grp & 1) * 8) * 2);
}

// ---------------- K0: fp32 -> bf16 hi/lo split --------------------------------
__global__ void split_q_kernel(const float* __restrict__ src) {
    int i = (blockIdx.x * 256 + threadIdx.x) * 4;
    float4 v = *(const float4*)(src + i);
    ushort h0, h1, h2, h3, l0, l1, l2, l3;
    split1(v.x, h0, l0); split1(v.y, h1, l1); split1(v.z, h2, l2); split1(v.w, h3, l3);
    *(uint2*)(g_qh + i) = make_uint2((uint)h0 | ((uint)h1 << 16), (uint)h2 | ((uint)h3 << 16));
    *(uint2*)(g_ql + i) = make_uint2((uint)l0 | ((uint)l1 << 16), (uint)l2 | ((uint)l3 << 16));
}
__global__ void split_w_kernel(const float* __restrict__ src, int sel) {
    int i = (blockIdx.x * 256 + threadIdx.x) * 4;
    float4 v = *(const float4*)(src + i);
    ushort h0, h1, h2, h3, l0, l1, l2, l3;
    split1(v.x, h0, l0); split1(v.y, h1, l1); split1(v.z, h2, l2); split1(v.w, h3, l3);
    *(uint2*)(g_Wh[sel] + i) = make_uint2((uint)h0 | ((uint)h1 << 16), (uint)h2 | ((uint)h3 << 16));
    *(uint2*)(g_Wl[sel] + i) = make_uint2((uint)l0 | ((uint)l1 << 16), (uint)l2 | ((uint)l3 << 16));
}

// ---------------- init d_out to -inf -------------------------------------------
__global__ void initout_kernel(float* __restrict__ out) {
    out[blockIdx.x * 256 + threadIdx.x] = __int_as_float(0xFF800000);
}

// ---------------- K1: QKV projection ------------------------------------------
__global__ __launch_bounds__(256, 1)
void qkv_mma_kernel(const float* __restrict__ bq, const float* __restrict__ bk,
                    const float* __restrict__ bv) {
    extern __shared__ ushort sh[];
    const int tid = threadIdx.x;
    const int w = tid >> 5, lane = tid & 31, g = lane >> 2, t = lane & 3;
    const int m0 = (w & 3) * 32, n0 = (w >> 2) * 64;
    const int rowBase = blockIdx.x * 128;
    const int sel = blockIdx.y;

    const uint32_t base = smem_u32(sh);
    const uint32_t aoff = a_lane_off(m0, lane, TSTR), boff = b_lane_off(n0, lane, TSTR);
    const uint32_t aH = base + T_AH * 2 + aoff, aL = base + T_AL * 2 + aoff;
    const uint32_t bH = base + T_BH * 2 + boff, bL = base + T_BL * 2 + boff;

    float c[2][8][4];
    #pragma unroll
    for (int i = 0; i < 2; i++)
        #pragma unroll
        for (int j = 0; j < 8; j++)
            #pragma unroll
            for (int r = 0; r < 4; r++) c[i][j][r] = 0.f;

    for (int ch = 0; ch < 2; ch++) {
        const int kc = ch * 128;
        fill_tile_async(base + T_AH * 2, g_qh + (size_t)rowBase * Xn + kc, Xn, tid);
        fill_tile_async(base + T_AL * 2, g_ql + (size_t)rowBase * Xn + kc, Xn, tid);
        fill_tile_async(base + T_BH * 2, g_Wh[sel] + kc, Xn, tid);
        fill_tile_async(base + T_BL * 2, g_Wl[sel] + kc, Xn, tid);
        CP_COMMIT();
        CP_WAIT(0);
        __syncthreads();
        warp_mma_chunk(c, aH, aL, bH, bL);
        __syncthreads();
    }

    const float* bias = (sel == 0) ? bq : (sel == 1) ? bk : bv;
    #pragma unroll
    for (int tm = 0; tm < 2; tm++) {
        #pragma unroll
        for (int half = 0; half < 2; half++) {
            const int mloc = m0 + tm * 16 + g + half * 8;
            const size_t row = (size_t)(rowBase + mloc) * Yn;
            #pragma unroll
            for (int tn = 0; tn < 8; tn++) {
                const int n = n0 + tn * 8 + t * 2;
                float v0 = c[tm][tn][half * 2 + 0] + __ldg(bias + n);
                float v1 = c[tm][tn][half * 2 + 1] + __ldg(bias + n + 1);
                if (sel < 2) {
                    __nv_bfloat16* dh = (sel == 0) ? g_Qh : g_Kh;
                    __nv_bfloat16* dl = (sel == 0) ? g_Ql : g_Kl;
                    ushort h0, h1, l0, l1;
                    split1(v0, h0, l0); split1(v1, h1, l1);
                    *(uint*)(dh + row + n) = (uint)h0 | ((uint)h1 << 16);
                    *(uint*)(dl + row + n) = (uint)l0 | ((uint)l1 << 16);
                } else {
                    *(float2*)(g_V + row + n) = make_float2(v0, v1);
                }
            }
        }
    }
}

// ---------------- K2: scores -> P = exp(S) hi/lo + per-tile column sums --------
__global__ __launch_bounds__(256, 1)
void scores_mma_kernel() {
    extern __shared__ ushort sh[];
    const int tid = threadIdx.x;
    const int w = tid >> 5, lane = tid & 31, g = lane >> 2, t = lane & 3;
    const int m0 = (w & 3) * 32, n0 = (w >> 2) * 64, mw = w & 3;
    const int kt = blockIdx.x, qt = blockIdx.y, b = blockIdx.z;

    const uint32_t base = smem_u32(sh);
    const uint32_t aoff = a_lane_off(m0, lane, TSTR), boff = b_lane_off(n0, lane, TSTR);

    float c[2][8][4];
    #pragma unroll
    for (int i = 0; i < 2; i++)
        #pragma unroll
        for (int j = 0; j < 8; j++)
            #pragma unroll
            for (int r = 0; r < 4; r++) c[i][j][r] = 0.f;

    const size_t qoff = ((size_t)b * Sn + qt * 128) * Yn;
    const size_t koff = ((size_t)b * Sn + kt * 128) * Yn;
    fill_tile_async(base + T_AH * 2, g_Qh + qoff, Yn, tid);
    fill_tile_async(base + T_AL * 2, g_Ql + qoff, Yn, tid);
    fill_tile_async(base + T_BH * 2, g_Kh + koff, Yn, tid);
    fill_tile_async(base + T_BL * 2, g_Kl + koff, Yn, tid);
    CP_COMMIT();
    CP_WAIT(0);
    __syncthreads();
    warp_mma_chunk(c, base + T_AH * 2 + aoff, base + T_AL * 2 + aoff,
                   base + T_BH * 2 + boff, base + T_BL * 2 + boff);

    // c := exp(c * scale) in place
    const float scale = 0.08838834764831845f;  // 1/sqrt(128)
    #pragma unroll
    for (int i = 0; i < 2; i++)
        #pragma unroll
        for (int j = 0; j < 8; j++)
            #pragma unroll
            for (int r = 0; r < 4; r++) c[i][j][r] = __expf(c[i][j][r] * scale);

    // write P hi/lo (bf16)
    __nv_bfloat16* Php = g_Ph + (size_t)b * Sn * Sn;
    __nv_bfloat16* Plp = g_Pl + (size_t)b * Sn * Sn;
    #pragma unroll
    for (int tm = 0; tm < 2; tm++) {
        #pragma unroll
        for (int half = 0; half < 2; half++) {
            const size_t m = (size_t)(qt * 128 + m0 + tm * 16 + g + half * 8);
            #pragma unroll
            for (int tn = 0; tn < 8; tn++) {
                const int n = kt * 128 + n0 + tn * 8 + t * 2;
                ushort h0, h1, l0, l1;
                split1(c[tm][tn][half * 2 + 0], h0, l0);
                split1(c[tm][tn][half * 2 + 1], h1, l1);
                *(uint*)(Php + m * Sn + n) = (uint)h0 | ((uint)h1 << 16);
                *(uint*)(Plp + m * Sn + n) = (uint)l0 | ((uint)l1 << 16);
            }
        }
    }

    // per-tile column sums of exp over this CTA's 128 q rows
    __syncthreads();                       // tiles no longer needed; reuse smem
    float* szz = (float*)sh;               // [128][4]
    float vz[16];
    #pragma unroll
    for (int tn = 0; tn < 8; tn++) {
        #pragma unroll
        for (int par = 0; par < 2; par++) {
            float z = c[0][tn][par] + c[0][tn][2 + par]
                    + c[1][tn][par] + c[1][tn][2 + par];
            z += __shfl_xor_sync(0xFFFFFFFF, z, 4);
            z += __shfl_xor_sync(0xFFFFFFFF, z, 8);
            z += __shfl_xor_sync(0xFFFFFFFF, z, 16);
            vz[tn * 2 + par] = z;
        }
    }
    if (lane < 4) {
        #pragma unroll
        for (int tn = 0; tn < 8; tn++)
            #pragma unroll
            for (int par = 0; par < 2; par++)
                szz[(n0 + tn * 8 + t * 2 + par) * 4 + mw] = vz[tn * 2 + par];
    }
    __syncthreads();
    if (tid < 128) {
        const int n = tid;
        const float z = szz[n * 4 + 0] + szz[n * 4 + 1] + szz[n * 4 + 2] + szz[n * 4 + 3];
        g_pz[((size_t)(b * 8 + qt)) * Sn + kt * 128 + n] = z;
    }
}

// ---------------- K3: combine per-tile sums -> g_Zr ----------------------------
__global__ void combine_kernel() {
    const int b = blockIdx.y;
    const int k = blockIdx.x * 256 + threadIdx.x;
    float z = 0.f;
    #pragma unroll
    for (int i = 0; i < 8; i++)
        z += g_pz[((size_t)(b * 8 + i)) * Sn + k];
    g_Zr[b * Sn + k] = 1.0f / z;
}

// ---------------- K3b: V^T with 1/Z folded, bf16 hi/lo -------------------------
__global__ __launch_bounds__(256)
void vtrans_kernel() {
    __shared__ ushort shh[64][65], shl[64][65];   // [d][k]
    const int b  = blockIdx.z;
    const int d0 = blockIdx.y * 64;
    const int k0 = blockIdx.x * 64;
    const int tt = threadIdx.x;
    {
        const int k   = tt >> 2;
        const int d16 = (tt & 3) * 16;
        const float zr = __ldg(g_Zr + b * Sn + k0 + k);
        const float* vp = g_V + ((size_t)b * Sn + k0 + k) * Yn + d0 + d16;
        #pragma unroll
        for (int j = 0; j < 4; j++) {
            float4 v = *(const float4*)(vp + j * 4);
            ushort h0, h1, h2, h3, l0, l1, l2, l3;
            split1(v.x * zr, h0, l0); split1(v.y * zr, h1, l1);
            split1(v.z * zr, h2, l2); split1(v.w * zr, h3, l3);
            const int dd = d16 + j * 4;
            shh[dd + 0][k] = h0; shh[dd + 1][k] = h1; shh[dd + 2][k] = h2; shh[dd + 3][k] = h3;
            shl[dd + 0][k] = l0; shl[dd + 1][k] = l1; shl[dd + 2][k] = l2; shl[dd + 3][k] = l3;
        }
    }
    __syncthreads();
    {
        const int d  = tt >> 2;
        const int kq = (tt & 3) * 16;
        __nv_bfloat16* oh = g_Vth + ((size_t)b * Yn + d0 + d) * Sn + k0 + kq;
        __nv_bfloat16* ol = g_Vtl + ((size_t)b * Yn + d0 + d) * Sn + k0 + kq;
        #pragma unroll
        for (int p = 0; p < 2; p++) {
            uint4 u;
            u.x = (uint)shh[d][kq+p*8+0] | ((uint)shh[d][kq+p*8+1] << 16);
            u.y = (uint)shh[d][kq+p*8+2] | ((uint)shh[d][kq+p*8+3] << 16);
            u.z = (uint)shh[d][kq+p*8+4] | ((uint)shh[d][kq+p*8+5] << 16);
            u.w = (uint)shh[d][kq+p*8+6] | ((uint)shh[d][kq+p*8+7] << 16);
            *(uint4*)(oh + p * 8) = u;
            u.x = (uint)shl[d][kq+p*8+0] | ((uint)shl[d][kq+p*8+1] << 16);
            u.y = (uint)shl[d][kq+p*8+2] | ((uint)shl[d][kq+p*8+3] << 16);
            u.z = (uint)shl[d][kq+p*8+4] | ((uint)shl[d][kq+p*8+5] << 16);
            u.w = (uint)shl[d][kq+p*8+6] | ((uint)shl[d][kq+p*8+7] << 16);
            *(uint4*)(ol + p * 8) = u;
        }
    }
}

// ---------------- K4: PV + fused max, fully double-buffered k=64 pipeline ------
__global__ __launch_bounds__(256, 1)
void pv_mma_kernel(float* __restrict__ out) {
    extern __shared__ ushort sh[];
    const int tid = threadIdx.x;
    const int w = tid >> 5, lane = tid & 31, t = lane & 3;
    const int m0 = (w & 3) * 32, n0 = (w >> 2) * 64;
    const int qt = blockIdx.x, b = blockIdx.y;

    const uint32_t base = smem_u32(sh);
    const uint32_t aoff = a_lane_off(m0, lane, TS2), boff = b_lane_off(n0, lane, TS2);

    const __nv_bfloat16* Php = g_Ph + (size_t)b * Sn * Sn + (size_t)(qt * 128) * Sn;
    const __nv_bfloat16* Plp = g_Pl + (size_t)b * Sn * Sn + (size_t)(qt * 128) * Sn;
    const __nv_bfloat16* Vh  = g_Vth + (size_t)b * Yn * Sn;
    const __nv_bfloat16* Vl  = g_Vtl + (size_t)b * Yn * Sn;

    float c[2][8][4];
    #pragma unroll
    for (int i = 0; i < 2; i++)
        #pragma unroll
        for (int j = 0; j < 8; j++)
            #pragma unroll
            for (int r = 0; r < 4; r++) c[i][j][r] = 0.f;

    // prefetch chunk 0 into stage 0
    fill_tile64_async(base + PVT(0) * 2, Php, Sn, tid);
    fill_tile64_async(base + PVT(1) * 2, Plp, Sn, tid);
    fill_tile64_async(base + PVT(2) * 2, Vh, Sn, tid);
    fill_tile64_async(base + PVT(3) * 2, Vl, Sn, tid);
    CP_COMMIT();

    for (int ch = 0; ch < 16; ch++) {
        const int stage = ch & 1;
        if (ch < 15) {
            const int kn = (ch + 1) * 64;
            const uint32_t so = PVT(4 * (stage ^ 1)) * 2;
            fill_tile64_async(base + so,                     Php + kn, Sn, tid);
            fill_tile64_async(base + so + PVT(1) * 2,        Plp + kn, Sn, tid);
            fill_tile64_async(base + so + PVT(2) * 2,        Vh + kn, Sn, tid);
            fill_tile64_async(base + so + PVT(3) * 2,        Vl + kn, Sn, tid);
            CP_COMMIT();
            CP_WAIT(1);
        } else {
            CP_WAIT(0);
        }
        __syncthreads();
        const uint32_t so = PVT(4 * stage) * 2;
        warp_mma_chunk64(c, base + so + aoff,
                            base + so + PVT(1) * 2 + aoff,
                            base + so + PVT(2) * 2 + boff,
                            base + so + PVT(3) * 2 + boff);
        __syncthreads();
    }

    // fused max over q: thread-local max, shuffle-reduce over g, one atomic per n.
    #pragma unroll
    for (int tn = 0; tn < 8; tn++) {
        #pragma unroll
        for (int par = 0; par < 2; par++) {
            float v = c[0][tn][par];
            v = fmaxf(v, c[0][tn][2 + par]);
            v = fmaxf(v, c[1][tn][par]);
            v = fmaxf(v, c[1][tn][2 + par]);
            v = fmaxf(v, __shfl_xor_sync(0xFFFFFFFF, v, 4));
            v = fmaxf(v, __shfl_xor_sync(0xFFFFFFFF, v, 8));
            v = fmaxf(v, __shfl_xor_sync(0xFFFFFFFF, v, 16));
            if (lane < 4)
                atomicMaxF(out + b * Yn + n0 + tn * 8 + t * 2 + par, v);
        }
    }
}

// ============================================================================
extern "C" void kernel_launch(void* const* d_in, const int* in_sizes, int n_in,
                              void* d_out, int out_size)
{
    const float* q  = (const float*)d_in[0];
    const float* Wq = (const float*)d_in[1];
    const float* bq = (const float*)d_in[2];
    const float* Wk = (const float*)d_in[3];
    const float* bk = (const float*)d_in[4];
    const float* Wv = (const float*)d_in[5];
    const float* bv = (const float*)d_in[6];
    float* out = (float*)d_out;

    cudaFuncSetAttribute(qkv_mma_kernel,    cudaFuncAttributeMaxDynamicSharedMemorySize, SM_TOTAL);
    cudaFuncSetAttribute(scores_mma_kernel, cudaFuncAttributeMaxDynamicSharedMemorySize, SM_TOTAL);
    cudaFuncSetAttribute(pv_mma_kernel,     cudaFuncAttributeMaxDynamicSharedMemorySize, SM_TOTAL_PV);

    initout_kernel<<<(Bn * Yn) / 256, 256>>>(out);
    split_q_kernel<<<(Bn * Sn * Xn) / 1024, 256>>>(q);
    split_w_kernel<<<(Yn * Xn) / 1024, 256>>>(Wq, 0);
    split_w_kernel<<<(Yn * Xn) / 1024, 256>>>(Wk, 1);
    split_w_kernel<<<(Yn * Xn) / 1024, 256>>>(Wv, 2);
    qkv_mma_kernel<<<dim3(Bn * Sn / 128, 3), 256, SM_TOTAL>>>(bq, bk, bv);
    scores_mma_kernel<<<dim3(Sn / 128, Sn / 128, Bn), 256, SM_TOTAL>>>();
    combine_kernel<<<dim3(Sn / 256, Bn), 256>>>();
    vtrans_kernel<<<dim3(Sn / 64, Yn / 64, Bn), 256>>>();
    pv_mma_kernel<<<dim3(Sn / 128, Bn), 256, SM_TOTAL_PV>>>(out);
}

// round 9
// speedup vs baseline: 2.6901x; 1.0771x over previous
#include <cuda_runtime.h>
#include <cuda_bf16.h>
#include <cstdint>

#define Bn 64
#define Sn 1024
#define Xn 256
#define Yn 128

typedef unsigned int uint;
typedef unsigned short ushort;

// ---------------- scratch (device globals: no cudaMalloc allowed) ----------
__device__ __nv_bfloat16 g_qh[Bn * Sn * Xn];   // q split hi
__device__ __nv_bfloat16 g_ql[Bn * Sn * Xn];   // q split lo
__device__ __nv_bfloat16 g_Wh[3][Yn * Xn];     // Wq/Wk/Wv hi
__device__ __nv_bfloat16 g_Wl[3][Yn * Xn];     // Wq/Wk/Wv lo
__device__ __nv_bfloat16 g_Qh[Bn * Sn * Yn], g_Ql[Bn * Sn * Yn];
__device__ __nv_bfloat16 g_Kh[Bn * Sn * Yn], g_Kl[Bn * Sn * Yn];
__device__ float         g_V [Bn * Sn * Yn];              // V fp32 (pre-norm)
__device__ __nv_bfloat16 g_Ph[(size_t)Bn * Sn * Sn];      // exp(S) hi  128MB
__device__ __nv_bfloat16 g_Pl[(size_t)Bn * Sn * Sn];      // exp(S) lo  128MB
__device__ float         g_pz[Bn * 8 * Sn];               // per-(b,qt,k) tile col sum-exp
__device__ float         g_Zr[Bn * Sn];                   // col 1/sum
__device__ __nv_bfloat16 g_Vth[Bn * Yn * Sn], g_Vtl[Bn * Yn * Sn]; // V^T/Z hi/lo [b][d][k]

// ---------------- shared tile layout: k=64 sub-tiles, stride 72 halves --------
// 72 halves = 144B stride: row r starts at 16*r mod 128 -> conflict-free LDSM.
#define TS2   72
#define PVT(i) ((i) * 128 * TS2)           // half offset of sub-tile i (18432B each)
#define SM_TOTAL_PIPE (8 * 128 * TS2 * 2)  // 147456 bytes, 8 sub-tiles (2 stages x 4)

// ---------------- helpers ------------------------------------------------------
__device__ __forceinline__ void split1(float v, ushort& h, ushort& l) {
    __nv_bfloat16 hb = __float2bfloat16(v);
    __nv_bfloat16 lb = __float2bfloat16(v - __bfloat162float(hb));
    h = __bfloat16_as_ushort(hb);
    l = __bfloat16_as_ushort(lb);
}

__device__ __forceinline__ uint32_t smem_u32(const void* p) {
    uint32_t a;
    asm("{ .reg .u64 t; cvta.to.shared.u64 t, %1; cvt.u32.u64 %0, t; }" : "=r"(a) : "l"(p));
    return a;
}

__device__ __forceinline__ void mma16816(float* c, const uint* a, const uint* b) {
    asm volatile("mma.sync.aligned.m16n8k16.row.col.f32.bf16.bf16.f32 "
        "{%0,%1,%2,%3}, {%4,%5,%6,%7}, {%8,%9}, {%0,%1,%2,%3};"
        : "+f"(c[0]), "+f"(c[1]), "+f"(c[2]), "+f"(c[3])
        : "r"(a[0]), "r"(a[1]), "r"(a[2]), "r"(a[3]), "r"(b[0]), "r"(b[1]));
}

#define LDSM4(r0, r1, r2, r3, addr) \
    asm volatile("ldmatrix.sync.aligned.m8n8.x4.shared.b16 {%0,%1,%2,%3}, [%4];" \
        : "=r"(r0), "=r"(r1), "=r"(r2), "=r"(r3) : "r"(addr))

#define CP_ASYNC16(dst, src) \
    asm volatile("cp.async.cg.shared.global [%0], [%1], 16;" :: "r"(dst), "l"(src))
#define CP_COMMIT() asm volatile("cp.async.commit_group;" ::: "memory")
#define CP_WAIT(N)  asm volatile("cp.async.wait_group %0;" :: "n"(N) : "memory")

__device__ __forceinline__ void atomicMaxF(float* a, float v) {
    if (v >= 0.f) atomicMax((int*)a, __float_as_int(v));
    else          atomicMin((uint*)a, (uint)__float_as_int(v));
}

// Async tile fill: 128 rows x 64 bf16, stride TS2.
__device__ __forceinline__ void fill_tile64_async(uint32_t dst, const __nv_bfloat16* src,
                                                  int stride, int tid) {
    #pragma unroll
    for (int it = 0; it < 4; it++) {
        int idx  = it * 256 + tid;
        int row  = idx >> 3;
        int col8 = (idx & 7) << 3;
        CP_ASYNC16(dst + (uint32_t)(row * TS2 + col8) * 2,
                   src + (size_t)row * stride + col8);
    }
}

// Warp compute, 64-k chunk (4 k-steps), 3-pass bf16 split, stride TS2.
__device__ __forceinline__ void warp_mma_chunk64(float (&c)[2][8][4],
        uint32_t aH, uint32_t aL, uint32_t bH, uint32_t bL) {
    #pragma unroll
    for (int ks = 0; ks < 4; ks++) {
        const uint32_t ko = ks * 32;
        uint ah[2][4], al[2][4], bh[4][4], bl[4][4];
        #pragma unroll
        for (int tm = 0; tm < 2; tm++) {
            LDSM4(ah[tm][0], ah[tm][1], ah[tm][2], ah[tm][3], aH + tm * (16 * TS2 * 2) + ko);
            LDSM4(al[tm][0], al[tm][1], al[tm][2], al[tm][3], aL + tm * (16 * TS2 * 2) + ko);
        }
        #pragma unroll
        for (int p = 0; p < 4; p++) {
            LDSM4(bh[p][0], bh[p][1], bh[p][2], bh[p][3], bH + p * (16 * TS2 * 2) + ko);
            LDSM4(bl[p][0], bl[p][1], bl[p][2], bl[p][3], bL + p * (16 * TS2 * 2) + ko);
        }
        #pragma unroll
        for (int tm = 0; tm < 2; tm++) {
            #pragma unroll
            for (int tn = 0; tn < 8; tn++) {
                const int p = tn >> 1, s = (tn & 1) * 2;
                mma16816(c[tm][tn], ah[tm], &bh[p][s]);
                mma16816(c[tm][tn], ah[tm], &bl[p][s]);
                mma16816(c[tm][tn], al[tm], &bh[p][s]);
            }
        }
    }
}

__device__ __forceinline__ uint32_t a_lane_off(int m0, int lane) {
    int r = lane & 7, grp = lane >> 3;
    return (uint32_t)(((m0 + (grp & 1) * 8 + r) * TS2 + (grp >> 1) * 8) * 2);
}
__device__ __forceinline__ uint32_t b_lane_off(int n0, int lane) {
    int r = lane & 7, grp = lane >> 3;
    return (uint32_t)(((n0 + (grp >> 1) * 8 + r) * TS2 + (grp & 1) * 8) * 2);
}

// Generic double-buffered pipeline over NCH chunks of k=64.
// Sources: a_hi/a_lo rows (stride sa), b_hi/b_lo rows (stride sb), advancing 64/chunk.
template <int NCH>
__device__ __forceinline__ void pipe_mma(float (&c)[2][8][4], uint32_t base,
        uint32_t aoff, uint32_t boff,
        const __nv_bfloat16* ah, const __nv_bfloat16* al, int sa,
        const __nv_bfloat16* bh, const __nv_bfloat16* bl, int sb, int tid) {
    fill_tile64_async(base + PVT(0) * 2, ah, sa, tid);
    fill_tile64_async(base + PVT(1) * 2, al, sa, tid);
    fill_tile64_async(base + PVT(2) * 2, bh, sb, tid);
    fill_tile64_async(base + PVT(3) * 2, bl, sb, tid);
    CP_COMMIT();
    #pragma unroll
    for (int ch = 0; ch < NCH; ch++) {
        const int stage = ch & 1;
        if (ch < NCH - 1) {
            const int kn = (ch + 1) * 64;
            const uint32_t so = PVT(4 * (stage ^ 1)) * 2;
            fill_tile64_async(base + so,              ah + kn, sa, tid);
            fill_tile64_async(base + so + PVT(1) * 2, al + kn, sa, tid);
            fill_tile64_async(base + so + PVT(2) * 2, bh + kn, sb, tid);
            fill_tile64_async(base + so + PVT(3) * 2, bl + kn, sb, tid);
            CP_COMMIT();
            CP_WAIT(1);
        } else {
            CP_WAIT(0);
        }
        __syncthreads();
        const uint32_t so = PVT(4 * stage) * 2;
        warp_mma_chunk64(c, base + so + aoff,
                            base + so + PVT(1) * 2 + aoff,
                            base + so + PVT(2) * 2 + boff,
                            base + so + PVT(3) * 2 + boff);
        __syncthreads();
    }
}

// ---------------- K0: fp32 -> bf16 hi/lo split --------------------------------
__global__ void split_q_kernel(const float* __restrict__ src) {
    int i = (blockIdx.x * 256 + threadIdx.x) * 4;
    float4 v = *(const float4*)(src + i);
    ushort h0, h1, h2, h3, l0, l1, l2, l3;
    split1(v.x, h0, l0); split1(v.y, h1, l1); split1(v.z, h2, l2); split1(v.w, h3, l3);
    *(uint2*)(g_qh + i) = make_uint2((uint)h0 | ((uint)h1 << 16), (uint)h2 | ((uint)h3 << 16));
    *(uint2*)(g_ql + i) = make_uint2((uint)l0 | ((uint)l1 << 16), (uint)l2 | ((uint)l3 << 16));
}
__global__ void split_w_kernel(const float* __restrict__ src, int sel) {
    int i = (blockIdx.x * 256 + threadIdx.x) * 4;
    float4 v = *(const float4*)(src + i);
    ushort h0, h1, h2, h3, l0, l1, l2, l3;
    split1(v.x, h0, l0); split1(v.y, h1, l1); split1(v.z, h2, l2); split1(v.w, h3, l3);
    *(uint2*)(g_Wh[sel] + i) = make_uint2((uint)h0 | ((uint)h1 << 16), (uint)h2 | ((uint)h3 << 16));
    *(uint2*)(g_Wl[sel] + i) = make_uint2((uint)l0 | ((uint)l1 << 16), (uint)l2 | ((uint)l3 << 16));
}

// ---------------- init d_out to -inf -------------------------------------------
__global__ void initout_kernel(float* __restrict__ out) {
    out[blockIdx.x * 256 + threadIdx.x] = __int_as_float(0xFF800000);
}

// ---------------- K1: QKV projection (double-buffered, 4 chunks) ---------------
__global__ __launch_bounds__(256, 1)
void qkv_mma_kernel(const float* __restrict__ bq, const float* __restrict__ bk,
                    const float* __restrict__ bv) {
    extern __shared__ ushort sh[];
    const int tid = threadIdx.x;
    const int w = tid >> 5, lane = tid & 31, g = lane >> 2, t = lane & 3;
    const int m0 = (w & 3) * 32, n0 = (w >> 2) * 64;
    const int rowBase = blockIdx.x * 128;
    const int sel = blockIdx.y;

    const uint32_t base = smem_u32(sh);
    const uint32_t aoff = a_lane_off(m0, lane), boff = b_lane_off(n0, lane);

    float c[2][8][4];
    #pragma unroll
    for (int i = 0; i < 2; i++)
        #pragma unroll
        for (int j = 0; j < 8; j++)
            #pragma unroll
            for (int r = 0; r < 4; r++) c[i][j][r] = 0.f;

    pipe_mma<4>(c, base, aoff, boff,
                g_qh + (size_t)rowBase * Xn, g_ql + (size_t)rowBase * Xn, Xn,
                g_Wh[sel], g_Wl[sel], Xn, tid);

    const float* bias = (sel == 0) ? bq : (sel == 1) ? bk : bv;
    #pragma unroll
    for (int tm = 0; tm < 2; tm++) {
        #pragma unroll
        for (int half = 0; half < 2; half++) {
            const int mloc = m0 + tm * 16 + g + half * 8;
            const size_t row = (size_t)(rowBase + mloc) * Yn;
            #pragma unroll
            for (int tn = 0; tn < 8; tn++) {
                const int n = n0 + tn * 8 + t * 2;
                float v0 = c[tm][tn][half * 2 + 0] + __ldg(bias + n);
                float v1 = c[tm][tn][half * 2 + 1] + __ldg(bias + n + 1);
                if (sel < 2) {
                    __nv_bfloat16* dh = (sel == 0) ? g_Qh : g_Kh;
                    __nv_bfloat16* dl = (sel == 0) ? g_Ql : g_Kl;
                    ushort h0, h1, l0, l1;
                    split1(v0, h0, l0); split1(v1, h1, l1);
                    *(uint*)(dh + row + n) = (uint)h0 | ((uint)h1 << 16);
                    *(uint*)(dl + row + n) = (uint)l0 | ((uint)l1 << 16);
                } else {
                    *(float2*)(g_V + row + n) = make_float2(v0, v1);
                }
            }
        }
    }
}

// ---------------- K2: scores (double-buffered, 2 chunks) -> P hi/lo + sums ----
__global__ __launch_bounds__(256, 1)
void scores_mma_kernel() {
    extern __shared__ ushort sh[];
    const int tid = threadIdx.x;
    const int w = tid >> 5, lane = tid & 31, g = lane >> 2, t = lane & 3;
    const int m0 = (w & 3) * 32, n0 = (w >> 2) * 64, mw = w & 3;
    const int kt = blockIdx.x, qt = blockIdx.y, b = blockIdx.z;

    const uint32_t base = smem_u32(sh);
    const uint32_t aoff = a_lane_off(m0, lane), boff = b_lane_off(n0, lane);

    float c[2][8][4];
    #pragma unroll
    for (int i = 0; i < 2; i++)
        #pragma unroll
        for (int j = 0; j < 8; j++)
            #pragma unroll
            for (int r = 0; r < 4; r++) c[i][j][r] = 0.f;

    const size_t qoff = ((size_t)b * Sn + qt * 128) * Yn;
    const size_t koff = ((size_t)b * Sn + kt * 128) * Yn;
    pipe_mma<2>(c, base, aoff, boff,
                g_Qh + qoff, g_Ql + qoff, Yn,
                g_Kh + koff, g_Kl + koff, Yn, tid);

    // c := exp(c * scale) in place
    const float scale = 0.08838834764831845f;  // 1/sqrt(128)
    #pragma unroll
    for (int i = 0; i < 2; i++)
        #pragma unroll
        for (int j = 0; j < 8; j++)
            #pragma unroll
            for (int r = 0; r < 4; r++) c[i][j][r] = __expf(c[i][j][r] * scale);

    // write P hi/lo (bf16)
    __nv_bfloat16* Php = g_Ph + (size_t)b * Sn * Sn;
    __nv_bfloat16* Plp = g_Pl + (size_t)b * Sn * Sn;
    #pragma unroll
    for (int tm = 0; tm < 2; tm++) {
        #pragma unroll
        for (int half = 0; half < 2; half++) {
            const size_t m = (size_t)(qt * 128 + m0 + tm * 16 + g + half * 8);
            #pragma unroll
            for (int tn = 0; tn < 8; tn++) {
                const int n = kt * 128 + n0 + tn * 8 + t * 2;
                ushort h0, h1, l0, l1;
                split1(c[tm][tn][half * 2 + 0], h0, l0);
                split1(c[tm][tn][half * 2 + 1], h1, l1);
                *(uint*)(Php + m * Sn + n) = (uint)h0 | ((uint)h1 << 16);
                *(uint*)(Plp + m * Sn + n) = (uint)l0 | ((uint)l1 << 16);
            }
        }
    }

    // per-tile column sums of exp over this CTA's 128 q rows
    __syncthreads();                       // tiles no longer needed; reuse smem
    float* szz = (float*)sh;               // [128][4]
    float vz[16];
    #pragma unroll
    for (int tn = 0; tn < 8; tn++) {
        #pragma unroll
        for (int par = 0; par < 2; par++) {
            float z = c[0][tn][par] + c[0][tn][2 + par]
                    + c[1][tn][par] + c[1][tn][2 + par];
            z += __shfl_xor_sync(0xFFFFFFFF, z, 4);
            z += __shfl_xor_sync(0xFFFFFFFF, z, 8);
            z += __shfl_xor_sync(0xFFFFFFFF, z, 16);
            vz[tn * 2 + par] = z;
        }
    }
    if (lane < 4) {
        #pragma unroll
        for (int tn = 0; tn < 8; tn++)
            #pragma unroll
            for (int par = 0; par < 2; par++)
                szz[(n0 + tn * 8 + t * 2 + par) * 4 + mw] = vz[tn * 2 + par];
    }
    __syncthreads();
    if (tid < 128) {
        const int n = tid;
        const float z = szz[n * 4 + 0] + szz[n * 4 + 1] + szz[n * 4 + 2] + szz[n * 4 + 3];
        g_pz[((size_t)(b * 8 + qt)) * Sn + kt * 128 + n] = z;
    }
}

// ---------------- K3: combine per-tile sums -> g_Zr ----------------------------
__global__ void combine_kernel() {
    const int b = blockIdx.y;
    const int k = blockIdx.x * 256 + threadIdx.x;
    float z = 0.f;
    #pragma unroll
    for (int i = 0; i < 8; i++)
        z += g_pz[((size_t)(b * 8 + i)) * Sn + k];
    g_Zr[b * Sn + k] = 1.0f / z;
}

// ---------------- K3b: V^T with 1/Z folded, bf16 hi/lo -------------------------
__global__ __launch_bounds__(256)
void vtrans_kernel() {
    __shared__ ushort shh[64][65], shl[64][65];   // [d][k]
    const int b  = blockIdx.z;
    const int d0 = blockIdx.y * 64;
    const int k0 = blockIdx.x * 64;
    const int tt = threadIdx.x;
    {
        const int k   = tt >> 2;
        const int d16 = (tt & 3) * 16;
        const float zr = __ldg(g_Zr + b * Sn + k0 + k);
        const float* vp = g_V + ((size_t)b * Sn + k0 + k) * Yn + d0 + d16;
        #pragma unroll
        for (int j = 0; j < 4; j++) {
            float4 v = *(const float4*)(vp + j * 4);
            ushort h0, h1, h2, h3, l0, l1, l2, l3;
            split1(v.x * zr, h0, l0); split1(v.y * zr, h1, l1);
            split1(v.z * zr, h2, l2); split1(v.w * zr, h3, l3);
            const int dd = d16 + j * 4;
            shh[dd + 0][k] = h0; shh[dd + 1][k] = h1; shh[dd + 2][k] = h2; shh[dd + 3][k] = h3;
            shl[dd + 0][k] = l0; shl[dd + 1][k] = l1; shl[dd + 2][k] = l2; shl[dd + 3][k] = l3;
        }
    }
    __syncthreads();
    {
        const int d  = tt >> 2;
        const int kq = (tt & 3) * 16;
        __nv_bfloat16* oh = g_Vth + ((size_t)b * Yn + d0 + d) * Sn + k0 + kq;
        __nv_bfloat16* ol = g_Vtl + ((size_t)b * Yn + d0 + d) * Sn + k0 + kq;
        #pragma unroll
        for (int p = 0; p < 2; p++) {
            uint4 u;
            u.x = (uint)shh[d][kq+p*8+0] | ((uint)shh[d][kq+p*8+1] << 16);
            u.y = (uint)shh[d][kq+p*8+2] | ((uint)shh[d][kq+p*8+3] << 16);
            u.z = (uint)shh[d][kq+p*8+4] | ((uint)shh[d][kq+p*8+5] << 16);
            u.w = (uint)shh[d][kq+p*8+6] | ((uint)shh[d][kq+p*8+7] << 16);
            *(uint4*)(oh + p * 8) = u;
            u.x = (uint)shl[d][kq+p*8+0] | ((uint)shl[d][kq+p*8+1] << 16);
            u.y = (uint)shl[d][kq+p*8+2] | ((uint)shl[d][kq+p*8+3] << 16);
            u.z = (uint)shl[d][kq+p*8+4] | ((uint)shl[d][kq+p*8+5] << 16);
            u.w = (uint)shl[d][kq+p*8+6] | ((uint)shl[d][kq+p*8+7] << 16);
            *(uint4*)(ol + p * 8) = u;
        }
    }
}

// ---------------- K4: PV + fused max (double-buffered, 16 chunks) --------------
__global__ __launch_bounds__(256, 1)
void pv_mma_kernel(float* __restrict__ out) {
    extern __shared__ ushort sh[];
    const int tid = threadIdx.x;
    const int w = tid >> 5, lane = tid & 31, t = lane & 3;
    const int m0 = (w & 3) * 32, n0 = (w >> 2) * 64;
    const int qt = blockIdx.x, b = blockIdx.y;

    const uint32_t base = smem_u32(sh);
    const uint32_t aoff = a_lane_off(m0, lane), boff = b_lane_off(n0, lane);

    const __nv_bfloat16* Php = g_Ph + (size_t)b * Sn * Sn + (size_t)(qt * 128) * Sn;
    const __nv_bfloat16* Plp = g_Pl + (size_t)b * Sn * Sn + (size_t)(qt * 128) * Sn;
    const __nv_bfloat16* Vh  = g_Vth + (size_t)b * Yn * Sn;
    const __nv_bfloat16* Vl  = g_Vtl + (size_t)b * Yn * Sn;

    float c[2][8][4];
    #pragma unroll
    for (int i = 0; i < 2; i++)
        #pragma unroll
        for (int j = 0; j < 8; j++)
            #pragma unroll
            for (int r = 0; r < 4; r++) c[i][j][r] = 0.f;

    pipe_mma<16>(c, base, aoff, boff, Php, Plp, Sn, Vh, Vl, Sn, tid);

    // fused max over q: thread-local max, shuffle-reduce over g, one atomic per n.
    #pragma unroll
    for (int tn = 0; tn < 8; tn++) {
        #pragma unroll
        for (int par = 0; par < 2; par++) {
            float v = c[0][tn][par];
            v = fmaxf(v, c[0][tn][2 + par]);
            v = fmaxf(v, c[1][tn][par]);
            v = fmaxf(v, c[1][tn][2 + par]);
            v = fmaxf(v, __shfl_xor_sync(0xFFFFFFFF, v, 4));
            v = fmaxf(v, __shfl_xor_sync(0xFFFFFFFF, v, 8));
            v = fmaxf(v, __shfl_xor_sync(0xFFFFFFFF, v, 16));
            if (lane < 4)
                atomicMaxF(out + b * Yn + n0 + tn * 8 + t * 2 + par, v);
        }
    }
}

// ============================================================================
extern "C" void kernel_launch(void* const* d_in, const int* in_sizes, int n_in,
                              void* d_out, int out_size)
{
    const float* q  = (const float*)d_in[0];
    const float* Wq = (const float*)d_in[1];
    const float* bq = (const float*)d_in[2];
    const float* Wk = (const float*)d_in[3];
    const float* bk = (const float*)d_in[4];
    const float* Wv = (const float*)d_in[5];
    const float* bv = (const float*)d_in[6];
    float* out = (float*)d_out;

    cudaFuncSetAttribute(qkv_mma_kernel,    cudaFuncAttributeMaxDynamicSharedMemorySize, SM_TOTAL_PIPE);
    cudaFuncSetAttribute(scores_mma_kernel, cudaFuncAttributeMaxDynamicSharedMemorySize, SM_TOTAL_PIPE);
    cudaFuncSetAttribute(pv_mma_kernel,     cudaFuncAttributeMaxDynamicSharedMemorySize, SM_TOTAL_PIPE);

    initout_kernel<<<(Bn * Yn) / 256, 256>>>(out);
    split_q_kernel<<<(Bn * Sn * Xn) / 1024, 256>>>(q);
    split_w_kernel<<<(Yn * Xn) / 1024, 256>>>(Wq, 0);
    split_w_kernel<<<(Yn * Xn) / 1024, 256>>>(Wk, 1);
    split_w_kernel<<<(Yn * Xn) / 1024, 256>>>(Wv, 2);
    qkv_mma_kernel<<<dim3(Bn * Sn / 128, 3), 256, SM_TOTAL_PIPE>>>(bq, bk, bv);
    scores_mma_kernel<<<dim3(Sn / 128, Sn / 128, Bn), 256, SM_TOTAL_PIPE>>>();
    combine_kernel<<<dim3(Sn / 256, Bn), 256>>>();
    vtrans_kernel<<<dim3(Sn / 64, Yn / 64, Bn), 256>>>();
    pv_mma_kernel<<<dim3(Sn / 128, Bn), 256, SM_TOTAL_PIPE>>>(out);
}

// round 10
// speedup vs baseline: 4.8634x; 1.8079x over previous
#include <cuda_runtime.h>
#include <cuda_bf16.h>
#include <cuda_fp16.h>
#include <cstdint>

#define Bn 64
#define Sn 1024
#define Xn 256
#define Yn 128

typedef unsigned int uint;
typedef unsigned short ushort;

// ---------------- scratch (device globals: no cudaMalloc allowed) ----------
__device__ __nv_bfloat16 g_qh[Bn * Sn * Xn];   // q split hi (QKV input)
__device__ __nv_bfloat16 g_ql[Bn * Sn * Xn];   // q split lo
__device__ __nv_bfloat16 g_Wh[3][Yn * Xn];     // Wq/Wk/Wv hi
__device__ __nv_bfloat16 g_Wl[3][Yn * Xn];     // Wq/Wk/Wv lo
__device__ ushort        g_Qf[Bn * Sn * Yn];   // Q fp16
__device__ ushort        g_Kf[Bn * Sn * Yn];   // K fp16
__device__ float         g_V [Bn * Sn * Yn];   // V fp32 (pre-norm)
__device__ ushort        g_P [(size_t)Bn * Sn * Sn];  // exp(S) fp16, 128MB
__device__ float         g_pz[Bn * 8 * Sn];    // per-(b,qt,k) tile col sum-exp
__device__ float         g_Zr[Bn * Sn];        // col 1/sum
__device__ ushort        g_Vt[Bn * Yn * Sn];   // V^T/Z fp16 [b][d][k]

// ---------------- shared tile layout: k=64 sub-tiles, stride 72 halves --------
// 72 halves = 144B stride: row r starts at 16*r mod 128 -> conflict-free LDSM.
#define TS2   72
#define PVT(i) ((i) * 128 * TS2)            // half offset of sub-tile i (18432B)
#define SM_QKV  (8 * 128 * TS2 * 2)         // 147456 B (4 sub-tiles x 2 stages)
#define SM_1P   (4 * 128 * TS2 * 2)         // 73728 B  (2 sub-tiles x 2 stages)

// ---------------- helpers ------------------------------------------------------
__device__ __forceinline__ void split1(float v, ushort& h, ushort& l) {
    __nv_bfloat16 hb = __float2bfloat16(v);
    __nv_bfloat16 lb = __float2bfloat16(v - __bfloat162float(hb));
    h = __bfloat16_as_ushort(hb);
    l = __bfloat16_as_ushort(lb);
}
__device__ __forceinline__ ushort f2h(float v) {
    return __half_as_ushort(__float2half_rn(v));
}

__device__ __forceinline__ uint32_t smem_u32(const void* p) {
    uint32_t a;
    asm("{ .reg .u64 t; cvta.to.shared.u64 t, %1; cvt.u32.u64 %0, t; }" : "=r"(a) : "l"(p));
    return a;
}

__device__ __forceinline__ void mma_bf16(float* c, const uint* a, const uint* b) {
    asm volatile("mma.sync.aligned.m16n8k16.row.col.f32.bf16.bf16.f32 "
        "{%0,%1,%2,%3}, {%4,%5,%6,%7}, {%8,%9}, {%0,%1,%2,%3};"
        : "+f"(c[0]), "+f"(c[1]), "+f"(c[2]), "+f"(c[3])
        : "r"(a[0]), "r"(a[1]), "r"(a[2]), "r"(a[3]), "r"(b[0]), "r"(b[1]));
}
__device__ __forceinline__ void mma_f16(float* c, const uint* a, const uint* b) {
    asm volatile("mma.sync.aligned.m16n8k16.row.col.f32.f16.f16.f32 "
        "{%0,%1,%2,%3}, {%4,%5,%6,%7}, {%8,%9}, {%0,%1,%2,%3};"
        : "+f"(c[0]), "+f"(c[1]), "+f"(c[2]), "+f"(c[3])
        : "r"(a[0]), "r"(a[1]), "r"(a[2]), "r"(a[3]), "r"(b[0]), "r"(b[1]));
}

#define LDSM4(r0, r1, r2, r3, addr) \
    asm volatile("ldmatrix.sync.aligned.m8n8.x4.shared.b16 {%0,%1,%2,%3}, [%4];" \
        : "=r"(r0), "=r"(r1), "=r"(r2), "=r"(r3) : "r"(addr))

#define CP_ASYNC16(dst, src) \
    asm volatile("cp.async.cg.shared.global [%0], [%1], 16;" :: "r"(dst), "l"(src))
#define CP_COMMIT() asm volatile("cp.async.commit_group;" ::: "memory")
#define CP_WAIT(N)  asm volatile("cp.async.wait_group %0;" :: "n"(N) : "memory")

__device__ __forceinline__ void atomicMaxF(float* a, float v) {
    if (v >= 0.f) atomicMax((int*)a, __float_as_int(v));
    else          atomicMin((uint*)a, (uint)__float_as_int(v));
}

// Async tile fill: 128 rows x 64 x 16-bit, stride TS2.
__device__ __forceinline__ void fill_tile64_async(uint32_t dst, const ushort* src,
                                                  int stride, int tid) {
    #pragma unroll
    for (int it = 0; it < 4; it++) {
        int idx  = it * 256 + tid;
        int row  = idx >> 3;
        int col8 = (idx & 7) << 3;
        CP_ASYNC16(dst + (uint32_t)(row * TS2 + col8) * 2,
                   src + (size_t)row * stride + col8);
    }
}

__device__ __forceinline__ uint32_t a_lane_off(int m0, int lane) {
    int r = lane & 7, grp = lane >> 3;
    return (uint32_t)(((m0 + (grp & 1) * 8 + r) * TS2 + (grp >> 1) * 8) * 2);
}
__device__ __forceinline__ uint32_t b_lane_off(int n0, int lane) {
    int r = lane & 7, grp = lane >> 3;
    return (uint32_t)(((n0 + (grp >> 1) * 8 + r) * TS2 + (grp & 1) * 8) * 2);
}

// ---- 3-pass bf16 chunk (k=64): hi*hi + hi*lo + lo*hi --------------------------
__device__ __forceinline__ void warp_mma64_3p(float (&c)[2][8][4],
        uint32_t aH, uint32_t aL, uint32_t bH, uint32_t bL) {
    #pragma unroll
    for (int ks = 0; ks < 4; ks++) {
        const uint32_t ko = ks * 32;
        uint ah[2][4], al[2][4], bh[4][4], bl[4][4];
        #pragma unroll
        for (int tm = 0; tm < 2; tm++) {
            LDSM4(ah[tm][0], ah[tm][1], ah[tm][2], ah[tm][3], aH + tm * (16 * TS2 * 2) + ko);
            LDSM4(al[tm][0], al[tm][1], al[tm][2], al[tm][3], aL + tm * (16 * TS2 * 2) + ko);
        }
        #pragma unroll
        for (int p = 0; p < 4; p++) {
            LDSM4(bh[p][0], bh[p][1], bh[p][2], bh[p][3], bH + p * (16 * TS2 * 2) + ko);
            LDSM4(bl[p][0], bl[p][1], bl[p][2], bl[p][3], bL + p * (16 * TS2 * 2) + ko);
        }
        #pragma unroll
        for (int tm = 0; tm < 2; tm++) {
            #pragma unroll
            for (int tn = 0; tn < 8; tn++) {
                const int p = tn >> 1, s = (tn & 1) * 2;
                mma_bf16(c[tm][tn], ah[tm], &bh[p][s]);
                mma_bf16(c[tm][tn], ah[tm], &bl[p][s]);
                mma_bf16(c[tm][tn], al[tm], &bh[p][s]);
            }
        }
    }
}

// ---- single-pass fp16 chunk (k=64) --------------------------------------------
__device__ __forceinline__ void warp_mma64_1p(float (&c)[2][8][4],
        uint32_t aP, uint32_t bP) {
    #pragma unroll
    for (int ks = 0; ks < 4; ks++) {
        const uint32_t ko = ks * 32;
        uint a[2][4], b[4][4];
        #pragma unroll
        for (int tm = 0; tm < 2; tm++)
            LDSM4(a[tm][0], a[tm][1], a[tm][2], a[tm][3], aP + tm * (16 * TS2 * 2) + ko);
        #pragma unroll
        for (int p = 0; p < 4; p++)
            LDSM4(b[p][0], b[p][1], b[p][2], b[p][3], bP + p * (16 * TS2 * 2) + ko);
        #pragma unroll
        for (int tm = 0; tm < 2; tm++) {
            #pragma unroll
            for (int tn = 0; tn < 8; tn++) {
                const int p = tn >> 1, s = (tn & 1) * 2;
                mma_f16(c[tm][tn], a[tm], &b[p][s]);
            }
        }
    }
}

// ---- double-buffered pipelines --------------------------------------------------
template <int NCH>
__device__ __forceinline__ void pipe3_mma(float (&c)[2][8][4], uint32_t base,
        uint32_t aoff, uint32_t boff,
        const ushort* ah, const ushort* al, int sa,
        const ushort* bh, const ushort* bl, int sb, int tid) {
    fill_tile64_async(base + PVT(0) * 2, ah, sa, tid);
    fill_tile64_async(base + PVT(1) * 2, al, sa, tid);
    fill_tile64_async(base + PVT(2) * 2, bh, sb, tid);
    fill_tile64_async(base + PVT(3) * 2, bl, sb, tid);
    CP_COMMIT();
    #pragma unroll
    for (int ch = 0; ch < NCH; ch++) {
        const int stage = ch & 1;
        if (ch < NCH - 1) {
            const int kn = (ch + 1) * 64;
            const uint32_t so = PVT(4 * (stage ^ 1)) * 2;
            fill_tile64_async(base + so,              ah + kn, sa, tid);
            fill_tile64_async(base + so + PVT(1) * 2, al + kn, sa, tid);
            fill_tile64_async(base + so + PVT(2) * 2, bh + kn, sb, tid);
            fill_tile64_async(base + so + PVT(3) * 2, bl + kn, sb, tid);
            CP_COMMIT();
            CP_WAIT(1);
        } else {
            CP_WAIT(0);
        }
        __syncthreads();
        const uint32_t so = PVT(4 * stage) * 2;
        warp_mma64_3p(c, base + so + aoff,
                         base + so + PVT(1) * 2 + aoff,
                         base + so + PVT(2) * 2 + boff,
                         base + so + PVT(3) * 2 + boff);
        __syncthreads();
    }
}

template <int NCH>
__device__ __forceinline__ void pipe1_mma(float (&c)[2][8][4], uint32_t base,
        uint32_t aoff, uint32_t boff,
        const ushort* a, int sa, const ushort* b, int sb, int tid) {
    fill_tile64_async(base + PVT(0) * 2, a, sa, tid);
    fill_tile64_async(base + PVT(1) * 2, b, sb, tid);
    CP_COMMIT();
    #pragma unroll
    for (int ch = 0; ch < NCH; ch++) {
        const int stage = ch & 1;
        if (ch < NCH - 1) {
            const int kn = (ch + 1) * 64;
            const uint32_t so = PVT(2 * (stage ^ 1)) * 2;
            fill_tile64_async(base + so,              a + kn, sa, tid);
            fill_tile64_async(base + so + PVT(1) * 2, b + kn, sb, tid);
            CP_COMMIT();
            CP_WAIT(1);
        } else {
            CP_WAIT(0);
        }
        __syncthreads();
        const uint32_t so = PVT(2 * stage) * 2;
        warp_mma64_1p(c, base + so + aoff, base + so + PVT(1) * 2 + boff);
        __syncthreads();
    }
}

// ---------------- K0: fp32 -> bf16 hi/lo split --------------------------------
__global__ void split_q_kernel(const float* __restrict__ src) {
    int i = (blockIdx.x * 256 + threadIdx.x) * 4;
    float4 v = *(const float4*)(src + i);
    ushort h0, h1, h2, h3, l0, l1, l2, l3;
    split1(v.x, h0, l0); split1(v.y, h1, l1); split1(v.z, h2, l2); split1(v.w, h3, l3);
    *(uint2*)(g_qh + i) = make_uint2((uint)h0 | ((uint)h1 << 16), (uint)h2 | ((uint)h3 << 16));
    *(uint2*)(g_ql + i) = make_uint2((uint)l0 | ((uint)l1 << 16), (uint)l2 | ((uint)l3 << 16));
}
__global__ void split_w_kernel(const float* __restrict__ src, int sel) {
    int i = (blockIdx.x * 256 + threadIdx.x) * 4;
    float4 v = *(const float4*)(src + i);
    ushort h0, h1, h2, h3, l0, l1, l2, l3;
    split1(v.x, h0, l0); split1(v.y, h1, l1); split1(v.z, h2, l2); split1(v.w, h3, l3);
    *(uint2*)(g_Wh[sel] + i) = make_uint2((uint)h0 | ((uint)h1 << 16), (uint)h2 | ((uint)h3 << 16));
    *(uint2*)(g_Wl[sel] + i) = make_uint2((uint)l0 | ((uint)l1 << 16), (uint)l2 | ((uint)l3 << 16));
}

// ---------------- init d_out to -inf -------------------------------------------
__global__ void initout_kernel(float* __restrict__ out) {
    out[blockIdx.x * 256 + threadIdx.x] = __int_as_float(0xFF800000);
}

// ---------------- K1: QKV projection (bf16 3-pass, 4 chunks) -------------------
__global__ __launch_bounds__(256, 1)
void qkv_mma_kernel(const float* __restrict__ bq, const float* __restrict__ bk,
                    const float* __restrict__ bv) {
    extern __shared__ ushort sh[];
    const int tid = threadIdx.x;
    const int w = tid >> 5, lane = tid & 31, g = lane >> 2, t = lane & 3;
    const int m0 = (w & 3) * 32, n0 = (w >> 2) * 64;
    const int rowBase = blockIdx.x * 128;
    const int sel = blockIdx.y;

    const uint32_t base = smem_u32(sh);
    const uint32_t aoff = a_lane_off(m0, lane), boff = b_lane_off(n0, lane);

    float c[2][8][4];
    #pragma unroll
    for (int i = 0; i < 2; i++)
        #pragma unroll
        for (int j = 0; j < 8; j++)
            #pragma unroll
            for (int r = 0; r < 4; r++) c[i][j][r] = 0.f;

    pipe3_mma<4>(c, base, aoff, boff,
                 (const ushort*)(g_qh + (size_t)rowBase * Xn),
                 (const ushort*)(g_ql + (size_t)rowBase * Xn), Xn,
                 (const ushort*)g_Wh[sel], (const ushort*)g_Wl[sel], Xn, tid);

    const float* bias = (sel == 0) ? bq : (sel == 1) ? bk : bv;
    #pragma unroll
    for (int tm = 0; tm < 2; tm++) {
        #pragma unroll
        for (int half = 0; half < 2; half++) {
            const int mloc = m0 + tm * 16 + g + half * 8;
            const size_t row = (size_t)(rowBase + mloc) * Yn;
            #pragma unroll
            for (int tn = 0; tn < 8; tn++) {
                const int n = n0 + tn * 8 + t * 2;
                float v0 = c[tm][tn][half * 2 + 0] + __ldg(bias + n);
                float v1 = c[tm][tn][half * 2 + 1] + __ldg(bias + n + 1);
                if (sel < 2) {
                    ushort* dst = (sel == 0) ? g_Qf : g_Kf;
                    *(uint*)(dst + row + n) = (uint)f2h(v0) | ((uint)f2h(v1) << 16);
                } else {
                    *(float2*)(g_V + row + n) = make_float2(v0, v1);
                }
            }
        }
    }
}

// ---------------- K2: scores (fp16 single-pass) -> P fp16 + sums ---------------
__global__ __launch_bounds__(256, 2)
void scores_mma_kernel() {
    extern __shared__ ushort sh[];
    const int tid = threadIdx.x;
    const int w = tid >> 5, lane = tid & 31, g = lane >> 2, t = lane & 3;
    const int m0 = (w & 3) * 32, n0 = (w >> 2) * 64, mw = w & 3;
    const int kt = blockIdx.x, qt = blockIdx.y, b = blockIdx.z;

    const uint32_t base = smem_u32(sh);
    const uint32_t aoff = a_lane_off(m0, lane), boff = b_lane_off(n0, lane);

    float c[2][8][4];
    #pragma unroll
    for (int i = 0; i < 2; i++)
        #pragma unroll
        for (int j = 0; j < 8; j++)
            #pragma unroll
            for (int r = 0; r < 4; r++) c[i][j][r] = 0.f;

    const size_t qoff = ((size_t)b * Sn + qt * 128) * Yn;
    const size_t koff = ((size_t)b * Sn + kt * 128) * Yn;
    pipe1_mma<2>(c, base, aoff, boff, g_Qf + qoff, Yn, g_Kf + koff, Yn, tid);

    // c := exp(c * scale) in place
    const float scale = 0.08838834764831845f;  // 1/sqrt(128)
    #pragma unroll
    for (int i = 0; i < 2; i++)
        #pragma unroll
        for (int j = 0; j < 8; j++)
            #pragma unroll
            for (int r = 0; r < 4; r++) c[i][j][r] = __expf(c[i][j][r] * scale);

    // write P (fp16)
    ushort* Pp = g_P + (size_t)b * Sn * Sn;
    #pragma unroll
    for (int tm = 0; tm < 2; tm++) {
        #pragma unroll
        for (int half = 0; half < 2; half++) {
            const size_t m = (size_t)(qt * 128 + m0 + tm * 16 + g + half * 8);
            #pragma unroll
            for (int tn = 0; tn < 8; tn++) {
                const int n = kt * 128 + n0 + tn * 8 + t * 2;
                *(uint*)(Pp + m * Sn + n) =
                    (uint)f2h(c[tm][tn][half * 2 + 0]) |
                    ((uint)f2h(c[tm][tn][half * 2 + 1]) << 16);
            }
        }
    }

    // per-tile column sums of exp over this CTA's 128 q rows
    __syncthreads();                       // tiles no longer needed; reuse smem
    float* szz = (float*)sh;               // [128][4]
    float vz[16];
    #pragma unroll
    for (int tn = 0; tn < 8; tn++) {
        #pragma unroll
        for (int par = 0; par < 2; par++) {
            float z = c[0][tn][par] + c[0][tn][2 + par]
                    + c[1][tn][par] + c[1][tn][2 + par];
            z += __shfl_xor_sync(0xFFFFFFFF, z, 4);
            z += __shfl_xor_sync(0xFFFFFFFF, z, 8);
            z += __shfl_xor_sync(0xFFFFFFFF, z, 16);
            vz[tn * 2 + par] = z;
        }
    }
    if (lane < 4) {
        #pragma unroll
        for (int tn = 0; tn < 8; tn++)
            #pragma unroll
            for (int par = 0; par < 2; par++)
                szz[(n0 + tn * 8 + t * 2 + par) * 4 + mw] = vz[tn * 2 + par];
    }
    __syncthreads();
    if (tid < 128) {
        const int n = tid;
        const float z = szz[n * 4 + 0] + szz[n * 4 + 1] + szz[n * 4 + 2] + szz[n * 4 + 3];
        g_pz[((size_t)(b * 8 + qt)) * Sn + kt * 128 + n] = z;
    }
}

// ---------------- K3: combine per-tile sums -> g_Zr ----------------------------
__global__ void combine_kernel() {
    const int b = blockIdx.y;
    const int k = blockIdx.x * 256 + threadIdx.x;
    float z = 0.f;
    #pragma unroll
    for (int i = 0; i < 8; i++)
        z += g_pz[((size_t)(b * 8 + i)) * Sn + k];
    g_Zr[b * Sn + k] = 1.0f / z;
}

// ---------------- K3b: V^T with 1/Z folded, fp16 -------------------------------
__global__ __launch_bounds__(256)
void vtrans_kernel() {
    __shared__ ushort shh[64][65];   // [d][k]
    const int b  = blockIdx.z;
    const int d0 = blockIdx.y * 64;
    const int k0 = blockIdx.x * 64;
    const int tt = threadIdx.x;
    {
        const int k   = tt >> 2;
        const int d16 = (tt & 3) * 16;
        const float zr = __ldg(g_Zr + b * Sn + k0 + k);
        const float* vp = g_V + ((size_t)b * Sn + k0 + k) * Yn + d0 + d16;
        #pragma unroll
        for (int j = 0; j < 4; j++) {
            float4 v = *(const float4*)(vp + j * 4);
            const int dd = d16 + j * 4;
            shh[dd + 0][k] = f2h(v.x * zr);
            shh[dd + 1][k] = f2h(v.y * zr);
            shh[dd + 2][k] = f2h(v.z * zr);
            shh[dd + 3][k] = f2h(v.w * zr);
        }
    }
    __syncthreads();
    {
        const int d  = tt >> 2;
        const int kq = (tt & 3) * 16;
        ushort* o = g_Vt + ((size_t)b * Yn + d0 + d) * Sn + k0 + kq;
        #pragma unroll
        for (int p = 0; p < 2; p++) {
            uint4 u;
            u.x = (uint)shh[d][kq+p*8+0] | ((uint)shh[d][kq+p*8+1] << 16);
            u.y = (uint)shh[d][kq+p*8+2] | ((uint)shh[d][kq+p*8+3] << 16);
            u.z = (uint)shh[d][kq+p*8+4] | ((uint)shh[d][kq+p*8+5] << 16);
            u.w = (uint)shh[d][kq+p*8+6] | ((uint)shh[d][kq+p*8+7] << 16);
            *(uint4*)(o + p * 8) = u;
        }
    }
}

// ---------------- K4: PV (fp16 single-pass) + fused max ------------------------
__global__ __launch_bounds__(256, 2)
void pv_mma_kernel(float* __restrict__ out) {
    extern __shared__ ushort sh[];
    const int tid = threadIdx.x;
    const int w = tid >> 5, lane = tid & 31, t = lane & 3;
    const int m0 = (w & 3) * 32, n0 = (w >> 2) * 64;
    const int qt = blockIdx.x, b = blockIdx.y;

    const uint32_t base = smem_u32(sh);
    const uint32_t aoff = a_lane_off(m0, lane), boff = b_lane_off(n0, lane);

    const ushort* Pp = g_P + (size_t)b * Sn * Sn + (size_t)(qt * 128) * Sn;
    const ushort* Vp = g_Vt + (size_t)b * Yn * Sn;

    float c[2][8][4];
    #pragma unroll
    for (int i = 0; i < 2; i++)
        #pragma unroll
        for (int j = 0; j < 8; j++)
            #pragma unroll
            for (int r = 0; r < 4; r++) c[i][j][r] = 0.f;

    pipe1_mma<16>(c, base, aoff, boff, Pp, Sn, Vp, Sn, tid);

    // fused max over q: thread-local max, shuffle-reduce over g, one atomic per n.
    #pragma unroll
    for (int tn = 0; tn < 8; tn++) {
        #pragma unroll
        for (int par = 0; par < 2; par++) {
            float v = c[0][tn][par];
            v = fmaxf(v, c[0][tn][2 + par]);
            v = fmaxf(v, c[1][tn][par]);
            v = fmaxf(v, c[1][tn][2 + par]);
            v = fmaxf(v, __shfl_xor_sync(0xFFFFFFFF, v, 4));
            v = fmaxf(v, __shfl_xor_sync(0xFFFFFFFF, v, 8));
            v = fmaxf(v, __shfl_xor_sync(0xFFFFFFFF, v, 16));
            if (lane < 4)
                atomicMaxF(out + b * Yn + n0 + tn * 8 + t * 2 + par, v);
        }
    }
}

// ============================================================================
extern "C" void kernel_launch(void* const* d_in, const int* in_sizes, int n_in,
                              void* d_out, int out_size)
{
    const float* q  = (const float*)d_in[0];
    const float* Wq = (const float*)d_in[1];
    const float* bq = (const float*)d_in[2];
    const float* Wk = (const float*)d_in[3];
    const float* bk = (const float*)d_in[4];
    const float* Wv = (const float*)d_in[5];
    const float* bv = (const float*)d_in[6];
    float* out = (float*)d_out;

    cudaFuncSetAttribute(qkv_mma_kernel,    cudaFuncAttributeMaxDynamicSharedMemorySize, SM_QKV);
    cudaFuncSetAttribute(scores_mma_kernel, cudaFuncAttributeMaxDynamicSharedMemorySize, SM_1P);
    cudaFuncSetAttribute(pv_mma_kernel,     cudaFuncAttributeMaxDynamicSharedMemorySize, SM_1P);

    initout_kernel<<<(Bn * Yn) / 256, 256>>>(out);
    split_q_kernel<<<(Bn * Sn * Xn) / 1024, 256>>>(q);
    split_w_kernel<<<(Yn * Xn) / 1024, 256>>>(Wq, 0);
    split_w_kernel<<<(Yn * Xn) / 1024, 256>>>(Wk, 1);
    split_w_kernel<<<(Yn * Xn) / 1024, 256>>>(Wv, 2);
    qkv_mma_kernel<<<dim3(Bn * Sn / 128, 3), 256, SM_QKV>>>(bq, bk, bv);
    scores_mma_kernel<<<dim3(Sn / 128, Sn / 128, Bn), 256, SM_1P>>>();
    combine_kernel<<<dim3(Sn / 256, Bn), 256>>>();
    vtrans_kernel<<<dim3(Sn / 64, Yn / 64, Bn), 256>>>();
    pv_mma_kernel<<<dim3(Sn / 128, Bn), 256, SM_1P>>>(out);
}

// round 11
// speedup vs baseline: 6.3144x; 1.2984x over previous
#include <cuda_runtime.h>
#include <cuda_bf16.h>
#include <cuda_fp16.h>
#include <cstdint>

#define Bn 64
#define Sn 1024
#define Xn 256
#define Yn 128

typedef unsigned int uint;
typedef unsigned short ushort;

// ---------------- scratch (device globals: no cudaMalloc allowed) ----------
__device__ ushort        g_qf[Bn * Sn * Xn];   // q fp16
__device__ ushort        g_Wf[3][Yn * Xn];     // Wq/Wk/Wv fp16
__device__ ushort        g_Qf[Bn * Sn * Yn];   // Q fp16
__device__ ushort        g_Kf[Bn * Sn * Yn];   // K fp16
__device__ float         g_V [Bn * Sn * Yn];   // V fp32 (pre-norm)
__device__ ushort        g_P [(size_t)Bn * Sn * Sn];  // exp(S) fp16, 128MB
__device__ float         g_pz[Bn * 8 * Sn];    // per-(b,qt,k) tile col sum-exp
__device__ float         g_Zr[Bn * Sn];        // col 1/sum
__device__ ushort        g_Vt[Bn * Yn * Sn];   // V^T/Z fp16 [b][d][k]

// ---------------- shared tile layout: k=64 sub-tiles, stride 72 halves --------
// 72 halves = 144B stride: row r starts at 16*r mod 128 -> conflict-free LDSM.
#define TS2   72
#define PVT(i) ((i) * 128 * TS2)            // half offset of sub-tile i (18432B)
#define SM_1P   (4 * 128 * TS2 * 2)         // 73728 B (2 sub-tiles x 2 stages)

// ---------------- helpers ------------------------------------------------------
__device__ __forceinline__ ushort f2h(float v) {
    return __half_as_ushort(__float2half_rn(v));
}

__device__ __forceinline__ uint32_t smem_u32(const void* p) {
    uint32_t a;
    asm("{ .reg .u64 t; cvta.to.shared.u64 t, %1; cvt.u32.u64 %0, t; }" : "=r"(a) : "l"(p));
    return a;
}

__device__ __forceinline__ void mma_f16(float* c, const uint* a, const uint* b) {
    asm volatile("mma.sync.aligned.m16n8k16.row.col.f32.f16.f16.f32 "
        "{%0,%1,%2,%3}, {%4,%5,%6,%7}, {%8,%9}, {%0,%1,%2,%3};"
        : "+f"(c[0]), "+f"(c[1]), "+f"(c[2]), "+f"(c[3])
        : "r"(a[0]), "r"(a[1]), "r"(a[2]), "r"(a[3]), "r"(b[0]), "r"(b[1]));
}

#define LDSM4(r0, r1, r2, r3, addr) \
    asm volatile("ldmatrix.sync.aligned.m8n8.x4.shared.b16 {%0,%1,%2,%3}, [%4];" \
        : "=r"(r0), "=r"(r1), "=r"(r2), "=r"(r3) : "r"(addr))

#define CP_ASYNC16(dst, src) \
    asm volatile("cp.async.cg.shared.global [%0], [%1], 16;" :: "r"(dst), "l"(src))
#define CP_COMMIT() asm volatile("cp.async.commit_group;" ::: "memory")
#define CP_WAIT(N)  asm volatile("cp.async.wait_group %0;" :: "n"(N) : "memory")

__device__ __forceinline__ void atomicMaxF(float* a, float v) {
    if (v >= 0.f) atomicMax((int*)a, __float_as_int(v));
    else          atomicMin((uint*)a, (uint)__float_as_int(v));
}

// Async tile fill: 128 rows x 64 x 16-bit, stride TS2.
__device__ __forceinline__ void fill_tile64_async(uint32_t dst, const ushort* src,
                                                  int stride, int tid) {
    #pragma unroll
    for (int it = 0; it < 4; it++) {
        int idx  = it * 256 + tid;
        int row  = idx >> 3;
        int col8 = (idx & 7) << 3;
        CP_ASYNC16(dst + (uint32_t)(row * TS2 + col8) * 2,
                   src + (size_t)row * stride + col8);
    }
}

__device__ __forceinline__ uint32_t a_lane_off(int m0, int lane) {
    int r = lane & 7, grp = lane >> 3;
    return (uint32_t)(((m0 + (grp & 1) * 8 + r) * TS2 + (grp >> 1) * 8) * 2);
}
__device__ __forceinline__ uint32_t b_lane_off(int n0, int lane) {
    int r = lane & 7, grp = lane >> 3;
    return (uint32_t)(((n0 + (grp >> 1) * 8 + r) * TS2 + (grp & 1) * 8) * 2);
}

// ---- single-pass fp16 chunk (k=64) --------------------------------------------
__device__ __forceinline__ void warp_mma64_1p(float (&c)[2][8][4],
        uint32_t aP, uint32_t bP) {
    #pragma unroll
    for (int ks = 0; ks < 4; ks++) {
        const uint32_t ko = ks * 32;
        uint a[2][4], b[4][4];
        #pragma unroll
        for (int tm = 0; tm < 2; tm++)
            LDSM4(a[tm][0], a[tm][1], a[tm][2], a[tm][3], aP + tm * (16 * TS2 * 2) + ko);
        #pragma unroll
        for (int p = 0; p < 4; p++)
            LDSM4(b[p][0], b[p][1], b[p][2], b[p][3], bP + p * (16 * TS2 * 2) + ko);
        #pragma unroll
        for (int tm = 0; tm < 2; tm++) {
            #pragma unroll
            for (int tn = 0; tn < 8; tn++) {
                const int p = tn >> 1, s = (tn & 1) * 2;
                mma_f16(c[tm][tn], a[tm], &b[p][s]);
            }
        }
    }
}

// ---- double-buffered single-pass pipeline ---------------------------------------
template <int NCH>
__device__ __forceinline__ void pipe1_mma(float (&c)[2][8][4], uint32_t base,
        uint32_t aoff, uint32_t boff,
        const ushort* a, int sa, const ushort* b, int sb, int tid) {
    fill_tile64_async(base + PVT(0) * 2, a, sa, tid);
    fill_tile64_async(base + PVT(1) * 2, b, sb, tid);
    CP_COMMIT();
    #pragma unroll
    for (int ch = 0; ch < NCH; ch++) {
        const int stage = ch & 1;
        if (ch < NCH - 1) {
            const int kn = (ch + 1) * 64;
            const uint32_t so = PVT(2 * (stage ^ 1)) * 2;
            fill_tile64_async(base + so,              a + kn, sa, tid);
            fill_tile64_async(base + so + PVT(1) * 2, b + kn, sb, tid);
            CP_COMMIT();
            CP_WAIT(1);
        } else {
            CP_WAIT(0);
        }
        __syncthreads();
        const uint32_t so = PVT(2 * stage) * 2;
        warp_mma64_1p(c, base + so + aoff, base + so + PVT(1) * 2 + boff);
        __syncthreads();
    }
}

// ---------------- K0: fp32 -> fp16 ----------------------------------------------
__global__ void tohalf_q_kernel(const float* __restrict__ src) {
    int i = (blockIdx.x * 256 + threadIdx.x) * 4;
    float4 v = *(const float4*)(src + i);
    uint2 u;
    u.x = (uint)f2h(v.x) | ((uint)f2h(v.y) << 16);
    u.y = (uint)f2h(v.z) | ((uint)f2h(v.w) << 16);
    *(uint2*)(g_qf + i) = u;
}
__global__ void tohalf_w_kernel(const float* __restrict__ src, int sel) {
    int i = (blockIdx.x * 256 + threadIdx.x) * 4;
    float4 v = *(const float4*)(src + i);
    uint2 u;
    u.x = (uint)f2h(v.x) | ((uint)f2h(v.y) << 16);
    u.y = (uint)f2h(v.z) | ((uint)f2h(v.w) << 16);
    *(uint2*)(g_Wf[sel] + i) = u;
}

// ---------------- init d_out to -inf -------------------------------------------
__global__ void initout_kernel(float* __restrict__ out) {
    out[blockIdx.x * 256 + threadIdx.x] = __int_as_float(0xFF800000);
}

// ---------------- K1: QKV projection (fp16 single-pass, 4 chunks) --------------
__global__ __launch_bounds__(256, 2)
void qkv_mma_kernel(const float* __restrict__ bq, const float* __restrict__ bk,
                    const float* __restrict__ bv) {
    extern __shared__ ushort sh[];
    const int tid = threadIdx.x;
    const int w = tid >> 5, lane = tid & 31, g = lane >> 2, t = lane & 3;
    const int m0 = (w & 3) * 32, n0 = (w >> 2) * 64;
    const int rowBase = blockIdx.x * 128;
    const int sel = blockIdx.y;

    const uint32_t base = smem_u32(sh);
    const uint32_t aoff = a_lane_off(m0, lane), boff = b_lane_off(n0, lane);

    float c[2][8][4];
    #pragma unroll
    for (int i = 0; i < 2; i++)
        #pragma unroll
        for (int j = 0; j < 8; j++)
            #pragma unroll
            for (int r = 0; r < 4; r++) c[i][j][r] = 0.f;

    pipe1_mma<4>(c, base, aoff, boff,
                 g_qf + (size_t)rowBase * Xn, Xn, g_Wf[sel], Xn, tid);

    const float* bias = (sel == 0) ? bq : (sel == 1) ? bk : bv;
    #pragma unroll
    for (int tm = 0; tm < 2; tm++) {
        #pragma unroll
        for (int half = 0; half < 2; half++) {
            const int mloc = m0 + tm * 16 + g + half * 8;
            const size_t row = (size_t)(rowBase + mloc) * Yn;
            #pragma unroll
            for (int tn = 0; tn < 8; tn++) {
                const int n = n0 + tn * 8 + t * 2;
                float v0 = c[tm][tn][half * 2 + 0] + __ldg(bias + n);
                float v1 = c[tm][tn][half * 2 + 1] + __ldg(bias + n + 1);
                if (sel < 2) {
                    ushort* dst = (sel == 0) ? g_Qf : g_Kf;
                    *(uint*)(dst + row + n) = (uint)f2h(v0) | ((uint)f2h(v1) << 16);
                } else {
                    *(float2*)(g_V + row + n) = make_float2(v0, v1);
                }
            }
        }
    }
}

// ---------------- K2: scores (fp16 single-pass) -> P fp16 + sums ---------------
__global__ __launch_bounds__(256, 2)
void scores_mma_kernel() {
    extern __shared__ ushort sh[];
    const int tid = threadIdx.x;
    const int w = tid >> 5, lane = tid & 31, g = lane >> 2, t = lane & 3;
    const int m0 = (w & 3) * 32, n0 = (w >> 2) * 64, mw = w & 3;
    const int kt = blockIdx.x, qt = blockIdx.y, b = blockIdx.z;

    const uint32_t base = smem_u32(sh);
    const uint32_t aoff = a_lane_off(m0, lane), boff = b_lane_off(n0, lane);

    float c[2][8][4];
    #pragma unroll
    for (int i = 0; i < 2; i++)
        #pragma unroll
        for (int j = 0; j < 8; j++)
            #pragma unroll
            for (int r = 0; r < 4; r++) c[i][j][r] = 0.f;

    const size_t qoff = ((size_t)b * Sn + qt * 128) * Yn;
    const size_t koff = ((size_t)b * Sn + kt * 128) * Yn;
    pipe1_mma<2>(c, base, aoff, boff, g_Qf + qoff, Yn, g_Kf + koff, Yn, tid);

    // c := exp(c * scale) in place
    const float scale = 0.08838834764831845f;  // 1/sqrt(128)
    #pragma unroll
    for (int i = 0; i < 2; i++)
        #pragma unroll
        for (int j = 0; j < 8; j++)
            #pragma unroll
            for (int r = 0; r < 4; r++) c[i][j][r] = __expf(c[i][j][r] * scale);

    // write P (fp16)
    ushort* Pp = g_P + (size_t)b * Sn * Sn;
    #pragma unroll
    for (int tm = 0; tm < 2; tm++) {
        #pragma unroll
        for (int half = 0; half < 2; half++) {
            const size_t m = (size_t)(qt * 128 + m0 + tm * 16 + g + half * 8);
            #pragma unroll
            for (int tn = 0; tn < 8; tn++) {
                const int n = kt * 128 + n0 + tn * 8 + t * 2;
                *(uint*)(Pp + m * Sn + n) =
                    (uint)f2h(c[tm][tn][half * 2 + 0]) |
                    ((uint)f2h(c[tm][tn][half * 2 + 1]) << 16);
            }
        }
    }

    // per-tile column sums of exp over this CTA's 128 q rows
    __syncthreads();                       // tiles no longer needed; reuse smem
    float* szz = (float*)sh;               // [128][4]
    float vz[16];
    #pragma unroll
    for (int tn = 0; tn < 8; tn++) {
        #pragma unroll
        for (int par = 0; par < 2; par++) {
            float z = c[0][tn][par] + c[0][tn][2 + par]
                    + c[1][tn][par] + c[1][tn][2 + par];
            z += __shfl_xor_sync(0xFFFFFFFF, z, 4);
            z += __shfl_xor_sync(0xFFFFFFFF, z, 8);
            z += __shfl_xor_sync(0xFFFFFFFF, z, 16);
            vz[tn * 2 + par] = z;
        }
    }
    if (lane < 4) {
        #pragma unroll
        for (int tn = 0; tn < 8; tn++)
            #pragma unroll
            for (int par = 0; par < 2; par++)
                szz[(n0 + tn * 8 + t * 2 + par) * 4 + mw] = vz[tn * 2 + par];
    }
    __syncthreads();
    if (tid < 128) {
        const int n = tid;
        const float z = szz[n * 4 + 0] + szz[n * 4 + 1] + szz[n * 4 + 2] + szz[n * 4 + 3];
        g_pz[((size_t)(b * 8 + qt)) * Sn + kt * 128 + n] = z;
    }
}

// ---------------- K3: combine per-tile sums -> g_Zr ----------------------------
__global__ void combine_kernel() {
    const int b = blockIdx.y;
    const int k = blockIdx.x * 256 + threadIdx.x;
    float z = 0.f;
    #pragma unroll
    for (int i = 0; i < 8; i++)
        z += g_pz[((size_t)(b * 8 + i)) * Sn + k];
    g_Zr[b * Sn + k] = 1.0f / z;
}

// ---------------- K3b: V^T with 1/Z folded, fp16 -------------------------------
__global__ __launch_bounds__(256)
void vtrans_kernel() {
    __shared__ ushort shh[64][65];   // [d][k]
    const int b  = blockIdx.z;
    const int d0 = blockIdx.y * 64;
    const int k0 = blockIdx.x * 64;
    const int tt = threadIdx.x;
    {
        const int k   = tt >> 2;
        const int d16 = (tt & 3) * 16;
        const float zr = __ldg(g_Zr + b * Sn + k0 + k);
        const float* vp = g_V + ((size_t)b * Sn + k0 + k) * Yn + d0 + d16;
        #pragma unroll
        for (int j = 0; j < 4; j++) {
            float4 v = *(const float4*)(vp + j * 4);
            const int dd = d16 + j * 4;
            shh[dd + 0][k] = f2h(v.x * zr);
            shh[dd + 1][k] = f2h(v.y * zr);
            shh[dd + 2][k] = f2h(v.z * zr);
            shh[dd + 3][k] = f2h(v.w * zr);
        }
    }
    __syncthreads();
    {
        const int d  = tt >> 2;
        const int kq = (tt & 3) * 16;
        ushort* o = g_Vt + ((size_t)b * Yn + d0 + d) * Sn + k0 + kq;
        #pragma unroll
        for (int p = 0; p < 2; p++) {
            uint4 u;
            u.x = (uint)shh[d][kq+p*8+0] | ((uint)shh[d][kq+p*8+1] << 16);
            u.y = (uint)shh[d][kq+p*8+2] | ((uint)shh[d][kq+p*8+3] << 16);
            u.z = (uint)shh[d][kq+p*8+4] | ((uint)shh[d][kq+p*8+5] << 16);
            u.w = (uint)shh[d][kq+p*8+6] | ((uint)shh[d][kq+p*8+7] << 16);
            *(uint4*)(o + p * 8) = u;
        }
    }
}

// ---------------- K4: PV (fp16 single-pass) + fused max ------------------------
__global__ __launch_bounds__(256, 2)
void pv_mma_kernel(float* __restrict__ out) {
    extern __shared__ ushort sh[];
    const int tid = threadIdx.x;
    const int w = tid >> 5, lane = tid & 31, t = lane & 3;
    const int m0 = (w & 3) * 32, n0 = (w >> 2) * 64;
    const int qt = blockIdx.x, b = blockIdx.y;

    const uint32_t base = smem_u32(sh);
    const uint32_t aoff = a_lane_off(m0, lane), boff = b_lane_off(n0, lane);

    const ushort* Pp = g_P + (size_t)b * Sn * Sn + (size_t)(qt * 128) * Sn;
    const ushort* Vp = g_Vt + (size_t)b * Yn * Sn;

    float c[2][8][4];
    #pragma unroll
    for (int i = 0; i < 2; i++)
        #pragma unroll
        for (int j = 0; j < 8; j++)
            #pragma unroll
            for (int r = 0; r < 4; r++) c[i][j][r] = 0.f;

    pipe1_mma<16>(c, base, aoff, boff, Pp, Sn, Vp, Sn, tid);

    // fused max over q: thread-local max, shuffle-reduce over g, one atomic per n.
    #pragma unroll
    for (int tn = 0; tn < 8; tn++) {
        #pragma unroll
        for (int par = 0; par < 2; par++) {
            float v = c[0][tn][par];
            v = fmaxf(v, c[0][tn][2 + par]);
            v = fmaxf(v, c[1][tn][par]);
            v = fmaxf(v, c[1][tn][2 + par]);
            v = fmaxf(v, __shfl_xor_sync(0xFFFFFFFF, v, 4));
            v = fmaxf(v, __shfl_xor_sync(0xFFFFFFFF, v, 8));
            v = fmaxf(v, __shfl_xor_sync(0xFFFFFFFF, v, 16));
            if (lane < 4)
                atomicMaxF(out + b * Yn + n0 + tn * 8 + t * 2 + par, v);
        }
    }
}

// ============================================================================
extern "C" void kernel_launch(void* const* d_in, const int* in_sizes, int n_in,
                              void* d_out, int out_size)
{
    const float* q  = (const float*)d_in[0];
    const float* Wq = (const float*)d_in[1];
    const float* bq = (const float*)d_in[2];
    const float* Wk = (const float*)d_in[3];
    const float* bk = (const float*)d_in[4];
    const float* Wv = (const float*)d_in[5];
    const float* bv = (const float*)d_in[6];
    float* out = (float*)d_out;

    cudaFuncSetAttribute(qkv_mma_kernel,    cudaFuncAttributeMaxDynamicSharedMemorySize, SM_1P);
    cudaFuncSetAttribute(scores_mma_kernel, cudaFuncAttributeMaxDynamicSharedMemorySize, SM_1P);
    cudaFuncSetAttribute(pv_mma_kernel,     cudaFuncAttributeMaxDynamicSharedMemorySize, SM_1P);

    initout_kernel<<<(Bn * Yn) / 256, 256>>>(out);
    tohalf_q_kernel<<<(Bn * Sn * Xn) / 1024, 256>>>(q);
    tohalf_w_kernel<<<(Yn * Xn) / 1024, 256>>>(Wq, 0);
    tohalf_w_kernel<<<(Yn * Xn) / 1024, 256>>>(Wk, 1);
    tohalf_w_kernel<<<(Yn * Xn) / 1024, 256>>>(Wv, 2);
    qkv_mma_kernel<<<dim3(Bn * Sn / 128, 3), 256, SM_1P>>>(bq, bk, bv);
    scores_mma_kernel<<<dim3(Sn / 128, Sn / 128, Bn), 256, SM_1P>>>();
    combine_kernel<<<dim3(Sn / 256, Bn), 256>>>();
    vtrans_kernel<<<dim3(Sn / 64, Yn / 64, Bn), 256>>>();
    pv_mma_kernel<<<dim3(Sn / 128, Bn), 256, SM_1P>>>(out);
}

// round 12
// speedup vs baseline: 6.4822x; 1.0266x over previous
#include <cuda_runtime.h>
#include <cuda_bf16.h>
#include <cuda_fp16.h>
#include <cstdint>

#define Bn 64
#define Sn 1024
#define Xn 256
#define Yn 128

typedef unsigned int uint;
typedef unsigned short ushort;

// ---------------- scratch (device globals: no cudaMalloc allowed) ----------
__device__ ushort        g_qf[Bn * Sn * Xn];   // q fp16
__device__ ushort        g_Wf[3][Yn * Xn];     // Wq/Wk/Wv fp16
__device__ ushort        g_Qf[Bn * Sn * Yn];   // Q fp16
__device__ ushort        g_Kf[Bn * Sn * Yn];   // K fp16
__device__ float         g_V [Bn * Sn * Yn];   // V fp32 (pre-norm)
__device__ ushort        g_P [(size_t)Bn * Sn * Sn];  // exp(S) fp16, 128MB
__device__ float         g_pz[Bn * 8 * Sn];    // per-(b,qt,k) tile col sum-exp
__device__ ushort        g_Vt[Bn * Yn * Sn];   // V^T/Z fp16 [b][d][k]

// ---------------- shared tile layout: k=64 sub-tiles, stride 72 halves --------
// 72 halves = 144B stride: row r starts at 16*r mod 128 -> conflict-free LDSM.
#define TS2   72
#define PVT(i) ((i) * 128 * TS2)            // half offset of sub-tile i (18432B)
#define SM_1P   (4 * 128 * TS2 * 2)         // 73728 B (2 sub-tiles x 2 stages)

// ---------------- helpers ------------------------------------------------------
__device__ __forceinline__ ushort f2h(float v) {
    return __half_as_ushort(__float2half_rn(v));
}

__device__ __forceinline__ uint32_t smem_u32(const void* p) {
    uint32_t a;
    asm("{ .reg .u64 t; cvta.to.shared.u64 t, %1; cvt.u32.u64 %0, t; }" : "=r"(a) : "l"(p));
    return a;
}

__device__ __forceinline__ void mma_f16(float* c, const uint* a, const uint* b) {
    asm volatile("mma.sync.aligned.m16n8k16.row.col.f32.f16.f16.f32 "
        "{%0,%1,%2,%3}, {%4,%5,%6,%7}, {%8,%9}, {%0,%1,%2,%3};"
        : "+f"(c[0]), "+f"(c[1]), "+f"(c[2]), "+f"(c[3])
        : "r"(a[0]), "r"(a[1]), "r"(a[2]), "r"(a[3]), "r"(b[0]), "r"(b[1]));
}

#define LDSM4(r0, r1, r2, r3, addr) \
    asm volatile("ldmatrix.sync.aligned.m8n8.x4.shared.b16 {%0,%1,%2,%3}, [%4];" \
        : "=r"(r0), "=r"(r1), "=r"(r2), "=r"(r3) : "r"(addr))

#define CP_ASYNC16(dst, src) \
    asm volatile("cp.async.cg.shared.global [%0], [%1], 16;" :: "r"(dst), "l"(src))
#define CP_COMMIT() asm volatile("cp.async.commit_group;" ::: "memory")
#define CP_WAIT(N)  asm volatile("cp.async.wait_group %0;" :: "n"(N) : "memory")

__device__ __forceinline__ void atomicMaxF(float* a, float v) {
    if (v >= 0.f) atomicMax((int*)a, __float_as_int(v));
    else          atomicMin((uint*)a, (uint)__float_as_int(v));
}

// Async tile fill: 128 rows x 64 x 16-bit, stride TS2.
__device__ __forceinline__ void fill_tile64_async(uint32_t dst, const ushort* src,
                                                  int stride, int tid) {
    #pragma unroll
    for (int it = 0; it < 4; it++) {
        int idx  = it * 256 + tid;
        int row  = idx >> 3;
        int col8 = (idx & 7) << 3;
        CP_ASYNC16(dst + (uint32_t)(row * TS2 + col8) * 2,
                   src + (size_t)row * stride + col8);
    }
}

__device__ __forceinline__ uint32_t a_lane_off(int m0, int lane) {
    int r = lane & 7, grp = lane >> 3;
    return (uint32_t)(((m0 + (grp & 1) * 8 + r) * TS2 + (grp >> 1) * 8) * 2);
}
__device__ __forceinline__ uint32_t b_lane_off(int n0, int lane) {
    int r = lane & 7, grp = lane >> 3;
    return (uint32_t)(((n0 + (grp >> 1) * 8 + r) * TS2 + (grp & 1) * 8) * 2);
}

// ---- single-pass fp16 chunk (k=64) --------------------------------------------
__device__ __forceinline__ void warp_mma64_1p(float (&c)[2][8][4],
        uint32_t aP, uint32_t bP) {
    #pragma unroll
    for (int ks = 0; ks < 4; ks++) {
        const uint32_t ko = ks * 32;
        uint a[2][4], b[4][4];
        #pragma unroll
        for (int tm = 0; tm < 2; tm++)
            LDSM4(a[tm][0], a[tm][1], a[tm][2], a[tm][3], aP + tm * (16 * TS2 * 2) + ko);
        #pragma unroll
        for (int p = 0; p < 4; p++)
            LDSM4(b[p][0], b[p][1], b[p][2], b[p][3], bP + p * (16 * TS2 * 2) + ko);
        #pragma unroll
        for (int tm = 0; tm < 2; tm++) {
            #pragma unroll
            for (int tn = 0; tn < 8; tn++) {
                const int p = tn >> 1, s = (tn & 1) * 2;
                mma_f16(c[tm][tn], a[tm], &b[p][s]);
            }
        }
    }
}

// ---- double-buffered single-pass pipeline ---------------------------------------
template <int NCH>
__device__ __forceinline__ void pipe1_mma(float (&c)[2][8][4], uint32_t base,
        uint32_t aoff, uint32_t boff,
        const ushort* a, int sa, const ushort* b, int sb, int tid) {
    fill_tile64_async(base + PVT(0) * 2, a, sa, tid);
    fill_tile64_async(base + PVT(1) * 2, b, sb, tid);
    CP_COMMIT();
    #pragma unroll
    for (int ch = 0; ch < NCH; ch++) {
        const int stage = ch & 1;
        if (ch < NCH - 1) {
            const int kn = (ch + 1) * 64;
            const uint32_t so = PVT(2 * (stage ^ 1)) * 2;
            fill_tile64_async(base + so,              a + kn, sa, tid);
            fill_tile64_async(base + so + PVT(1) * 2, b + kn, sb, tid);
            CP_COMMIT();
            CP_WAIT(1);
        } else {
            CP_WAIT(0);
        }
        __syncthreads();
        const uint32_t so = PVT(2 * stage) * 2;
        warp_mma64_1p(c, base + so + aoff, base + so + PVT(1) * 2 + boff);
        __syncthreads();
    }
}

// ---------------- K0: fused prep: q->fp16, W->fp16, out->-inf ------------------
// grid: [0,16384) q conversion | [16384,16480) W (3 x 32) | [16480,16512) initout
__global__ void prep_kernel(const float* __restrict__ q,
                            const float* __restrict__ Wq,
                            const float* __restrict__ Wk,
                            const float* __restrict__ Wv,
                            float* __restrict__ out) {
    const int bid = blockIdx.x;
    const int tid = threadIdx.x;
    if (bid < 16384) {
        int i = (bid * 256 + tid) * 4;
        float4 v = *(const float4*)(q + i);
        uint2 u;
        u.x = (uint)f2h(v.x) | ((uint)f2h(v.y) << 16);
        u.y = (uint)f2h(v.z) | ((uint)f2h(v.w) << 16);
        *(uint2*)(g_qf + i) = u;
    } else if (bid < 16480) {
        const int bid2 = bid - 16384;
        const int sel = bid2 >> 5;
        const int blk = bid2 & 31;
        const float* src = (sel == 0) ? Wq : (sel == 1) ? Wk : Wv;
        int i = (blk * 256 + tid) * 4;
        float4 v = *(const float4*)(src + i);
        uint2 u;
        u.x = (uint)f2h(v.x) | ((uint)f2h(v.y) << 16);
        u.y = (uint)f2h(v.z) | ((uint)f2h(v.w) << 16);
        *(uint2*)(g_Wf[sel] + i) = u;
    } else {
        int i = (bid - 16480) * 256 + tid;
        out[i] = __int_as_float(0xFF800000);
    }
}

// ---------------- K1: QKV projection (fp16 single-pass, 4 chunks) --------------
__global__ __launch_bounds__(256, 2)
void qkv_mma_kernel(const float* __restrict__ bq, const float* __restrict__ bk,
                    const float* __restrict__ bv) {
    extern __shared__ ushort sh[];
    const int tid = threadIdx.x;
    const int w = tid >> 5, lane = tid & 31, g = lane >> 2, t = lane & 3;
    const int m0 = (w & 3) * 32, n0 = (w >> 2) * 64;
    const int rowBase = blockIdx.x * 128;
    const int sel = blockIdx.y;

    const uint32_t base = smem_u32(sh);
    const uint32_t aoff = a_lane_off(m0, lane), boff = b_lane_off(n0, lane);

    float c[2][8][4];
    #pragma unroll
    for (int i = 0; i < 2; i++)
        #pragma unroll
        for (int j = 0; j < 8; j++)
            #pragma unroll
            for (int r = 0; r < 4; r++) c[i][j][r] = 0.f;

    pipe1_mma<4>(c, base, aoff, boff,
                 g_qf + (size_t)rowBase * Xn, Xn, g_Wf[sel], Xn, tid);

    const float* bias = (sel == 0) ? bq : (sel == 1) ? bk : bv;
    #pragma unroll
    for (int tm = 0; tm < 2; tm++) {
        #pragma unroll
        for (int half = 0; half < 2; half++) {
            const int mloc = m0 + tm * 16 + g + half * 8;
            const size_t row = (size_t)(rowBase + mloc) * Yn;
            #pragma unroll
            for (int tn = 0; tn < 8; tn++) {
                const int n = n0 + tn * 8 + t * 2;
                float v0 = c[tm][tn][half * 2 + 0] + __ldg(bias + n);
                float v1 = c[tm][tn][half * 2 + 1] + __ldg(bias + n + 1);
                if (sel < 2) {
                    ushort* dst = (sel == 0) ? g_Qf : g_Kf;
                    *(uint*)(dst + row + n) = (uint)f2h(v0) | ((uint)f2h(v1) << 16);
                } else {
                    *(float2*)(g_V + row + n) = make_float2(v0, v1);
                }
            }
        }
    }
}

// ---------------- K2: scores (fp16 single-pass) -> P fp16 + sums ---------------
__global__ __launch_bounds__(256, 2)
void scores_mma_kernel() {
    extern __shared__ ushort sh[];
    const int tid = threadIdx.x;
    const int w = tid >> 5, lane = tid & 31, g = lane >> 2, t = lane & 3;
    const int m0 = (w & 3) * 32, n0 = (w >> 2) * 64, mw = w & 3;
    const int kt = blockIdx.x, qt = blockIdx.y, b = blockIdx.z;

    const uint32_t base = smem_u32(sh);
    const uint32_t aoff = a_lane_off(m0, lane), boff = b_lane_off(n0, lane);

    float c[2][8][4];
    #pragma unroll
    for (int i = 0; i < 2; i++)
        #pragma unroll
        for (int j = 0; j < 8; j++)
            #pragma unroll
            for (int r = 0; r < 4; r++) c[i][j][r] = 0.f;

    const size_t qoff = ((size_t)b * Sn + qt * 128) * Yn;
    const size_t koff = ((size_t)b * Sn + kt * 128) * Yn;
    pipe1_mma<2>(c, base, aoff, boff, g_Qf + qoff, Yn, g_Kf + koff, Yn, tid);

    // c := exp(c * scale) in place
    const float scale = 0.08838834764831845f;  // 1/sqrt(128)
    #pragma unroll
    for (int i = 0; i < 2; i++)
        #pragma unroll
        for (int j = 0; j < 8; j++)
            #pragma unroll
            for (int r = 0; r < 4; r++) c[i][j][r] = __expf(c[i][j][r] * scale);

    // write P (fp16)
    ushort* Pp = g_P + (size_t)b * Sn * Sn;
    #pragma unroll
    for (int tm = 0; tm < 2; tm++) {
        #pragma unroll
        for (int half = 0; half < 2; half++) {
            const size_t m = (size_t)(qt * 128 + m0 + tm * 16 + g + half * 8);
            #pragma unroll
            for (int tn = 0; tn < 8; tn++) {
                const int n = kt * 128 + n0 + tn * 8 + t * 2;
                *(uint*)(Pp + m * Sn + n) =
                    (uint)f2h(c[tm][tn][half * 2 + 0]) |
                    ((uint)f2h(c[tm][tn][half * 2 + 1]) << 16);
            }
        }
    }

    // per-tile column sums of exp over this CTA's 128 q rows
    __syncthreads();                       // tiles no longer needed; reuse smem
    float* szz = (float*)sh;               // [128][4]
    float vz[16];
    #pragma unroll
    for (int tn = 0; tn < 8; tn++) {
        #pragma unroll
        for (int par = 0; par < 2; par++) {
            float z = c[0][tn][par] + c[0][tn][2 + par]
                    + c[1][tn][par] + c[1][tn][2 + par];
            z += __shfl_xor_sync(0xFFFFFFFF, z, 4);
            z += __shfl_xor_sync(0xFFFFFFFF, z, 8);
            z += __shfl_xor_sync(0xFFFFFFFF, z, 16);
            vz[tn * 2 + par] = z;
        }
    }
    if (lane < 4) {
        #pragma unroll
        for (int tn = 0; tn < 8; tn++)
            #pragma unroll
            for (int par = 0; par < 2; par++)
                szz[(n0 + tn * 8 + t * 2 + par) * 4 + mw] = vz[tn * 2 + par];
    }
    __syncthreads();
    if (tid < 128) {
        const int n = tid;
        const float z = szz[n * 4 + 0] + szz[n * 4 + 1] + szz[n * 4 + 2] + szz[n * 4 + 3];
        g_pz[((size_t)(b * 8 + qt)) * Sn + kt * 128 + n] = z;
    }
}

// ---------------- K3: V^T with 1/Z folded (Z combined inline), fp16 ------------
__global__ __launch_bounds__(256)
void vtrans_kernel() {
    __shared__ ushort shh[64][65];   // [d][k]
    __shared__ float  szr[64];       // 1/Z for k0..k0+63
    const int b  = blockIdx.z;
    const int d0 = blockIdx.y * 64;
    const int k0 = blockIdx.x * 64;
    const int tt = threadIdx.x;

    // combine per-tile sums -> 1/Z for the 64 k-rows this block needs
    if (tt < 64) {
        const int k = k0 + tt;
        float z = 0.f;
        #pragma unroll
        for (int i = 0; i < 8; i++)
            z += g_pz[((size_t)(b * 8 + i)) * Sn + k];
        szr[tt] = 1.0f / z;
    }
    __syncthreads();

    {
        const int k   = tt >> 2;
        const int d16 = (tt & 3) * 16;
        const float zr = szr[k];
        const float* vp = g_V + ((size_t)b * Sn + k0 + k) * Yn + d0 + d16;
        #pragma unroll
        for (int j = 0; j < 4; j++) {
            float4 v = *(const float4*)(vp + j * 4);
            const int dd = d16 + j * 4;
            shh[dd + 0][k] = f2h(v.x * zr);
            shh[dd + 1][k] = f2h(v.y * zr);
            shh[dd + 2][k] = f2h(v.z * zr);
            shh[dd + 3][k] = f2h(v.w * zr);
        }
    }
    __syncthreads();
    {
        const int d  = tt >> 2;
        const int kq = (tt & 3) * 16;
        ushort* o = g_Vt + ((size_t)b * Yn + d0 + d) * Sn + k0 + kq;
        #pragma unroll
        for (int p = 0; p < 2; p++) {
            uint4 u;
            u.x = (uint)shh[d][kq+p*8+0] | ((uint)shh[d][kq+p*8+1] << 16);
            u.y = (uint)shh[d][kq+p*8+2] | ((uint)shh[d][kq+p*8+3] << 16);
            u.z = (uint)shh[d][kq+p*8+4] | ((uint)shh[d][kq+p*8+5] << 16);
            u.w = (uint)shh[d][kq+p*8+6] | ((uint)shh[d][kq+p*8+7] << 16);
            *(uint4*)(o + p * 8) = u;
        }
    }
}

// ---------------- K4: PV (fp16 single-pass) + fused max ------------------------
__global__ __launch_bounds__(256, 2)
void pv_mma_kernel(float* __restrict__ out) {
    extern __shared__ ushort sh[];
    const int tid = threadIdx.x;
    const int w = tid >> 5, lane = tid & 31, t = lane & 3;
    const int m0 = (w & 3) * 32, n0 = (w >> 2) * 64;
    const int qt = blockIdx.x, b = blockIdx.y;

    const uint32_t base = smem_u32(sh);
    const uint32_t aoff = a_lane_off(m0, lane), boff = b_lane_off(n0, lane);

    const ushort* Pp = g_P + (size_t)b * Sn * Sn + (size_t)(qt * 128) * Sn;
    const ushort* Vp = g_Vt + (size_t)b * Yn * Sn;

    float c[2][8][4];
    #pragma unroll
    for (int i = 0; i < 2; i++)
        #pragma unroll
        for (int j = 0; j < 8; j++)
            #pragma unroll
            for (int r = 0; r < 4; r++) c[i][j][r] = 0.f;

    pipe1_mma<16>(c, base, aoff, boff, Pp, Sn, Vp, Sn, tid);

    // fused max over q: thread-local max, shuffle-reduce over g, one atomic per n.
    #pragma unroll
    for (int tn = 0; tn < 8; tn++) {
        #pragma unroll
        for (int par = 0; par < 2; par++) {
            float v = c[0][tn][par];
            v = fmaxf(v, c[0][tn][2 + par]);
            v = fmaxf(v, c[1][tn][par]);
            v = fmaxf(v, c[1][tn][2 + par]);
            v = fmaxf(v, __shfl_xor_sync(0xFFFFFFFF, v, 4));
            v = fmaxf(v, __shfl_xor_sync(0xFFFFFFFF, v, 8));
            v = fmaxf(v, __shfl_xor_sync(0xFFFFFFFF, v, 16));
            if (lane < 4)
                atomicMaxF(out + b * Yn + n0 + tn * 8 + t * 2 + par, v);
        }
    }
}

// ============================================================================
extern "C" void kernel_launch(void* const* d_in, const int* in_sizes, int n_in,
                              void* d_out, int out_size)
{
    const float* q  = (const float*)d_in[0];
    const float* Wq = (const float*)d_in[1];
    const float* bq = (const float*)d_in[2];
    const float* Wk = (const float*)d_in[3];
    const float* bk = (const float*)d_in[4];
    const float* Wv = (const float*)d_in[5];
    const float* bv = (const float*)d_in[6];
    float* out = (float*)d_out;

    cudaFuncSetAttribute(qkv_mma_kernel,    cudaFuncAttributeMaxDynamicSharedMemorySize, SM_1P);
    cudaFuncSetAttribute(scores_mma_kernel, cudaFuncAttributeMaxDynamicSharedMemorySize, SM_1P);
    cudaFuncSetAttribute(pv_mma_kernel,     cudaFuncAttributeMaxDynamicSharedMemorySize, SM_1P);

    prep_kernel<<<16512, 256>>>(q, Wq, Wk, Wv, out);
    qkv_mma_kernel<<<dim3(Bn * Sn / 128, 3), 256, SM_1P>>>(bq, bk, bv);
    scores_mma_kernel<<<dim3(Sn / 128, Sn / 128, Bn), 256, SM_1P>>>();
    vtrans_kernel<<<dim3(Sn / 64, Yn / 64, Bn), 256>>>();
    pv_mma_kernel<<<dim3(Sn / 128, Bn), 256, SM_1P>>>(out);
}

// round 13
// speedup vs baseline: 6.7927x; 1.0479x over previous
#include <cuda_runtime.h>
#include <cuda_bf16.h>
#include <cuda_fp16.h>
#include <cstdint>

#define Bn 64
#define Sn 1024
#define Xn 256
#define Yn 128

typedef unsigned int uint;
typedef unsigned short ushort;

// ---------------- scratch (device globals: no cudaMalloc allowed) ----------
__device__ ushort        g_qf[Bn * Sn * Xn];   // q fp16
__device__ ushort        g_Wf[3][Yn * Xn];     // Wq/Wk/Wv fp16
__device__ ushort        g_Qf[Bn * Sn * Yn];   // Q fp16
__device__ ushort        g_Kf[Bn * Sn * Yn];   // K fp16
__device__ ushort        g_Vf[Bn * Sn * Yn];   // V fp16 (pre-norm) [k][d]
__device__ ushort        g_P [(size_t)Bn * Sn * Sn];  // exp(S) fp16, 128MB
__device__ float         g_pz[Bn * 8 * Sn];    // per-(b,qt,k) tile col sum-exp
__device__ ushort        g_Vt[Bn * Yn * Sn];   // V^T/Z fp16 [b][d][k]

// ---------------- shared tile layout: k=64 sub-tiles, stride 72 halves --------
// 72 halves = 144B stride: row r starts at 16*r mod 128 -> conflict-free LDSM.
// 3-stage pipeline: stage s uses A at PVT(2s), B at PVT(2s+1).
#define TS2   72
#define PVT(i) ((i) * 128 * TS2)            // half offset of sub-tile i (18432B)
#define SM_1P   (6 * 128 * TS2 * 2)         // 110592 B (2 sub-tiles x 3 stages)

// ---------------- helpers ------------------------------------------------------
__device__ __forceinline__ ushort f2h(float v) {
    return __half_as_ushort(__float2half_rn(v));
}
__device__ __forceinline__ float h2f(ushort v) {
    return __half2float(__ushort_as_half(v));
}

__device__ __forceinline__ uint32_t smem_u32(const void* p) {
    uint32_t a;
    asm("{ .reg .u64 t; cvta.to.shared.u64 t, %1; cvt.u32.u64 %0, t; }" : "=r"(a) : "l"(p));
    return a;
}

__device__ __forceinline__ void mma_f16(float* c, const uint* a, const uint* b) {
    asm volatile("mma.sync.aligned.m16n8k16.row.col.f32.f16.f16.f32 "
        "{%0,%1,%2,%3}, {%4,%5,%6,%7}, {%8,%9}, {%0,%1,%2,%3};"
        : "+f"(c[0]), "+f"(c[1]), "+f"(c[2]), "+f"(c[3])
        : "r"(a[0]), "r"(a[1]), "r"(a[2]), "r"(a[3]), "r"(b[0]), "r"(b[1]));
}

#define LDSM4(r0, r1, r2, r3, addr) \
    asm volatile("ldmatrix.sync.aligned.m8n8.x4.shared.b16 {%0,%1,%2,%3}, [%4];" \
        : "=r"(r0), "=r"(r1), "=r"(r2), "=r"(r3) : "r"(addr))

#define CP_ASYNC16(dst, src) \
    asm volatile("cp.async.cg.shared.global [%0], [%1], 16;" :: "r"(dst), "l"(src))
#define CP_COMMIT() asm volatile("cp.async.commit_group;" ::: "memory")
#define CP_WAIT(N)  asm volatile("cp.async.wait_group %0;" :: "n"(N) : "memory")

__device__ __forceinline__ void atomicMaxF(float* a, float v) {
    if (v >= 0.f) atomicMax((int*)a, __float_as_int(v));
    else          atomicMin((uint*)a, (uint)__float_as_int(v));
}

// Async tile fill: 128 rows x 64 x 16-bit, stride TS2.
__device__ __forceinline__ void fill_tile64_async(uint32_t dst, const ushort* src,
                                                  int stride, int tid) {
    #pragma unroll
    for (int it = 0; it < 4; it++) {
        int idx  = it * 256 + tid;
        int row  = idx >> 3;
        int col8 = (idx & 7) << 3;
        CP_ASYNC16(dst + (uint32_t)(row * TS2 + col8) * 2,
                   src + (size_t)row * stride + col8);
    }
}

__device__ __forceinline__ uint32_t a_lane_off(int m0, int lane) {
    int r = lane & 7, grp = lane >> 3;
    return (uint32_t)(((m0 + (grp & 1) * 8 + r) * TS2 + (grp >> 1) * 8) * 2);
}
__device__ __forceinline__ uint32_t b_lane_off(int n0, int lane) {
    int r = lane & 7, grp = lane >> 3;
    return (uint32_t)(((n0 + (grp >> 1) * 8 + r) * TS2 + (grp & 1) * 8) * 2);
}

// ---- single-pass fp16 chunk (k=64) --------------------------------------------
__device__ __forceinline__ void warp_mma64_1p(float (&c)[2][8][4],
        uint32_t aP, uint32_t bP) {
    #pragma unroll
    for (int ks = 0; ks < 4; ks++) {
        const uint32_t ko = ks * 32;
        uint a[2][4], b[4][4];
        #pragma unroll
        for (int tm = 0; tm < 2; tm++)
            LDSM4(a[tm][0], a[tm][1], a[tm][2], a[tm][3], aP + tm * (16 * TS2 * 2) + ko);
        #pragma unroll
        for (int p = 0; p < 4; p++)
            LDSM4(b[p][0], b[p][1], b[p][2], b[p][3], bP + p * (16 * TS2 * 2) + ko);
        #pragma unroll
        for (int tm = 0; tm < 2; tm++) {
            #pragma unroll
            for (int tn = 0; tn < 8; tn++) {
                const int p = tn >> 1, s = (tn & 1) * 2;
                mma_f16(c[tm][tn], a[tm], &b[p][s]);
            }
        }
    }
}

// ---- 3-stage pipeline, single sync per iteration --------------------------------
// Prefetch distance = 2 iterations (~600cyc) to cover DRAM latency.
// Fill in iter ch targets stage (ch+2)%3 == (ch-1)%3, safe because the sync at
// the top of iter ch guarantees all warps finished mma(ch-1).
template <int NCH>
__device__ __forceinline__ void pipe1_mma(float (&c)[2][8][4], uint32_t base,
        uint32_t aoff, uint32_t boff,
        const ushort* a, int sa, const ushort* b, int sb, int tid) {
    fill_tile64_async(base + PVT(0) * 2, a, sa, tid);
    fill_tile64_async(base + PVT(1) * 2, b, sb, tid);
    CP_COMMIT();
    if (NCH > 1) {
        fill_tile64_async(base + PVT(2) * 2, a + 64, sa, tid);
        fill_tile64_async(base + PVT(3) * 2, b + 64, sb, tid);
        CP_COMMIT();
    }
    #pragma unroll
    for (int ch = 0; ch < NCH; ch++) {
        const int st = ch % 3;
        if (ch < NCH - 1) { CP_WAIT(1); } else { CP_WAIT(0); }
        __syncthreads();
        if (ch + 2 < NCH) {
            const int sn = (ch + 2) % 3;
            const int kn = (ch + 2) * 64;
            fill_tile64_async(base + PVT(2 * sn) * 2,     a + kn, sa, tid);
            fill_tile64_async(base + PVT(2 * sn + 1) * 2, b + kn, sb, tid);
            CP_COMMIT();
        }
        warp_mma64_1p(c, base + PVT(2 * st) * 2 + aoff,
                         base + PVT(2 * st + 1) * 2 + boff);
    }
}

// ---------------- K0: fused prep: q->fp16, W->fp16, out->-inf ------------------
// grid: [0,16384) q conversion | [16384,16480) W (3 x 32) | [16480,16512) initout
__global__ void prep_kernel(const float* __restrict__ q,
                            const float* __restrict__ Wq,
                            const float* __restrict__ Wk,
                            const float* __restrict__ Wv,
                            float* __restrict__ out) {
    const int bid = blockIdx.x;
    const int tid = threadIdx.x;
    if (bid < 16384) {
        int i = (bid * 256 + tid) * 4;
        float4 v = *(const float4*)(q + i);
        uint2 u;
        u.x = (uint)f2h(v.x) | ((uint)f2h(v.y) << 16);
        u.y = (uint)f2h(v.z) | ((uint)f2h(v.w) << 16);
        *(uint2*)(g_qf + i) = u;
    } else if (bid < 16480) {
        const int bid2 = bid - 16384;
        const int sel = bid2 >> 5;
        const int blk = bid2 & 31;
        const float* src = (sel == 0) ? Wq : (sel == 1) ? Wk : Wv;
        int i = (blk * 256 + tid) * 4;
        float4 v = *(const float4*)(src + i);
        uint2 u;
        u.x = (uint)f2h(v.x) | ((uint)f2h(v.y) << 16);
        u.y = (uint)f2h(v.z) | ((uint)f2h(v.w) << 16);
        *(uint2*)(g_Wf[sel] + i) = u;
    } else {
        int i = (bid - 16480) * 256 + tid;
        out[i] = __int_as_float(0xFF800000);
    }
}

// ---------------- K1: QKV projection (fp16 single-pass, 4 chunks) --------------
__global__ __launch_bounds__(256, 2)
void qkv_mma_kernel(const float* __restrict__ bq, const float* __restrict__ bk,
                    const float* __restrict__ bv) {
    extern __shared__ ushort sh[];
    const int tid = threadIdx.x;
    const int w = tid >> 5, lane = tid & 31, g = lane >> 2, t = lane & 3;
    const int m0 = (w & 3) * 32, n0 = (w >> 2) * 64;
    const int rowBase = blockIdx.x * 128;
    const int sel = blockIdx.y;

    const uint32_t base = smem_u32(sh);
    const uint32_t aoff = a_lane_off(m0, lane), boff = b_lane_off(n0, lane);

    float c[2][8][4];
    #pragma unroll
    for (int i = 0; i < 2; i++)
        #pragma unroll
        for (int j = 0; j < 8; j++)
            #pragma unroll
            for (int r = 0; r < 4; r++) c[i][j][r] = 0.f;

    pipe1_mma<4>(c, base, aoff, boff,
                 g_qf + (size_t)rowBase * Xn, Xn, g_Wf[sel], Xn, tid);

    const float* bias = (sel == 0) ? bq : (sel == 1) ? bk : bv;
    ushort* dst = (sel == 0) ? g_Qf : (sel == 1) ? g_Kf : g_Vf;
    #pragma unroll
    for (int tm = 0; tm < 2; tm++) {
        #pragma unroll
        for (int half = 0; half < 2; half++) {
            const int mloc = m0 + tm * 16 + g + half * 8;
            const size_t row = (size_t)(rowBase + mloc) * Yn;
            #pragma unroll
            for (int tn = 0; tn < 8; tn++) {
                const int n = n0 + tn * 8 + t * 2;
                float v0 = c[tm][tn][half * 2 + 0] + __ldg(bias + n);
                float v1 = c[tm][tn][half * 2 + 1] + __ldg(bias + n + 1);
                *(uint*)(dst + row + n) = (uint)f2h(v0) | ((uint)f2h(v1) << 16);
            }
        }
    }
}

// ---------------- K2: scores (fp16 single-pass) -> P fp16 + sums ---------------
__global__ __launch_bounds__(256, 2)
void scores_mma_kernel() {
    extern __shared__ ushort sh[];
    const int tid = threadIdx.x;
    const int w = tid >> 5, lane = tid & 31, g = lane >> 2, t = lane & 3;
    const int m0 = (w & 3) * 32, n0 = (w >> 2) * 64, mw = w & 3;
    const int kt = blockIdx.x, qt = blockIdx.y, b = blockIdx.z;

    const uint32_t base = smem_u32(sh);
    const uint32_t aoff = a_lane_off(m0, lane), boff = b_lane_off(n0, lane);

    float c[2][8][4];
    #pragma unroll
    for (int i = 0; i < 2; i++)
        #pragma unroll
        for (int j = 0; j < 8; j++)
            #pragma unroll
            for (int r = 0; r < 4; r++) c[i][j][r] = 0.f;

    const size_t qoff = ((size_t)b * Sn + qt * 128) * Yn;
    const size_t koff = ((size_t)b * Sn + kt * 128) * Yn;
    pipe1_mma<2>(c, base, aoff, boff, g_Qf + qoff, Yn, g_Kf + koff, Yn, tid);

    // c := exp(c * scale) in place
    const float scale = 0.08838834764831845f;  // 1/sqrt(128)
    #pragma unroll
    for (int i = 0; i < 2; i++)
        #pragma unroll
        for (int j = 0; j < 8; j++)
            #pragma unroll
            for (int r = 0; r < 4; r++) c[i][j][r] = __expf(c[i][j][r] * scale);

    // write P (fp16)
    ushort* Pp = g_P + (size_t)b * Sn * Sn;
    #pragma unroll
    for (int tm = 0; tm < 2; tm++) {
        #pragma unroll
        for (int half = 0; half < 2; half++) {
            const size_t m = (size_t)(qt * 128 + m0 + tm * 16 + g + half * 8);
            #pragma unroll
            for (int tn = 0; tn < 8; tn++) {
                const int n = kt * 128 + n0 + tn * 8 + t * 2;
                *(uint*)(Pp + m * Sn + n) =
                    (uint)f2h(c[tm][tn][half * 2 + 0]) |
                    ((uint)f2h(c[tm][tn][half * 2 + 1]) << 16);
            }
        }
    }

    // per-tile column sums of exp over this CTA's 128 q rows
    __syncthreads();                       // tiles no longer needed; reuse smem
    float* szz = (float*)sh;               // [128][4]
    float vz[16];
    #pragma unroll
    for (int tn = 0; tn < 8; tn++) {
        #pragma unroll
        for (int par = 0; par < 2; par++) {
            float z = c[0][tn][par] + c[0][tn][2 + par]
                    + c[1][tn][par] + c[1][tn][2 + par];
            z += __shfl_xor_sync(0xFFFFFFFF, z, 4);
            z += __shfl_xor_sync(0xFFFFFFFF, z, 8);
            z += __shfl_xor_sync(0xFFFFFFFF, z, 16);
            vz[tn * 2 + par] = z;
        }
    }
    if (lane < 4) {
        #pragma unroll
        for (int tn = 0; tn < 8; tn++)
            #pragma unroll
            for (int par = 0; par < 2; par++)
                szz[(n0 + tn * 8 + t * 2 + par) * 4 + mw] = vz[tn * 2 + par];
    }
    __syncthreads();
    if (tid < 128) {
        const int n = tid;
        const float z = szz[n * 4 + 0] + szz[n * 4 + 1] + szz[n * 4 + 2] + szz[n * 4 + 3];
        g_pz[((size_t)(b * 8 + qt)) * Sn + kt * 128 + n] = z;
    }
}

// ---------------- K3: V^T with 1/Z folded (Z combined inline), fp16 in/out -----
__global__ __launch_bounds__(256)
void vtrans_kernel() {
    __shared__ ushort shh[64][65];   // [d][k]
    __shared__ float  szr[64];       // 1/Z for k0..k0+63
    const int b  = blockIdx.z;
    const int d0 = blockIdx.y * 64;
    const int k0 = blockIdx.x * 64;
    const int tt = threadIdx.x;

    // combine per-tile sums -> 1/Z for the 64 k-rows this block needs
    if (tt < 64) {
        const int k = k0 + tt;
        float z = 0.f;
        #pragma unroll
        for (int i = 0; i < 8; i++)
            z += g_pz[((size_t)(b * 8 + i)) * Sn + k];
        szr[tt] = 1.0f / z;
    }
    __syncthreads();

    {
        const int k   = tt >> 2;
        const int d16 = (tt & 3) * 16;
        const float zr = szr[k];
        const ushort* vp = g_Vf + ((size_t)b * Sn + k0 + k) * Yn + d0 + d16;
        #pragma unroll
        for (int j = 0; j < 2; j++) {
            uint4 u = *(const uint4*)(vp + j * 8);   // 8 halves
            const int dd = d16 + j * 8;
            shh[dd + 0][k] = f2h(h2f((ushort)(u.x      )) * zr);
            shh[dd + 1][k] = f2h(h2f((ushort)(u.x >> 16)) * zr);
            shh[dd + 2][k] = f2h(h2f((ushort)(u.y      )) * zr);
            shh[dd + 3][k] = f2h(h2f((ushort)(u.y >> 16)) * zr);
            shh[dd + 4][k] = f2h(h2f((ushort)(u.z      )) * zr);
            shh[dd + 5][k] = f2h(h2f((ushort)(u.z >> 16)) * zr);
            shh[dd + 6][k] = f2h(h2f((ushort)(u.w      )) * zr);
            shh[dd + 7][k] = f2h(h2f((ushort)(u.w >> 16)) * zr);
        }
    }
    __syncthreads();
    {
        const int d  = tt >> 2;
        const int kq = (tt & 3) * 16;
        ushort* o = g_Vt + ((size_t)b * Yn + d0 + d) * Sn + k0 + kq;
        #pragma unroll
        for (int p = 0; p < 2; p++) {
            uint4 u;
            u.x = (uint)shh[d][kq+p*8+0] | ((uint)shh[d][kq+p*8+1] << 16);
            u.y = (uint)shh[d][kq+p*8+2] | ((uint)shh[d][kq+p*8+3] << 16);
            u.z = (uint)shh[d][kq+p*8+4] | ((uint)shh[d][kq+p*8+5] << 16);
            u.w = (uint)shh[d][kq+p*8+6] | ((uint)shh[d][kq+p*8+7] << 16);
            *(uint4*)(o + p * 8) = u;
        }
    }
}

// ---------------- K4: PV (fp16 single-pass) + fused max ------------------------
__global__ __launch_bounds__(256, 2)
void pv_mma_kernel(float* __restrict__ out) {
    extern __shared__ ushort sh[];
    const int tid = threadIdx.x;
    const int w = tid >> 5, lane = tid & 31, t = lane & 3;
    const int m0 = (w & 3) * 32, n0 = (w >> 2) * 64;
    const int qt = blockIdx.x, b = blockIdx.y;

    const uint32_t base = smem_u32(sh);
    const uint32_t aoff = a_lane_off(m0, lane), boff = b_lane_off(n0, lane);

    const ushort* Pp = g_P + (size_t)b * Sn * Sn + (size_t)(qt * 128) * Sn;
    const ushort* Vp = g_Vt + (size_t)b * Yn * Sn;

    float c[2][8][4];
    #pragma unroll
    for (int i = 0; i < 2; i++)
        #pragma unroll
        for (int j = 0; j < 8; j++)
            #pragma unroll
            for (int r = 0; r < 4; r++) c[i][j][r] = 0.f;

    pipe1_mma<16>(c, base, aoff, boff, Pp, Sn, Vp, Sn, tid);

    // fused max over q: thread-local max, shuffle-reduce over g, one atomic per n.
    #pragma unroll
    for (int tn = 0; tn < 8; tn++) {
        #pragma unroll
        for (int par = 0; par < 2; par++) {
            float v = c[0][tn][par];
            v = fmaxf(v, c[0][tn][2 + par]);
            v = fmaxf(v, c[1][tn][par]);
            v = fmaxf(v, c[1][tn][2 + par]);
            v = fmaxf(v, __shfl_xor_sync(0xFFFFFFFF, v, 4));
            v = fmaxf(v, __shfl_xor_sync(0xFFFFFFFF, v, 8));
            v = fmaxf(v, __shfl_xor_sync(0xFFFFFFFF, v, 16));
            if (lane < 4)
                atomicMaxF(out + b * Yn + n0 + tn * 8 + t * 2 + par, v);
        }
    }
}

// ============================================================================
extern "C" void kernel_launch(void* const* d_in, const int* in_sizes, int n_in,
                              void* d_out, int out_size)
{
    const float* q  = (const float*)d_in[0];
    const float* Wq = (const float*)d_in[1];
    const float* bq = (const float*)d_in[2];
    const float* Wk = (const float*)d_in[3];
    const float* bk = (const float*)d_in[4];
    const float* Wv = (const float*)d_in[5];
    const float* bv = (const float*)d_in[6];
    float* out = (float*)d_out;

    cudaFuncSetAttribute(qkv_mma_kernel,    cudaFuncAttributeMaxDynamicSharedMemorySize, SM_1P);
    cudaFuncSetAttribute(scores_mma_kernel, cudaFuncAttributeMaxDynamicSharedMemorySize, SM_1P);
    cudaFuncSetAttribute(pv_mma_kernel,     cudaFuncAttributeMaxDynamicSharedMemorySize, SM_1P);

    prep_kernel<<<16512, 256>>>(q, Wq, Wk, Wv, out);
    qkv_mma_kernel<<<dim3(Bn * Sn / 128, 3), 256, SM_1P>>>(bq, bk, bv);
    scores_mma_kernel<<<dim3(Sn / 128, Sn / 128, Bn), 256, SM_1P>>>();
    vtrans_kernel<<<dim3(Sn / 64, Yn / 64, Bn), 256>>>();
    pv_mma_kernel<<<dim3(Sn / 128, Bn), 256, SM_1P>>>(out);
}

// round 14
// speedup vs baseline: 6.8148x; 1.0033x over previous
#include <cuda_runtime.h>
#include <cuda_bf16.h>
#include <cuda_fp16.h>
#include <cstdint>

#define Bn 64
#define Sn 1024
#define Xn 256
#define Yn 128

typedef unsigned int uint;
typedef unsigned short ushort;

// ---------------- scratch (device globals: no cudaMalloc allowed) ----------
__device__ ushort        g_qf[Bn * Sn * Xn];   // q fp16
__device__ ushort        g_Wf[3][Yn * Xn];     // Wq/Wk/Wv fp16
__device__ ushort        g_Qf[Bn * Sn * Yn];   // Q fp16
__device__ ushort        g_Kf[Bn * Sn * Yn];   // K fp16
__device__ ushort        g_Vf[Bn * Sn * Yn];   // V fp16 (pre-norm) [b][k][d]
__device__ ushort        g_P [(size_t)Bn * Sn * Sn];  // exp(S) fp16, 128MB
__device__ float         g_pz[Bn * 8 * Sn];    // per-(b,qt,k) tile col sum-exp
__device__ ushort        g_Vt[Bn * Sn * Yn];   // V/Z fp16 [b][k][d]

// ---------------- shared tile layouts ------------------------------------------
// A-tiles (m x k): 128 rows x 64 halves, stride 72 (144B: rows at 16r mod 128).
#define TS2   72
#define PVT(i) ((i) * 128 * TS2)            // half offset of sub-tile i (18432B)
#define SM_1P   (6 * 128 * TS2 * 2)         // 110592 B (qkv/scores: 2 tiles x 3 stages)

// pv B-tiles ([k][d]): 64 rows x 128 halves, stride 136 (272B: rows at 16r mod 128).
#define TSB   136
#define PV_A(s) ((s) * 18432)               // byte offset, A stage s
#define PV_B(s) (3 * 18432 + (s) * 17408)   // byte offset, B stage s
#define SM_PV   (3 * 18432 + 3 * 17408)     // 107520 B

// ---------------- helpers ------------------------------------------------------
__device__ __forceinline__ ushort f2h(float v) {
    return __half_as_ushort(__float2half_rn(v));
}
__device__ __forceinline__ float h2f(ushort v) {
    return __half2float(__ushort_as_half(v));
}

__device__ __forceinline__ uint32_t smem_u32(const void* p) {
    uint32_t a;
    asm("{ .reg .u64 t; cvta.to.shared.u64 t, %1; cvt.u32.u64 %0, t; }" : "=r"(a) : "l"(p));
    return a;
}

__device__ __forceinline__ void mma_f16(float* c, const uint* a, const uint* b) {
    asm volatile("mma.sync.aligned.m16n8k16.row.col.f32.f16.f16.f32 "
        "{%0,%1,%2,%3}, {%4,%5,%6,%7}, {%8,%9}, {%0,%1,%2,%3};"
        : "+f"(c[0]), "+f"(c[1]), "+f"(c[2]), "+f"(c[3])
        : "r"(a[0]), "r"(a[1]), "r"(a[2]), "r"(a[3]), "r"(b[0]), "r"(b[1]));
}

#define LDSM4(r0, r1, r2, r3, addr) \
    asm volatile("ldmatrix.sync.aligned.m8n8.x4.shared.b16 {%0,%1,%2,%3}, [%4];" \
        : "=r"(r0), "=r"(r1), "=r"(r2), "=r"(r3) : "r"(addr))
#define LDSM4T(r0, r1, r2, r3, addr) \
    asm volatile("ldmatrix.sync.aligned.m8n8.x4.trans.shared.b16 {%0,%1,%2,%3}, [%4];" \
        : "=r"(r0), "=r"(r1), "=r"(r2), "=r"(r3) : "r"(addr))

#define CP_ASYNC16(dst, src) \
    asm volatile("cp.async.cg.shared.global [%0], [%1], 16;" :: "r"(dst), "l"(src))
#define CP_COMMIT() asm volatile("cp.async.commit_group;" ::: "memory")
#define CP_WAIT(N)  asm volatile("cp.async.wait_group %0;" :: "n"(N) : "memory")

__device__ __forceinline__ void atomicMaxF(float* a, float v) {
    if (v >= 0.f) atomicMax((int*)a, __float_as_int(v));
    else          atomicMin((uint*)a, (uint)__float_as_int(v));
}

// Async tile fill: 128 rows x 64 halves, stride TS2.
__device__ __forceinline__ void fill_tile64_async(uint32_t dst, const ushort* src,
                                                  int stride, int tid) {
    #pragma unroll
    for (int it = 0; it < 4; it++) {
        int idx  = it * 256 + tid;
        int row  = idx >> 3;
        int col8 = (idx & 7) << 3;
        CP_ASYNC16(dst + (uint32_t)(row * TS2 + col8) * 2,
                   src + (size_t)row * stride + col8);
    }
}

// Async B tile fill for pv: 64 rows x 128 halves, stride TSB; src stride Yn=128.
__device__ __forceinline__ void fill_tileB_async(uint32_t dst, const ushort* src,
                                                 int tid) {
    #pragma unroll
    for (int it = 0; it < 4; it++) {
        int idx  = it * 256 + tid;
        int row  = idx >> 4;
        int col8 = (idx & 15) << 3;
        CP_ASYNC16(dst + (uint32_t)(row * TSB + col8) * 2,
                   src + (size_t)row * Yn + col8);
    }
}

__device__ __forceinline__ uint32_t a_lane_off(int m0, int lane) {
    int r = lane & 7, grp = lane >> 3;
    return (uint32_t)(((m0 + (grp & 1) * 8 + r) * TS2 + (grp >> 1) * 8) * 2);
}
__device__ __forceinline__ uint32_t b_lane_off(int n0, int lane) {
    int r = lane & 7, grp = lane >> 3;
    return (uint32_t)(((n0 + (grp >> 1) * 8 + r) * TS2 + (grp & 1) * 8) * 2);
}
// trans B lane offset ([k][d] tile): row k = lane&15, col half-group = 8*(lane>>4)
__device__ __forceinline__ uint32_t bT_lane_off(int n0, int lane) {
    return (uint32_t)(((lane & 15) * TSB + n0 + ((lane >> 4) << 3)) * 2);
}

// ---- single-pass fp16 chunk (k=64), A[m][k] + B[n][k], strides TS2 ------------
__device__ __forceinline__ void warp_mma64_1p(float (&c)[2][8][4],
        uint32_t aP, uint32_t bP) {
    #pragma unroll
    for (int ks = 0; ks < 4; ks++) {
        const uint32_t ko = ks * 32;
        uint a[2][4], b[4][4];
        #pragma unroll
        for (int tm = 0; tm < 2; tm++)
            LDSM4(a[tm][0], a[tm][1], a[tm][2], a[tm][3], aP + tm * (16 * TS2 * 2) + ko);
        #pragma unroll
        for (int p = 0; p < 4; p++)
            LDSM4(b[p][0], b[p][1], b[p][2], b[p][3], bP + p * (16 * TS2 * 2) + ko);
        #pragma unroll
        for (int tm = 0; tm < 2; tm++) {
            #pragma unroll
            for (int tn = 0; tn < 8; tn++) {
                const int p = tn >> 1, s = (tn & 1) * 2;
                mma_f16(c[tm][tn], a[tm], &b[p][s]);
            }
        }
    }
}

// ---- pv chunk: A[m][k] stride TS2 + B[k][d] stride TSB via ldmatrix.trans -----
__device__ __forceinline__ void warp_mma64_trans(float (&c)[2][8][4],
        uint32_t aP, uint32_t bP) {
    #pragma unroll
    for (int ks = 0; ks < 4; ks++) {
        uint a[2][4], b[4][4];
        #pragma unroll
        for (int tm = 0; tm < 2; tm++)
            LDSM4(a[tm][0], a[tm][1], a[tm][2], a[tm][3],
                  aP + tm * (16 * TS2 * 2) + ks * 32);
        #pragma unroll
        for (int p = 0; p < 4; p++)
            LDSM4T(b[p][0], b[p][1], b[p][2], b[p][3],
                   bP + ks * (16 * TSB * 2) + p * 32);
        #pragma unroll
        for (int tm = 0; tm < 2; tm++) {
            #pragma unroll
            for (int tn = 0; tn < 8; tn++) {
                const int p = tn >> 1, s = (tn & 1) * 2;
                mma_f16(c[tm][tn], a[tm], &b[p][s]);
            }
        }
    }
}

// ---- 3-stage pipeline (qkv/scores), single sync per iteration -------------------
template <int NCH>
__device__ __forceinline__ void pipe1_mma(float (&c)[2][8][4], uint32_t base,
        uint32_t aoff, uint32_t boff,
        const ushort* a, int sa, const ushort* b, int sb, int tid) {
    fill_tile64_async(base + PVT(0) * 2, a, sa, tid);
    fill_tile64_async(base + PVT(1) * 2, b, sb, tid);
    CP_COMMIT();
    if (NCH > 1) {
        fill_tile64_async(base + PVT(2) * 2, a + 64, sa, tid);
        fill_tile64_async(base + PVT(3) * 2, b + 64, sb, tid);
        CP_COMMIT();
    }
    #pragma unroll
    for (int ch = 0; ch < NCH; ch++) {
        const int st = ch % 3;
        if (ch < NCH - 1) { CP_WAIT(1); } else { CP_WAIT(0); }
        __syncthreads();
        if (ch + 2 < NCH) {
            const int sn = (ch + 2) % 3;
            const int kn = (ch + 2) * 64;
            fill_tile64_async(base + PVT(2 * sn) * 2,     a + kn, sa, tid);
            fill_tile64_async(base + PVT(2 * sn + 1) * 2, b + kn, sb, tid);
            CP_COMMIT();
        }
        warp_mma64_1p(c, base + PVT(2 * st) * 2 + aoff,
                         base + PVT(2 * st + 1) * 2 + boff);
    }
}

// ---------------- K0: fused prep: q->fp16, W->fp16, out->-inf ------------------
__global__ void prep_kernel(const float* __restrict__ q,
                            const float* __restrict__ Wq,
                            const float* __restrict__ Wk,
                            const float* __restrict__ Wv,
                            float* __restrict__ out) {
    const int bid = blockIdx.x;
    const int tid = threadIdx.x;
    if (bid < 16384) {
        int i = (bid * 256 + tid) * 4;
        float4 v = *(const float4*)(q + i);
        uint2 u;
        u.x = (uint)f2h(v.x) | ((uint)f2h(v.y) << 16);
        u.y = (uint)f2h(v.z) | ((uint)f2h(v.w) << 16);
        *(uint2*)(g_qf + i) = u;
    } else if (bid < 16480) {
        const int bid2 = bid - 16384;
        const int sel = bid2 >> 5;
        const int blk = bid2 & 31;
        const float* src = (sel == 0) ? Wq : (sel == 1) ? Wk : Wv;
        int i = (blk * 256 + tid) * 4;
        float4 v = *(const float4*)(src + i);
        uint2 u;
        u.x = (uint)f2h(v.x) | ((uint)f2h(v.y) << 16);
        u.y = (uint)f2h(v.z) | ((uint)f2h(v.w) << 16);
        *(uint2*)(g_Wf[sel] + i) = u;
    } else {
        int i = (bid - 16480) * 256 + tid;
        out[i] = __int_as_float(0xFF800000);
    }
}

// ---------------- K1: QKV projection (fp16 single-pass, 4 chunks) --------------
__global__ __launch_bounds__(256, 2)
void qkv_mma_kernel(const float* __restrict__ bq, const float* __restrict__ bk,
                    const float* __restrict__ bv) {
    extern __shared__ ushort sh[];
    const int tid = threadIdx.x;
    const int w = tid >> 5, lane = tid & 31, g = lane >> 2, t = lane & 3;
    const int m0 = (w & 3) * 32, n0 = (w >> 2) * 64;
    const int rowBase = blockIdx.x * 128;
    const int sel = blockIdx.y;

    const uint32_t base = smem_u32(sh);
    const uint32_t aoff = a_lane_off(m0, lane), boff = b_lane_off(n0, lane);

    float c[2][8][4];
    #pragma unroll
    for (int i = 0; i < 2; i++)
        #pragma unroll
        for (int j = 0; j < 8; j++)
            #pragma unroll
            for (int r = 0; r < 4; r++) c[i][j][r] = 0.f;

    pipe1_mma<4>(c, base, aoff, boff,
                 g_qf + (size_t)rowBase * Xn, Xn, g_Wf[sel], Xn, tid);

    const float* bias = (sel == 0) ? bq : (sel == 1) ? bk : bv;
    ushort* dst = (sel == 0) ? g_Qf : (sel == 1) ? g_Kf : g_Vf;
    #pragma unroll
    for (int tm = 0; tm < 2; tm++) {
        #pragma unroll
        for (int half = 0; half < 2; half++) {
            const int mloc = m0 + tm * 16 + g + half * 8;
            const size_t row = (size_t)(rowBase + mloc) * Yn;
            #pragma unroll
            for (int tn = 0; tn < 8; tn++) {
                const int n = n0 + tn * 8 + t * 2;
                float v0 = c[tm][tn][half * 2 + 0] + __ldg(bias + n);
                float v1 = c[tm][tn][half * 2 + 1] + __ldg(bias + n + 1);
                *(uint*)(dst + row + n) = (uint)f2h(v0) | ((uint)f2h(v1) << 16);
            }
        }
    }
}

// ---------------- K2: scores (fp16 single-pass) -> P fp16 + sums ---------------
__global__ __launch_bounds__(256, 2)
void scores_mma_kernel() {
    extern __shared__ ushort sh[];
    const int tid = threadIdx.x;
    const int w = tid >> 5, lane = tid & 31, g = lane >> 2, t = lane & 3;
    const int m0 = (w & 3) * 32, n0 = (w >> 2) * 64, mw = w & 3;
    const int kt = blockIdx.x, qt = blockIdx.y, b = blockIdx.z;

    const uint32_t base = smem_u32(sh);
    const uint32_t aoff = a_lane_off(m0, lane), boff = b_lane_off(n0, lane);

    float c[2][8][4];
    #pragma unroll
    for (int i = 0; i < 2; i++)
        #pragma unroll
        for (int j = 0; j < 8; j++)
            #pragma unroll
            for (int r = 0; r < 4; r++) c[i][j][r] = 0.f;

    const size_t qoff = ((size_t)b * Sn + qt * 128) * Yn;
    const size_t koff = ((size_t)b * Sn + kt * 128) * Yn;
    pipe1_mma<2>(c, base, aoff, boff, g_Qf + qoff, Yn, g_Kf + koff, Yn, tid);

    // c := exp(c * scale) in place
    const float scale = 0.08838834764831845f;  // 1/sqrt(128)
    #pragma unroll
    for (int i = 0; i < 2; i++)
        #pragma unroll
        for (int j = 0; j < 8; j++)
            #pragma unroll
            for (int r = 0; r < 4; r++) c[i][j][r] = __expf(c[i][j][r] * scale);

    // write P (fp16)
    ushort* Pp = g_P + (size_t)b * Sn * Sn;
    #pragma unroll
    for (int tm = 0; tm < 2; tm++) {
        #pragma unroll
        for (int half = 0; half < 2; half++) {
            const size_t m = (size_t)(qt * 128 + m0 + tm * 16 + g + half * 8);
            #pragma unroll
            for (int tn = 0; tn < 8; tn++) {
                const int n = kt * 128 + n0 + tn * 8 + t * 2;
                *(uint*)(Pp + m * Sn + n) =
                    (uint)f2h(c[tm][tn][half * 2 + 0]) |
                    ((uint)f2h(c[tm][tn][half * 2 + 1]) << 16);
            }
        }
    }

    // per-tile column sums of exp over this CTA's 128 q rows
    __syncthreads();                       // tiles no longer needed; reuse smem
    float* szz = (float*)sh;               // [128][4]
    float vz[16];
    #pragma unroll
    for (int tn = 0; tn < 8; tn++) {
        #pragma unroll
        for (int par = 0; par < 2; par++) {
            float z = c[0][tn][par] + c[0][tn][2 + par]
                    + c[1][tn][par] + c[1][tn][2 + par];
            z += __shfl_xor_sync(0xFFFFFFFF, z, 4);
            z += __shfl_xor_sync(0xFFFFFFFF, z, 8);
            z += __shfl_xor_sync(0xFFFFFFFF, z, 16);
            vz[tn * 2 + par] = z;
        }
    }
    if (lane < 4) {
        #pragma unroll
        for (int tn = 0; tn < 8; tn++)
            #pragma unroll
            for (int par = 0; par < 2; par++)
                szz[(n0 + tn * 8 + t * 2 + par) * 4 + mw] = vz[tn * 2 + par];
    }
    __syncthreads();
    if (tid < 128) {
        const int n = tid;
        const float z = szz[n * 4 + 0] + szz[n * 4 + 1] + szz[n * 4 + 2] + szz[n * 4 + 3];
        g_pz[((size_t)(b * 8 + qt)) * Sn + kt * 128 + n] = z;
    }
}

// ---------------- K3: V/Z row scale, [k][d] layout (no transpose) --------------
__global__ __launch_bounds__(256)
void vscale_kernel() {
    __shared__ float szr[64];       // 1/Z for k0..k0+63
    const int b  = blockIdx.y;
    const int k0 = blockIdx.x * 64;
    const int tt = threadIdx.x;

    if (tt < 64) {
        const int k = k0 + tt;
        float z = 0.f;
        #pragma unroll
        for (int i = 0; i < 8; i++)
            z += g_pz[((size_t)(b * 8 + i)) * Sn + k];
        szr[tt] = 1.0f / z;
    }
    __syncthreads();

    #pragma unroll
    for (int it = 0; it < 4; it++) {
        const int idx  = it * 256 + tt;
        const int row  = idx >> 4;          // 0..63
        const int col8 = (idx & 15) << 3;   // 0..120
        const float zr = szr[row];
        const size_t off = ((size_t)b * Sn + k0 + row) * Yn + col8;
        uint4 u = *(const uint4*)(g_Vf + off);
        uint4 o;
        o.x = (uint)f2h(h2f((ushort)(u.x      )) * zr) |
              ((uint)f2h(h2f((ushort)(u.x >> 16)) * zr) << 16);
        o.y = (uint)f2h(h2f((ushort)(u.y      )) * zr) |
              ((uint)f2h(h2f((ushort)(u.y >> 16)) * zr) << 16);
        o.z = (uint)f2h(h2f((ushort)(u.z      )) * zr) |
              ((uint)f2h(h2f((ushort)(u.z >> 16)) * zr) << 16);
        o.w = (uint)f2h(h2f((ushort)(u.w      )) * zr) |
              ((uint)f2h(h2f((ushort)(u.w >> 16)) * zr) << 16);
        *(uint4*)(g_Vt + off) = o;
    }
}

// ---------------- K4: PV (fp16, B via ldmatrix.trans) + fused max --------------
__global__ __launch_bounds__(256, 2)
void pv_mma_kernel(float* __restrict__ out) {
    extern __shared__ ushort sh[];
    const int tid = threadIdx.x;
    const int w = tid >> 5, lane = tid & 31, t = lane & 3;
    const int m0 = (w & 3) * 32, n0 = (w >> 2) * 64;
    const int qt = blockIdx.x, b = blockIdx.y;

    const uint32_t base = smem_u32(sh);
    const uint32_t aoff = a_lane_off(m0, lane), boff = bT_lane_off(n0, lane);

    const ushort* Pp = g_P + (size_t)b * Sn * Sn + (size_t)(qt * 128) * Sn;
    const ushort* Vp = g_Vt + (size_t)b * Sn * Yn;   // [k][d]

    float c[2][8][4];
    #pragma unroll
    for (int i = 0; i < 2; i++)
        #pragma unroll
        for (int j = 0; j < 8; j++)
            #pragma unroll
            for (int r = 0; r < 4; r++) c[i][j][r] = 0.f;

    // 3-stage pipeline
    fill_tile64_async(base + PV_A(0), Pp, Sn, tid);
    fill_tileB_async (base + PV_B(0), Vp, tid);
    CP_COMMIT();
    fill_tile64_async(base + PV_A(1), Pp + 64, Sn, tid);
    fill_tileB_async (base + PV_B(1), Vp + 64 * Yn, tid);
    CP_COMMIT();
    #pragma unroll
    for (int ch = 0; ch < 16; ch++) {
        const int st = ch % 3;
        if (ch < 15) { CP_WAIT(1); } else { CP_WAIT(0); }
        __syncthreads();
        if (ch + 2 < 16) {
            const int sn = (ch + 2) % 3;
            fill_tile64_async(base + PV_A(sn), Pp + (ch + 2) * 64, Sn, tid);
            fill_tileB_async (base + PV_B(sn), Vp + (size_t)(ch + 2) * 64 * Yn, tid);
            CP_COMMIT();
        }
        warp_mma64_trans(c, base + PV_A(st) + aoff, base + PV_B(st) + boff);
    }

    // fused max over q: thread-local max, shuffle-reduce over g, one atomic per n.
    #pragma unroll
    for (int tn = 0; tn < 8; tn++) {
        #pragma unroll
        for (int par = 0; par < 2; par++) {
            float v = c[0][tn][par];
            v = fmaxf(v, c[0][tn][2 + par]);
            v = fmaxf(v, c[1][tn][par]);
            v = fmaxf(v, c[1][tn][2 + par]);
            v = fmaxf(v, __shfl_xor_sync(0xFFFFFFFF, v, 4));
            v = fmaxf(v, __shfl_xor_sync(0xFFFFFFFF, v, 8));
            v = fmaxf(v, __shfl_xor_sync(0xFFFFFFFF, v, 16));
            if (lane < 4)
                atomicMaxF(out + b * Yn + n0 + tn * 8 + t * 2 + par, v);
        }
    }
}

// ============================================================================
extern "C" void kernel_launch(void* const* d_in, const int* in_sizes, int n_in,
                              void* d_out, int out_size)
{
    const float* q  = (const float*)d_in[0];
    const float* Wq = (const float*)d_in[1];
    const float* bq = (const float*)d_in[2];
    const float* Wk = (const float*)d_in[3];
    const float* bk = (const float*)d_in[4];
    const float* Wv = (const float*)d_in[5];
    const float* bv = (const float*)d_in[6];
    float* out = (float*)d_out;

    cudaFuncSetAttribute(qkv_mma_kernel,    cudaFuncAttributeMaxDynamicSharedMemorySize, SM_1P);
    cudaFuncSetAttribute(scores_mma_kernel, cudaFuncAttributeMaxDynamicSharedMemorySize, SM_1P);
    cudaFuncSetAttribute(pv_mma_kernel,     cudaFuncAttributeMaxDynamicSharedMemorySize, SM_PV);

    prep_kernel<<<16512, 256>>>(q, Wq, Wk, Wv, out);
    qkv_mma_kernel<<<dim3(Bn * Sn / 128, 3), 256, SM_1P>>>(bq, bk, bv);
    scores_mma_kernel<<<dim3(Sn / 128, Sn / 128, Bn), 256, SM_1P>>>();
    vscale_kernel<<<dim3(Sn / 64, Bn), 256>>>();
    pv_mma_kernel<<<dim3(Sn / 128, Bn), 256, SM_PV>>>(out);
}